// round 1
// baseline (speedup 1.0000x reference)
#include <cuda_runtime.h>

#define NROWS 16384   // B*S = 32*512
#define DIM 512
#define HEAD 8
#define SLOT 112
#define HD 64         // DIM/HEAD
#define RADIUSF 16.0f

// ---------------- scratch (device globals; no runtime allocation) ----------------
__device__ float g_eq[NROWS * DIM];          // eq_pre -> eq_norm (in place)
__device__ float g_ev[NROWS * DIM];          // ev
__device__ float g_ksim[NROWS * HEAD * SLOT];// key_sim -> key_add (in place)
__device__ float g_virpre[NROWS * DIM];
__device__ float g_vsim[NROWS * SLOT];       // value_sim -> value_add (in place)
__device__ float g_aud[NROWS * DIM];
__device__ float g_m2[HEAD * SLOT * DIM];    // folded value_mem @ Wl_h^T
__device__ float g_knorm[HEAD * SLOT * HD];
__device__ float g_vnorm[SLOT * DIM];
__device__ float g_invn[NROWS];
__device__ float g_cosbuf[NROWS];
__device__ float g_cpart[SLOT];

// ---------------- reductions ----------------
__device__ __forceinline__ float blockReduceSum(float v, float* red) {
    int lane = threadIdx.x & 31, w = threadIdx.x >> 5;
    #pragma unroll
    for (int o = 16; o; o >>= 1) v += __shfl_down_sync(0xffffffffu, v, o);
    if (lane == 0) red[w] = v;
    __syncthreads();
    int nw = blockDim.x >> 5;
    float r = (threadIdx.x < nw) ? red[threadIdx.x] : 0.0f;
    if (w == 0) {
        #pragma unroll
        for (int o = 16; o; o >>= 1) r += __shfl_down_sync(0xffffffffu, r, o);
        if (lane == 0) red[0] = r;
    }
    __syncthreads();
    float out = red[0];
    __syncthreads();
    return out;
}

// ---------------- SGEMM: C(MxN) = A(MxK) * op(B) + bias, fp32 ----------------
// TRANSB: B is (N x K) row-major (NT).  !TRANSB: B is (K x N) row-major (NN).
// K must be a multiple of 8 and >= 8. Tile 128x128x8, 256 threads, 8x8 per thread.
template<bool TRANSB, bool GUARD>
__global__ void sgemm_kernel(const float* __restrict__ A, const float* __restrict__ B,
                             float* __restrict__ C, const float* __restrict__ bias,
                             int M, int N, int K, int lda, int ldb, int ldc,
                             long long sA, long long sB, long long sC)
{
    A += (long long)blockIdx.z * sA;
    B += (long long)blockIdx.z * sB;
    C += (long long)blockIdx.z * sC;

    __shared__ float As[8][128];
    __shared__ float Bs[8][128];

    const int tid = threadIdx.x;
    const int blockRow = blockIdx.y * 128;
    const int blockCol = blockIdx.x * 128;

    const int rowA = tid >> 1;
    const int colA = (tid & 1) * 4;
    const int rowBt = tid >> 1;            // NT: n index
    const int colBt = (tid & 1) * 4;       // NT: k index
    const int rowBn = tid >> 5;            // NN: k index (0..7)
    const int colBn = (tid & 31) * 4;      // NN: n index

    const int tx = tid & 15;
    const int ty = tid >> 4;

    float acc[8][8];
    #pragma unroll
    for (int i = 0; i < 8; i++)
        #pragma unroll
        for (int j = 0; j < 8; j++) acc[i][j] = 0.0f;

    for (int k0 = 0; k0 < K; k0 += 8) {
        {
            int gr = blockRow + rowA;
            float4 v = make_float4(0.f, 0.f, 0.f, 0.f);
            if (!GUARD || gr < M)
                v = *(const float4*)(A + (long long)gr * lda + k0 + colA);
            As[colA + 0][rowA] = v.x; As[colA + 1][rowA] = v.y;
            As[colA + 2][rowA] = v.z; As[colA + 3][rowA] = v.w;
        }
        if (TRANSB) {
            int gn = blockCol + rowBt;
            float4 v = make_float4(0.f, 0.f, 0.f, 0.f);
            if (!GUARD || gn < N)
                v = *(const float4*)(B + (long long)gn * ldb + k0 + colBt);
            Bs[colBt + 0][rowBt] = v.x; Bs[colBt + 1][rowBt] = v.y;
            Bs[colBt + 2][rowBt] = v.z; Bs[colBt + 3][rowBt] = v.w;
        } else {
            int gn = blockCol + colBn;
            float4 v = make_float4(0.f, 0.f, 0.f, 0.f);
            if (!GUARD || gn < N)
                v = *(const float4*)(B + (long long)(k0 + rowBn) * ldb + gn);
            *(float4*)&Bs[rowBn][colBn] = v;
        }
        __syncthreads();

        #pragma unroll
        for (int kk = 0; kk < 8; kk++) {
            float ar[8], br[8];
            float4 a0 = *(const float4*)&As[kk][ty * 8];
            float4 a1 = *(const float4*)&As[kk][ty * 8 + 4];
            float4 b0 = *(const float4*)&Bs[kk][tx * 8];
            float4 b1 = *(const float4*)&Bs[kk][tx * 8 + 4];
            ar[0]=a0.x; ar[1]=a0.y; ar[2]=a0.z; ar[3]=a0.w;
            ar[4]=a1.x; ar[5]=a1.y; ar[6]=a1.z; ar[7]=a1.w;
            br[0]=b0.x; br[1]=b0.y; br[2]=b0.z; br[3]=b0.w;
            br[4]=b1.x; br[5]=b1.y; br[6]=b1.z; br[7]=b1.w;
            #pragma unroll
            for (int i = 0; i < 8; i++)
                #pragma unroll
                for (int j = 0; j < 8; j++)
                    acc[i][j] = fmaf(ar[i], br[j], acc[i][j]);
        }
        __syncthreads();
    }

    #pragma unroll
    for (int i = 0; i < 8; i++) {
        int gr = blockRow + ty * 8 + i;
        if (GUARD && gr >= M) continue;
        #pragma unroll
        for (int j = 0; j < 8; j++) {
            int gc = blockCol + tx * 8 + j;
            if (GUARD && gc >= N) continue;
            float v = acc[i][j];
            if (bias) v += bias[gc];
            C[(long long)gr * ldc + gc] = v;
        }
    }
}

// ---------------- elementwise / row kernels ----------------
__global__ void normalize_rows_kernel(const float* __restrict__ src, float* __restrict__ dst, int cols) {
    __shared__ float red[32];
    long long r = blockIdx.x;
    float s = 0.0f;
    for (int c = threadIdx.x; c < cols; c += blockDim.x) {
        float v = src[r * cols + c];
        s += v * v;
    }
    s = blockReduceSum(s, red);
    float inv = 1.0f / fmaxf(sqrtf(s), 1e-12f);
    for (int c = threadIdx.x; c < cols; c += blockDim.x)
        dst[r * cols + c] = src[r * cols + c] * inv;
}

__global__ void row_invnorm_kernel(const float* __restrict__ x, float* __restrict__ invn, int cols) {
    __shared__ float red[32];
    long long r = blockIdx.x;
    float s = 0.0f;
    for (int c = threadIdx.x; c < cols; c += blockDim.x) {
        float v = x[r * cols + c];
        s += v * v;
    }
    s = blockReduceSum(s, red);
    if (threadIdx.x == 0) invn[r] = 1.0f / fmaxf(sqrtf(s), 1e-12f);
}

// softmax over 8 head-segments of 112, in place, scale = RADIUS.  grid=NROWS, block=256 (8 warps)
__global__ void softmax_key_kernel(float* __restrict__ ks) {
    int w = threadIdx.x >> 5, lane = threadIdx.x & 31;
    float* p = ks + (long long)blockIdx.x * (HEAD * SLOT) + w * SLOT;
    float v[4];
    float m = -1e30f;
    #pragma unroll
    for (int k = 0; k < 4; k++) {
        int s = lane + 32 * k;
        v[k] = (s < SLOT) ? RADIUSF * p[s] : -1e30f;
        m = fmaxf(m, v[k]);
    }
    #pragma unroll
    for (int o = 16; o; o >>= 1) m = fmaxf(m, __shfl_xor_sync(0xffffffffu, m, o));
    float sum = 0.0f;
    #pragma unroll
    for (int k = 0; k < 4; k++) { v[k] = __expf(v[k] - m); sum += v[k]; }
    #pragma unroll
    for (int o = 16; o; o >>= 1) sum += __shfl_xor_sync(0xffffffffu, sum, o);
    float inv = 1.0f / sum;
    #pragma unroll
    for (int k = 0; k < 4; k++) {
        int s = lane + 32 * k;
        if (s < SLOT) p[s] = v[k] * inv;
    }
}

// softmax over 112, row scale = RADIUS*invn[row].  grid=NROWS/8, block=256 (warp per row)
__global__ void softmax_val_kernel(float* __restrict__ vs, const float* __restrict__ invn) {
    int w = threadIdx.x >> 5, lane = threadIdx.x & 31;
    long long r = (long long)blockIdx.x * 8 + w;
    float scale = RADIUSF * invn[r];
    float* p = vs + r * SLOT;
    float v[4];
    float m = -1e30f;
    #pragma unroll
    for (int k = 0; k < 4; k++) {
        int s = lane + 32 * k;
        v[k] = (s < SLOT) ? scale * p[s] : -1e30f;
        m = fmaxf(m, v[k]);
    }
    #pragma unroll
    for (int o = 16; o; o >>= 1) m = fmaxf(m, __shfl_xor_sync(0xffffffffu, m, o));
    float sum = 0.0f;
    #pragma unroll
    for (int k = 0; k < 4; k++) { v[k] = __expf(v[k] - m); sum += v[k]; }
    #pragma unroll
    for (int o = 16; o; o >>= 1) sum += __shfl_xor_sync(0xffffffffu, sum, o);
    float inv = 1.0f / sum;
    #pragma unroll
    for (int k = 0; k < 4; k++) {
        int s = lane + 32 * k;
        if (s < SLOT) p[s] = v[k] * inv;
    }
}

// te = LN(query + LN(virpre, g2,b2), g1,b1).  grid=NROWS, block=128
__global__ void fuse_te_kernel(const float* __restrict__ virpre, const float* __restrict__ query,
                               const float* __restrict__ g1, const float* __restrict__ b1,
                               const float* __restrict__ g2, const float* __restrict__ b2,
                               float* __restrict__ out_te)
{
    __shared__ float red[32];
    long long r = blockIdx.x;
    const float* vp = virpre + r * DIM;
    const float* q  = query  + r * DIM;
    float x[4], qv[4];
    float s = 0.f, s2 = 0.f;
    #pragma unroll
    for (int i = 0; i < 4; i++) {
        int c = threadIdx.x + 128 * i;
        x[i] = vp[c]; qv[i] = q[c];
        s += x[i]; s2 += x[i] * x[i];
    }
    s  = blockReduceSum(s,  red);
    s2 = blockReduceSum(s2, red);
    float mu = s * (1.0f / DIM);
    float var = s2 * (1.0f / DIM) - mu * mu;
    float inv = rsqrtf(var + 1e-5f);
    float t[4]; float ts = 0.f, ts2 = 0.f;
    #pragma unroll
    for (int i = 0; i < 4; i++) {
        int c = threadIdx.x + 128 * i;
        float ln = (x[i] - mu) * inv * g2[c] + b2[c];
        t[i] = qv[i] + ln; ts += t[i]; ts2 += t[i] * t[i];
    }
    ts  = blockReduceSum(ts,  red);
    ts2 = blockReduceSum(ts2, red);
    mu = ts * (1.0f / DIM);
    var = ts2 * (1.0f / DIM) - mu * mu;
    inv = rsqrtf(var + 1e-5f);
    #pragma unroll
    for (int i = 0; i < 4; i++) {
        int c = threadIdx.x + 128 * i;
        out_te[r * DIM + c] = (t[i] - mu) * inv * g1[c] + b1[c];
    }
}

// cos/recon + tr = LN(query + LN(aud, g3,b3), g1,b1).  grid=NROWS, block=128
__global__ void fuse_tr_kernel(const float* __restrict__ aud, const float* __restrict__ query,
                               const float* __restrict__ value,
                               const float* __restrict__ g1, const float* __restrict__ b1,
                               const float* __restrict__ g3, const float* __restrict__ b3,
                               float* __restrict__ out_tr, float* __restrict__ cosbuf)
{
    __shared__ float red[32];
    long long r = blockIdx.x;
    const float* a = aud   + r * DIM;
    const float* q = query + r * DIM;
    const float* v = value + r * DIM;
    float av[4], qv[4], vv[4];
    float sa = 0.f, saa = 0.f, sav = 0.f, svv = 0.f;
    #pragma unroll
    for (int i = 0; i < 4; i++) {
        int c = threadIdx.x + 128 * i;
        av[i] = a[c]; qv[i] = q[c]; vv[i] = v[c];
        sa += av[i]; saa += av[i] * av[i]; sav += av[i] * vv[i]; svv += vv[i] * vv[i];
    }
    sa  = blockReduceSum(sa,  red);
    saa = blockReduceSum(saa, red);
    sav = blockReduceSum(sav, red);
    svv = blockReduceSum(svv, red);
    if (threadIdx.x == 0) {
        float cosv = sav / fmaxf(sqrtf(saa) * sqrtf(svv), 1e-8f);
        cosbuf[r] = fabsf(1.0f - cosv);
    }
    float mu = sa * (1.0f / DIM);
    float var = saa * (1.0f / DIM) - mu * mu;
    float inv = rsqrtf(var + 1e-5f);
    float t[4]; float ts = 0.f, ts2 = 0.f;
    #pragma unroll
    for (int i = 0; i < 4; i++) {
        int c = threadIdx.x + 128 * i;
        float ln = (av[i] - mu) * inv * g3[c] + b3[c];
        t[i] = qv[i] + ln; ts += t[i]; ts2 += t[i] * t[i];
    }
    ts  = blockReduceSum(ts,  red);
    ts2 = blockReduceSum(ts2, red);
    mu = ts * (1.0f / DIM);
    var = ts2 * (1.0f / DIM) - mu * mu;
    inv = rsqrtf(var + 1e-5f);
    #pragma unroll
    for (int i = 0; i < 4; i++) {
        int c = threadIdx.x + 128 * i;
        out_tr[r * DIM + c] = (t[i] - mu) * inv * g1[c] + b1[c];
    }
}

// recon[b] = sum_s cosbuf[b*512+s], deterministic.  grid=32, block=128
__global__ void recon_reduce_kernel(const float* __restrict__ cosbuf, float* __restrict__ recon) {
    __shared__ float red[32];
    int b = blockIdx.x;
    float s = 0.0f;
    for (int i = threadIdx.x; i < 512; i += blockDim.x) s += cosbuf[b * 512 + i];
    s = blockReduceSum(s, red);
    if (threadIdx.x == 0) recon[b] = s;
}

// contrastive partials: part[i] = sum_j |delta_ij - vn_i . vn_j|.  grid=112, block=128
__global__ void contrastive_partial_kernel(const float* __restrict__ vnorm, float* __restrict__ part) {
    __shared__ float vi[DIM];
    __shared__ float red[32];
    int i = blockIdx.x;
    for (int c = threadIdx.x; c < DIM; c += blockDim.x) vi[c] = vnorm[(long long)i * DIM + c];
    __syncthreads();
    int w = threadIdx.x >> 5, lane = threadIdx.x & 31;
    float s = 0.0f;
    for (int j = w; j < SLOT; j += 4) {
        float d = 0.0f;
        for (int c = lane; c < DIM; c += 32) d += vi[c] * vnorm[(long long)j * DIM + c];
        #pragma unroll
        for (int o = 16; o; o >>= 1) d += __shfl_down_sync(0xffffffffu, d, o);
        if (lane == 0) s += fabsf(((i == j) ? 1.0f : 0.0f) - d);
    }
    s = blockReduceSum(s, red);
    if (threadIdx.x == 0) part[i] = s;
}

__global__ void contrastive_final_kernel(const float* __restrict__ part, float* __restrict__ out) {
    if (threadIdx.x == 0) {
        float s = 0.0f;
        for (int i = 0; i < SLOT; i++) s += part[i];
        out[0] = 0.5f * s;
    }
}

// ---------------- launch ----------------
extern "C" void kernel_launch(void* const* d_in, const int* in_sizes, int n_in,
                              void* d_out, int out_size)
{
    const float* query     = (const float*)d_in[0];
    const float* value     = (const float*)d_in[1];
    const float* key_mem   = (const float*)d_in[2];
    const float* value_mem = (const float*)d_in[3];
    const float* Wq = (const float*)d_in[4];
    const float* bq = (const float*)d_in[5];
    const float* Wv = (const float*)d_in[6];
    const float* bv = (const float*)d_in[7];
    const float* Wl = (const float*)d_in[8];
    const float* bl = (const float*)d_in[9];
    const float* g1 = (const float*)d_in[10];
    const float* b1 = (const float*)d_in[11];
    const float* g2 = (const float*)d_in[12];
    const float* b2 = (const float*)d_in[13];
    const float* g3 = (const float*)d_in[14];
    const float* b3 = (const float*)d_in[15];

    float* out        = (float*)d_out;
    float* out_te     = out;
    float* out_tr     = out + (long long)NROWS * DIM;
    float* out_recon  = out + 2ll * NROWS * DIM;
    float* out_contr  = out_recon + 32;

    float *p_eq, *p_ev, *p_ksim, *p_virpre, *p_vsim, *p_aud, *p_m2, *p_knorm, *p_vnorm, *p_invn, *p_cos, *p_cpart;
    cudaGetSymbolAddress((void**)&p_eq, g_eq);
    cudaGetSymbolAddress((void**)&p_ev, g_ev);
    cudaGetSymbolAddress((void**)&p_ksim, g_ksim);
    cudaGetSymbolAddress((void**)&p_virpre, g_virpre);
    cudaGetSymbolAddress((void**)&p_vsim, g_vsim);
    cudaGetSymbolAddress((void**)&p_aud, g_aud);
    cudaGetSymbolAddress((void**)&p_m2, g_m2);
    cudaGetSymbolAddress((void**)&p_knorm, g_knorm);
    cudaGetSymbolAddress((void**)&p_vnorm, g_vnorm);
    cudaGetSymbolAddress((void**)&p_invn, g_invn);
    cudaGetSymbolAddress((void**)&p_cos, g_cosbuf);
    cudaGetSymbolAddress((void**)&p_cpart, g_cpart);

    // --- small precomputes ---
    normalize_rows_kernel<<<HEAD * SLOT, 64>>>(key_mem, p_knorm, HD);          // key_norm
    normalize_rows_kernel<<<SLOT, 128>>>(value_mem, p_vnorm, DIM);             // value_norm
    contrastive_partial_kernel<<<SLOT, 128>>>(p_vnorm, p_cpart);
    contrastive_final_kernel<<<1, 32>>>(p_cpart, out_contr);

    // M2[h*112+s, j] = sum_d value_mem[s,d] * Wl[j, h*512+d]   (8 batched NT GEMMs)
    sgemm_kernel<true, true><<<dim3(4, 1, HEAD), 256>>>(
        value_mem, Wl, p_m2, nullptr,
        SLOT, DIM, DIM, DIM, HEAD * DIM, DIM,
        0, DIM, (long long)SLOT * DIM);

    // --- read path ---
    // eq_pre = query @ Wq^T + bq
    sgemm_kernel<true, false><<<dim3(4, 128, 1), 256>>>(
        query, Wq, p_eq, bq, NROWS, DIM, DIM, DIM, DIM, DIM, 0, 0, 0);
    // per-head l2 normalize in place (131072 segments of 64)
    normalize_rows_kernel<<<NROWS * HEAD, 64>>>(p_eq, p_eq, HD);
    // key_sim[i, h*112+s] = eq_norm_h[i] . key_norm[h,s]   (8 batched NT GEMMs)
    sgemm_kernel<true, true><<<dim3(1, 128, HEAD), 256>>>(
        p_eq, p_knorm, p_ksim, nullptr,
        NROWS, SLOT, HD, DIM, HD, HEAD * SLOT,
        HD, (long long)SLOT * HD, SLOT);
    softmax_key_kernel<<<NROWS, 256>>>(p_ksim);
    // vir_pre = key_add @ M2 + bl   (NN, K=896)
    sgemm_kernel<false, false><<<dim3(4, 128, 1), 256>>>(
        p_ksim, p_m2, p_virpre, bl,
        NROWS, DIM, HEAD * SLOT, HEAD * SLOT, DIM, DIM, 0, 0, 0);
    fuse_te_kernel<<<NROWS, 128>>>(p_virpre, query, g1, b1, g2, b2, out_te);

    // --- write path ---
    sgemm_kernel<true, false><<<dim3(4, 128, 1), 256>>>(
        value, Wv, p_ev, bv, NROWS, DIM, DIM, DIM, DIM, DIM, 0, 0, 0);
    row_invnorm_kernel<<<NROWS, 128>>>(p_ev, p_invn, DIM);
    // value_sim_raw = ev @ value_norm^T   (NT, N=112)
    sgemm_kernel<true, true><<<dim3(1, 128, 1), 256>>>(
        p_ev, p_vnorm, p_vsim, nullptr,
        NROWS, SLOT, DIM, DIM, DIM, SLOT, 0, 0, 0);
    softmax_val_kernel<<<NROWS / 8, 256>>>(p_vsim, p_invn);
    // aud = value_add @ value_mem   (NN, K=112)
    sgemm_kernel<false, false><<<dim3(4, 128, 1), 256>>>(
        p_vsim, value_mem, p_aud, nullptr,
        NROWS, DIM, SLOT, SLOT, DIM, DIM, 0, 0, 0);
    fuse_tr_kernel<<<NROWS, 128>>>(p_aud, query, value, g1, b1, g3, b3, out_tr, p_cos);
    recon_reduce_kernel<<<32, 128>>>(p_cos, out_recon);
}

// round 3
// speedup vs baseline: 2.3050x; 2.3050x over previous
#include <cuda_runtime.h>
#include <cuda_bf16.h>
#include <cstdint>

#define NROWS 16384   // B*S
#define DIM 512
#define HEAD 8
#define SLOT 112
#define HD 64
#define RADIUSF 16.0f

// ---------------- scratch (device globals) ----------------
// f32 intermediates
__device__ float g_eq[NROWS * DIM];
__device__ float g_ksim[NROWS * HEAD * SLOT];
__device__ float g_virpre[NROWS * DIM];
__device__ float g_vsim[NROWS * 128];
__device__ float g_aud[NROWS * DIM];
__device__ float g_vnorm[SLOT * DIM];
__device__ float g_invn[NROWS];
__device__ float g_cosbuf[NROWS];
__device__ float g_cpart[SLOT];
// bf16 split pairs
__device__ __nv_bfloat16 g_q_h[NROWS * DIM],  g_q_l[NROWS * DIM];
__device__ __nv_bfloat16 g_v_h[NROWS * DIM],  g_v_l[NROWS * DIM];
__device__ __nv_bfloat16 g_wq_h[DIM * DIM],   g_wq_l[DIM * DIM];
__device__ __nv_bfloat16 g_wv_h[DIM * DIM],   g_wv_l[DIM * DIM];
__device__ __nv_bfloat16 g_wl_h[DIM * DIM * HEAD], g_wl_l[DIM * DIM * HEAD];
__device__ __nv_bfloat16 g_vm_h[SLOT * DIM],  g_vm_l[SLOT * DIM];
__device__ __nv_bfloat16 g_eqn_h[NROWS * DIM], g_eqn_l[NROWS * DIM];
__device__ __nv_bfloat16 g_kn_h[HEAD * SLOT * HD], g_kn_l[HEAD * SLOT * HD];
__device__ __nv_bfloat16 g_ka_h[NROWS * HEAD * SLOT], g_ka_l[NROWS * HEAD * SLOT];
__device__ __nv_bfloat16 g_m2_h[DIM * HEAD * SLOT],   g_m2_l[DIM * HEAD * SLOT];
__device__ __nv_bfloat16 g_ev_h[NROWS * DIM], g_ev_l[NROWS * DIM];
__device__ __nv_bfloat16 g_vn_h[SLOT * DIM],  g_vn_l[SLOT * DIM];
__device__ __nv_bfloat16 g_va_h[NROWS * 128], g_va_l[NROWS * 128];
__device__ __nv_bfloat16 g_vt_h[DIM * 128],   g_vt_l[DIM * 128];

// ---------------- helpers ----------------
__device__ __forceinline__ uint32_t smem_u32(const void* p) {
    uint32_t a;
    asm("{ .reg .u64 t; cvta.to.shared.u64 t, %1; cvt.u32.u64 %0, t; }" : "=r"(a) : "l"(p));
    return a;
}
__device__ __forceinline__ void cp16(uint32_t dst, const void* src, int sz) {
    asm volatile("cp.async.cg.shared.global [%0], [%1], 16, %2;"
                 :: "r"(dst), "l"(src), "r"(sz));
}
__device__ __forceinline__ void cp_commit() { asm volatile("cp.async.commit_group;" ::: "memory"); }
__device__ __forceinline__ void cp_wait1()  { asm volatile("cp.async.wait_group 1;"  ::: "memory"); }

__device__ __forceinline__ void ldm4(uint32_t (&r)[4], uint32_t a) {
    asm volatile("ldmatrix.sync.aligned.m8n8.x4.shared.b16 {%0,%1,%2,%3}, [%4];"
                 : "=r"(r[0]), "=r"(r[1]), "=r"(r[2]), "=r"(r[3]) : "r"(a));
}
__device__ __forceinline__ void mma16816(float (&c)[4], const uint32_t (&a)[4],
                                         uint32_t b0, uint32_t b1) {
    asm volatile(
        "mma.sync.aligned.m16n8k16.row.col.f32.bf16.bf16.f32 "
        "{%0,%1,%2,%3}, {%4,%5,%6,%7}, {%8,%9}, {%0,%1,%2,%3};"
        : "+f"(c[0]), "+f"(c[1]), "+f"(c[2]), "+f"(c[3])
        : "r"(a[0]), "r"(a[1]), "r"(a[2]), "r"(a[3]), "r"(b0), "r"(b1));
}
__device__ __forceinline__ void wsplit(__nv_bfloat16* h, __nv_bfloat16* l, long long i, float v) {
    __nv_bfloat16 hh = __float2bfloat16_rn(v);
    h[i] = hh;
    l[i] = __float2bfloat16_rn(v - __bfloat162float(hh));
}

// ---------------- bf16-split HMMA GEMM ----------------
// C[m,n] = sum_k (Ah+Al)[m,k]*(Bh+Bl)[n,k] (+bias[n])  via hh+hl+lh
// M mult of 128 (grid.y), K mult of 32. NGUARD: N<128, grid.x=1, zfill B rows.
#define ROWB   80
#define HALFB  10240
#define STAGEB 40960
#define GSMEM  (3 * STAGEB)

template<bool NGUARD, bool HASBIAS, bool SPLITOUT>
__global__ void __launch_bounds__(256, 1) gemm_nt(
    const __nv_bfloat16* __restrict__ Ah, const __nv_bfloat16* __restrict__ Al,
    int lda, long long sA,
    const __nv_bfloat16* __restrict__ Bh, const __nv_bfloat16* __restrict__ Bl,
    int ldb, long long sB,
    float* __restrict__ Cf, __nv_bfloat16* __restrict__ Ch, __nv_bfloat16* __restrict__ Cl,
    int ldc, long long sC,
    const float* __restrict__ bias, int N, int K)
{
    extern __shared__ char smem[];
    const uint32_t sb = smem_u32(smem);
    const int tid = threadIdx.x, lane = tid & 31, wid = tid >> 5;
    const int wr = wid >> 2, wc = wid & 3;
    const long long z = blockIdx.z;
    const int blockRow = blockIdx.y * 128, blockCol = blockIdx.x * 128;

    Ah += z * sA + (long long)blockRow * lda;
    Al += z * sA + (long long)blockRow * lda;
    Bh += z * sB + (long long)blockCol * ldb;
    Bl += z * sB + (long long)blockCol * ldb;

    const int nvalid = N - blockCol;
    const int nc = K >> 5;

    auto issue = [&](int st, int c) {
        #pragma unroll
        for (int j = 0; j < 2; j++) {
            int id = tid + j * 256;             // 0..511
            int row = id >> 2, ch = id & 3;
            long long offa = (long long)row * lda + c * 32 + ch * 8;
            uint32_t d = sb + st * STAGEB + row * ROWB + ch * 16;
            cp16(d,          Ah + offa, 16);
            cp16(d + HALFB,  Al + offa, 16);
            long long offb = (long long)row * ldb + c * 32 + ch * 8;
            int vb = (!NGUARD || row < nvalid) ? 16 : 0;
            if (vb == 0) offb = 0;
            cp16(d + 2 * HALFB, Bh + offb, vb);
            cp16(d + 3 * HALFB, Bl + offb, vb);
        }
    };

    float acc[4][4][4];
    #pragma unroll
    for (int i = 0; i < 4; i++)
        #pragma unroll
        for (int j = 0; j < 4; j++)
            #pragma unroll
            for (int t = 0; t < 4; t++) acc[i][j][t] = 0.0f;

    issue(0, 0); cp_commit();
    issue(1, 1); cp_commit();

    const int rA = lane & 15, cA = lane >> 4;
    const int rB = (lane & 7) + ((lane >> 4) << 3), cB = (lane >> 3) & 1;

    for (int c = 0; c < nc; c++) {
        cp_wait1();
        __syncthreads();
        const uint32_t base = sb + (c % 3) * STAGEB;
        #pragma unroll
        for (int k16 = 0; k16 < 2; k16++) {
            const int k2 = k16 * 2;
            uint32_t fAh[4][4], fAl[4][4], fBh[2][4], fBl[2][4];
            #pragma unroll
            for (int mi = 0; mi < 4; mi++) {
                uint32_t a = base + (uint32_t)((wr * 64 + mi * 16 + rA) * ROWB + (k2 + cA) * 16);
                ldm4(fAh[mi], a);
                ldm4(fAl[mi], a + HALFB);
            }
            #pragma unroll
            for (int ni = 0; ni < 2; ni++) {
                uint32_t b = base + 2 * HALFB +
                             (uint32_t)((wc * 32 + ni * 16 + rB) * ROWB + (k2 + cB) * 16);
                ldm4(fBh[ni], b);
                ldm4(fBl[ni], b + HALFB);
            }
            #pragma unroll
            for (int mi = 0; mi < 4; mi++)
                #pragma unroll
                for (int nj = 0; nj < 4; nj++) {
                    const int bi = nj >> 1, bs = (nj & 1) * 2;
                    mma16816(acc[mi][nj], fAh[mi], fBh[bi][bs], fBh[bi][bs + 1]);
                    mma16816(acc[mi][nj], fAh[mi], fBl[bi][bs], fBl[bi][bs + 1]);
                    mma16816(acc[mi][nj], fAl[mi], fBh[bi][bs], fBh[bi][bs + 1]);
                }
        }
        __syncthreads();
        int nxt = c + 2;
        if (nxt < nc) issue(nxt % 3, nxt);
        cp_commit();
    }

    // epilogue
    Cf += z * sC; Ch += z * sC; Cl += z * sC;
    #pragma unroll
    for (int mi = 0; mi < 4; mi++) {
        const int r0 = blockRow + wr * 64 + mi * 16 + (lane >> 2);
        const int r1 = r0 + 8;
        #pragma unroll
        for (int nj = 0; nj < 4; nj++) {
            const int col = blockCol + wc * 32 + nj * 8 + (lane & 3) * 2;
            if (NGUARD && col >= N) continue;
            float c0 = acc[mi][nj][0], c1 = acc[mi][nj][1];
            float c2 = acc[mi][nj][2], c3 = acc[mi][nj][3];
            if (HASBIAS) {
                float b0 = bias[col], b1 = bias[col + 1];
                c0 += b0; c1 += b1; c2 += b0; c3 += b1;
            }
            if (SPLITOUT) {
                __nv_bfloat16 h0 = __float2bfloat16_rn(c0), h1 = __float2bfloat16_rn(c1);
                __nv_bfloat16 h2 = __float2bfloat16_rn(c2), h3 = __float2bfloat16_rn(c3);
                __nv_bfloat162 hp0 = __halves2bfloat162(h0, h1);
                __nv_bfloat162 hp1 = __halves2bfloat162(h2, h3);
                __nv_bfloat162 lp0 = __halves2bfloat162(
                    __float2bfloat16_rn(c0 - __bfloat162float(h0)),
                    __float2bfloat16_rn(c1 - __bfloat162float(h1)));
                __nv_bfloat162 lp1 = __halves2bfloat162(
                    __float2bfloat16_rn(c2 - __bfloat162float(h2)),
                    __float2bfloat16_rn(c3 - __bfloat162float(h3)));
                *(__nv_bfloat162*)(Ch + (long long)r0 * ldc + col) = hp0;
                *(__nv_bfloat162*)(Ch + (long long)r1 * ldc + col) = hp1;
                *(__nv_bfloat162*)(Cl + (long long)r0 * ldc + col) = lp0;
                *(__nv_bfloat162*)(Cl + (long long)r1 * ldc + col) = lp1;
            } else {
                *(float2*)(Cf + (long long)r0 * ldc + col) = make_float2(c0, c1);
                *(float2*)(Cf + (long long)r1 * ldc + col) = make_float2(c2, c3);
            }
        }
    }
}

// ---------------- reductions ----------------
__device__ __forceinline__ float blockReduceSum(float v, float* red) {
    int lane = threadIdx.x & 31, w = threadIdx.x >> 5;
    #pragma unroll
    for (int o = 16; o; o >>= 1) v += __shfl_down_sync(0xffffffffu, v, o);
    if (lane == 0) red[w] = v;
    __syncthreads();
    int nw = blockDim.x >> 5;
    float r = (threadIdx.x < nw) ? red[threadIdx.x] : 0.0f;
    if (w == 0) {
        #pragma unroll
        for (int o = 16; o; o >>= 1) r += __shfl_down_sync(0xffffffffu, r, o);
        if (lane == 0) red[0] = r;
    }
    __syncthreads();
    float out = red[0];
    __syncthreads();
    return out;
}

// ---------------- elementwise kernels ----------------
// split f32 -> bf16 hi/lo, float4-vectorized
__global__ void split_kernel(const float4* __restrict__ src, __nv_bfloat16* __restrict__ h,
                             __nv_bfloat16* __restrict__ l, long long n4) {
    long long i = (long long)blockIdx.x * 256 + threadIdx.x;
    if (i >= n4) return;
    float4 v = src[i];
    __nv_bfloat16 h0 = __float2bfloat16_rn(v.x), h1 = __float2bfloat16_rn(v.y);
    __nv_bfloat16 h2 = __float2bfloat16_rn(v.z), h3 = __float2bfloat16_rn(v.w);
    *(__nv_bfloat162*)(h + i * 4)     = __halves2bfloat162(h0, h1);
    *(__nv_bfloat162*)(h + i * 4 + 2) = __halves2bfloat162(h2, h3);
    *(__nv_bfloat162*)(l + i * 4) = __halves2bfloat162(
        __float2bfloat16_rn(v.x - __bfloat162float(h0)),
        __float2bfloat16_rn(v.y - __bfloat162float(h1)));
    *(__nv_bfloat162*)(l + i * 4 + 2) = __halves2bfloat162(
        __float2bfloat16_rn(v.z - __bfloat162float(h2)),
        __float2bfloat16_rn(v.w - __bfloat162float(h3)));
}

// l2norm of contiguous 64-elem segments, warp per segment, write split
__global__ void l2norm64_split(const float* __restrict__ src,
                               __nv_bfloat16* __restrict__ h, __nv_bfloat16* __restrict__ l,
                               int nseg) {
    int seg = blockIdx.x * 8 + (threadIdx.x >> 5);
    if (seg >= nseg) return;
    int lane = threadIdx.x & 31;
    long long base = (long long)seg * 64;
    float a = src[base + lane], b = src[base + lane + 32];
    float s = a * a + b * b;
    #pragma unroll
    for (int o = 16; o; o >>= 1) s += __shfl_xor_sync(0xffffffffu, s, o);
    float inv = 1.0f / fmaxf(sqrtf(s), 1e-12f);
    wsplit(h, l, base + lane, a * inv);
    wsplit(h, l, base + lane + 32, b * inv);
}

// l2norm 512-elem rows: write f32 + split (for value_norm)
__global__ void vnorm_split_kernel(const float* __restrict__ src, float* __restrict__ dst,
                                   __nv_bfloat16* __restrict__ h, __nv_bfloat16* __restrict__ l) {
    __shared__ float red[32];
    long long r = blockIdx.x;
    float x[4], s = 0.0f;
    #pragma unroll
    for (int i = 0; i < 4; i++) {
        x[i] = src[r * DIM + threadIdx.x + 128 * i];
        s += x[i] * x[i];
    }
    s = blockReduceSum(s, red);
    float inv = 1.0f / fmaxf(sqrtf(s), 1e-12f);
    #pragma unroll
    for (int i = 0; i < 4; i++) {
        long long idx = r * DIM + threadIdx.x + 128 * i;
        float v = x[i] * inv;
        dst[idx] = v;
        wsplit(h, l, idx, v);
    }
}

// vmemT[j, s] = value_mem[s, j] (s<112) else 0; split only
__global__ void vmemT_split(const float* __restrict__ vm,
                            __nv_bfloat16* __restrict__ h, __nv_bfloat16* __restrict__ l) {
    int idx = blockIdx.x * 256 + threadIdx.x;
    if (idx < DIM * 128) {
        int j = idx >> 7, s = idx & 127;
        float v = (s < SLOT) ? vm[(long long)s * DIM + j] : 0.0f;
        wsplit(h, l, idx, v);
    }
}

// key softmax over 8 segments of 112 (in f32 ksim), write split key_add
__global__ void softmax_key_split(const float* __restrict__ ks,
                                  __nv_bfloat16* __restrict__ h, __nv_bfloat16* __restrict__ l) {
    int w = threadIdx.x >> 5, lane = threadIdx.x & 31;
    long long rowbase = (long long)blockIdx.x * (HEAD * SLOT) + w * SLOT;
    const float* p = ks + rowbase;
    float v[4];
    float m = -1e30f;
    #pragma unroll
    for (int k = 0; k < 4; k++) {
        int s = lane + 32 * k;
        v[k] = (s < SLOT) ? RADIUSF * p[s] : -1e30f;
        m = fmaxf(m, v[k]);
    }
    #pragma unroll
    for (int o = 16; o; o >>= 1) m = fmaxf(m, __shfl_xor_sync(0xffffffffu, m, o));
    float sum = 0.0f;
    #pragma unroll
    for (int k = 0; k < 4; k++) { v[k] = __expf(v[k] - m); sum += v[k]; }
    #pragma unroll
    for (int o = 16; o; o >>= 1) sum += __shfl_xor_sync(0xffffffffu, sum, o);
    float inv = 1.0f / sum;
    #pragma unroll
    for (int k = 0; k < 4; k++) {
        int s = lane + 32 * k;
        if (s < SLOT) wsplit(h, l, rowbase + s, v[k] * inv);
    }
}

// value softmax over 112 with row scale, write split to stride-128 buffer w/ zero pads
__global__ void softmax_val_split(const float* __restrict__ vs, const float* __restrict__ invn,
                                  __nv_bfloat16* __restrict__ h, __nv_bfloat16* __restrict__ l) {
    int w = threadIdx.x >> 5, lane = threadIdx.x & 31;
    long long r = (long long)blockIdx.x * 8 + w;
    float scale = RADIUSF * invn[r];
    const float* p = vs + r * 128;
    float v[4];
    float m = -1e30f;
    #pragma unroll
    for (int k = 0; k < 4; k++) {
        int s = lane + 32 * k;
        v[k] = (s < SLOT) ? scale * p[s] : -1e30f;
        m = fmaxf(m, v[k]);
    }
    #pragma unroll
    for (int o = 16; o; o >>= 1) m = fmaxf(m, __shfl_xor_sync(0xffffffffu, m, o));
    float sum = 0.0f;
    #pragma unroll
    for (int k = 0; k < 4; k++) { v[k] = __expf(v[k] - m); sum += v[k]; }
    #pragma unroll
    for (int o = 16; o; o >>= 1) sum += __shfl_xor_sync(0xffffffffu, sum, o);
    float inv = 1.0f / sum;
    #pragma unroll
    for (int k = 0; k < 4; k++) {
        int s = lane + 32 * k;
        long long idx = r * 128 + s;
        if (s < SLOT) wsplit(h, l, idx, v[k] * inv);
        else { h[idx] = __float2bfloat16_rn(0.0f); l[idx] = __float2bfloat16_rn(0.0f); }
    }
}

// row inv-norm from split ev
__global__ void row_invnorm_split(const __nv_bfloat16* __restrict__ h,
                                  const __nv_bfloat16* __restrict__ l,
                                  float* __restrict__ invn) {
    __shared__ float red[32];
    long long r = blockIdx.x;
    float s = 0.0f;
    #pragma unroll
    for (int i = 0; i < 4; i++) {
        long long idx = r * DIM + threadIdx.x + 128 * i;
        float v = __bfloat162float(h[idx]) + __bfloat162float(l[idx]);
        s += v * v;
    }
    s = blockReduceSum(s, red);
    if (threadIdx.x == 0) invn[r] = 1.0f / fmaxf(sqrtf(s), 1e-12f);
}

__global__ void fuse_te_kernel(const float* __restrict__ virpre, const float* __restrict__ query,
                               const float* __restrict__ g1, const float* __restrict__ b1,
                               const float* __restrict__ g2, const float* __restrict__ b2,
                               float* __restrict__ out_te)
{
    __shared__ float red[32];
    long long r = blockIdx.x;
    const float* vp = virpre + r * DIM;
    const float* q  = query  + r * DIM;
    float x[4], qv[4];
    float s = 0.f, s2 = 0.f;
    #pragma unroll
    for (int i = 0; i < 4; i++) {
        int c = threadIdx.x + 128 * i;
        x[i] = vp[c]; qv[i] = q[c];
        s += x[i]; s2 += x[i] * x[i];
    }
    s  = blockReduceSum(s,  red);
    s2 = blockReduceSum(s2, red);
    float mu = s * (1.0f / DIM);
    float var = s2 * (1.0f / DIM) - mu * mu;
    float inv = rsqrtf(var + 1e-5f);
    float t[4]; float ts = 0.f, ts2 = 0.f;
    #pragma unroll
    for (int i = 0; i < 4; i++) {
        int c = threadIdx.x + 128 * i;
        float ln = (x[i] - mu) * inv * g2[c] + b2[c];
        t[i] = qv[i] + ln; ts += t[i]; ts2 += t[i] * t[i];
    }
    ts  = blockReduceSum(ts,  red);
    ts2 = blockReduceSum(ts2, red);
    mu = ts * (1.0f / DIM);
    var = ts2 * (1.0f / DIM) - mu * mu;
    inv = rsqrtf(var + 1e-5f);
    #pragma unroll
    for (int i = 0; i < 4; i++) {
        int c = threadIdx.x + 128 * i;
        out_te[r * DIM + c] = (t[i] - mu) * inv * g1[c] + b1[c];
    }
}

__global__ void fuse_tr_kernel(const float* __restrict__ aud, const float* __restrict__ query,
                               const float* __restrict__ value,
                               const float* __restrict__ g1, const float* __restrict__ b1,
                               const float* __restrict__ g3, const float* __restrict__ b3,
                               float* __restrict__ out_tr, float* __restrict__ cosbuf)
{
    __shared__ float red[32];
    long long r = blockIdx.x;
    const float* a = aud   + r * DIM;
    const float* q = query + r * DIM;
    const float* v = value + r * DIM;
    float av[4], qv[4], vv[4];
    float sa = 0.f, saa = 0.f, sav = 0.f, svv = 0.f;
    #pragma unroll
    for (int i = 0; i < 4; i++) {
        int c = threadIdx.x + 128 * i;
        av[i] = a[c]; qv[i] = q[c]; vv[i] = v[c];
        sa += av[i]; saa += av[i] * av[i]; sav += av[i] * vv[i]; svv += vv[i] * vv[i];
    }
    sa  = blockReduceSum(sa,  red);
    saa = blockReduceSum(saa, red);
    sav = blockReduceSum(sav, red);
    svv = blockReduceSum(svv, red);
    if (threadIdx.x == 0) {
        float cosv = sav / fmaxf(sqrtf(saa) * sqrtf(svv), 1e-8f);
        cosbuf[r] = fabsf(1.0f - cosv);
    }
    float mu = sa * (1.0f / DIM);
    float var = saa * (1.0f / DIM) - mu * mu;
    float inv = rsqrtf(var + 1e-5f);
    float t[4]; float ts = 0.f, ts2 = 0.f;
    #pragma unroll
    for (int i = 0; i < 4; i++) {
        int c = threadIdx.x + 128 * i;
        float ln = (av[i] - mu) * inv * g3[c] + b3[c];
        t[i] = qv[i] + ln; ts += t[i]; ts2 += t[i] * t[i];
    }
    ts  = blockReduceSum(ts,  red);
    ts2 = blockReduceSum(ts2, red);
    mu = ts * (1.0f / DIM);
    var = ts2 * (1.0f / DIM) - mu * mu;
    inv = rsqrtf(var + 1e-5f);
    #pragma unroll
    for (int i = 0; i < 4; i++) {
        int c = threadIdx.x + 128 * i;
        out_tr[r * DIM + c] = (t[i] - mu) * inv * g1[c] + b1[c];
    }
}

__global__ void recon_reduce_kernel(const float* __restrict__ cosbuf, float* __restrict__ recon) {
    __shared__ float red[32];
    int b = blockIdx.x;
    float s = 0.0f;
    for (int i = threadIdx.x; i < 512; i += blockDim.x) s += cosbuf[b * 512 + i];
    s = blockReduceSum(s, red);
    if (threadIdx.x == 0) recon[b] = s;
}

__global__ void contrastive_partial_kernel(const float* __restrict__ vnorm, float* __restrict__ part) {
    __shared__ float vi[DIM];
    __shared__ float red[32];
    int i = blockIdx.x;
    for (int c = threadIdx.x; c < DIM; c += blockDim.x) vi[c] = vnorm[(long long)i * DIM + c];
    __syncthreads();
    int w = threadIdx.x >> 5, lane = threadIdx.x & 31;
    float s = 0.0f;
    for (int j = w; j < SLOT; j += 4) {
        float d = 0.0f;
        for (int c = lane; c < DIM; c += 32) d += vi[c] * vnorm[(long long)j * DIM + c];
        #pragma unroll
        for (int o = 16; o; o >>= 1) d += __shfl_down_sync(0xffffffffu, d, o);
        if (lane == 0) s += fabsf(((i == j) ? 1.0f : 0.0f) - d);
    }
    s = blockReduceSum(s, red);
    if (threadIdx.x == 0) part[i] = s;
}

__global__ void contrastive_final_kernel(const float* __restrict__ part, float* __restrict__ out) {
    if (threadIdx.x == 0) {
        float s = 0.0f;
        for (int i = 0; i < SLOT; i++) s += part[i];
        out[0] = 0.5f * s;
    }
}

// ---------------- launch ----------------
#define SYM(p, s) cudaGetSymbolAddress((void**)&p, s)

extern "C" void kernel_launch(void* const* d_in, const int* in_sizes, int n_in,
                              void* d_out, int out_size)
{
    const float* query     = (const float*)d_in[0];
    const float* value     = (const float*)d_in[1];
    const float* key_mem   = (const float*)d_in[2];
    const float* value_mem = (const float*)d_in[3];
    const float* Wq = (const float*)d_in[4];
    const float* bq = (const float*)d_in[5];
    const float* Wv = (const float*)d_in[6];
    const float* bv = (const float*)d_in[7];
    const float* Wl = (const float*)d_in[8];
    const float* bl = (const float*)d_in[9];
    const float* g1 = (const float*)d_in[10];
    const float* b1 = (const float*)d_in[11];
    const float* g2 = (const float*)d_in[12];
    const float* b2 = (const float*)d_in[13];
    const float* g3 = (const float*)d_in[14];
    const float* b3 = (const float*)d_in[15];

    float* out        = (float*)d_out;
    float* out_te     = out;
    float* out_tr     = out + (long long)NROWS * DIM;
    float* out_recon  = out + 2ll * NROWS * DIM;
    float* out_contr  = out_recon + 32;

    float *p_eq, *p_ksim, *p_virpre, *p_vsim, *p_aud, *p_vnorm, *p_invn, *p_cos, *p_cpart;
    SYM(p_eq, g_eq); SYM(p_ksim, g_ksim); SYM(p_virpre, g_virpre); SYM(p_vsim, g_vsim);
    SYM(p_aud, g_aud); SYM(p_vnorm, g_vnorm); SYM(p_invn, g_invn); SYM(p_cos, g_cosbuf);
    SYM(p_cpart, g_cpart);

    __nv_bfloat16 *q_h, *q_l, *v_h, *v_l, *wq_h, *wq_l, *wv_h, *wv_l, *wl_h, *wl_l;
    __nv_bfloat16 *vm_h, *vm_l, *eqn_h, *eqn_l, *kn_h, *kn_l, *ka_h, *ka_l, *m2_h, *m2_l;
    __nv_bfloat16 *ev_h, *ev_l, *vn_h, *vn_l, *va_h, *va_l, *vt_h, *vt_l;
    SYM(q_h, g_q_h); SYM(q_l, g_q_l); SYM(v_h, g_v_h); SYM(v_l, g_v_l);
    SYM(wq_h, g_wq_h); SYM(wq_l, g_wq_l); SYM(wv_h, g_wv_h); SYM(wv_l, g_wv_l);
    SYM(wl_h, g_wl_h); SYM(wl_l, g_wl_l); SYM(vm_h, g_vm_h); SYM(vm_l, g_vm_l);
    SYM(eqn_h, g_eqn_h); SYM(eqn_l, g_eqn_l); SYM(kn_h, g_kn_h); SYM(kn_l, g_kn_l);
    SYM(ka_h, g_ka_h); SYM(ka_l, g_ka_l); SYM(m2_h, g_m2_h); SYM(m2_l, g_m2_l);
    SYM(ev_h, g_ev_h); SYM(ev_l, g_ev_l); SYM(vn_h, g_vn_h); SYM(vn_l, g_vn_l);
    SYM(va_h, g_va_h); SYM(va_l, g_va_l); SYM(vt_h, g_vt_h); SYM(vt_l, g_vt_l);

    cudaFuncSetAttribute(gemm_nt<true,  false, true >, cudaFuncAttributeMaxDynamicSharedMemorySize, GSMEM);
    cudaFuncSetAttribute(gemm_nt<false, true,  false>, cudaFuncAttributeMaxDynamicSharedMemorySize, GSMEM);
    cudaFuncSetAttribute(gemm_nt<true,  false, false>, cudaFuncAttributeMaxDynamicSharedMemorySize, GSMEM);
    cudaFuncSetAttribute(gemm_nt<false, true,  true >, cudaFuncAttributeMaxDynamicSharedMemorySize, GSMEM);
    cudaFuncSetAttribute(gemm_nt<false, false, false>, cudaFuncAttributeMaxDynamicSharedMemorySize, GSMEM);

    // --- input splits ---
    split_kernel<<<(NROWS * DIM / 4 + 255) / 256, 256>>>((const float4*)query, q_h, q_l, NROWS * DIM / 4);
    split_kernel<<<(NROWS * DIM / 4 + 255) / 256, 256>>>((const float4*)value, v_h, v_l, NROWS * DIM / 4);
    split_kernel<<<(DIM * DIM / 4 + 255) / 256, 256>>>((const float4*)Wq, wq_h, wq_l, DIM * DIM / 4);
    split_kernel<<<(DIM * DIM / 4 + 255) / 256, 256>>>((const float4*)Wv, wv_h, wv_l, DIM * DIM / 4);
    split_kernel<<<(DIM * DIM * HEAD / 4 + 255) / 256, 256>>>((const float4*)Wl, wl_h, wl_l, DIM * DIM * HEAD / 4);
    split_kernel<<<(SLOT * DIM / 4 + 255) / 256, 256>>>((const float4*)value_mem, vm_h, vm_l, SLOT * DIM / 4);

    // --- small precomputes ---
    l2norm64_split<<<HEAD * SLOT / 8, 256>>>(key_mem, kn_h, kn_l, HEAD * SLOT);
    vnorm_split_kernel<<<SLOT, 128>>>(value_mem, p_vnorm, vn_h, vn_l);
    contrastive_partial_kernel<<<SLOT, 128>>>(p_vnorm, p_cpart);
    contrastive_final_kernel<<<1, 32>>>(p_cpart, out_contr);
    vmemT_split<<<(DIM * 128) / 256, 256>>>(value_mem, vt_h, vt_l);

    // M2T[j, h*112+s] = sum_d Wl[j, h*512+d] * value_mem[s, d]  (split out)
    gemm_nt<true, false, true><<<dim3(1, 4, HEAD), 256, GSMEM>>>(
        wl_h, wl_l, HEAD * DIM, 512, vm_h, vm_l, DIM, 0,
        nullptr, m2_h, m2_l, HEAD * SLOT, 112, nullptr, SLOT, DIM);

    // --- read path ---
    gemm_nt<false, true, false><<<dim3(4, 128, 1), 256, GSMEM>>>(
        q_h, q_l, DIM, 0, wq_h, wq_l, DIM, 0,
        p_eq, nullptr, nullptr, DIM, 0, bq, DIM, DIM);
    l2norm64_split<<<NROWS, 256>>>(p_eq, eqn_h, eqn_l, NROWS * HEAD);
    gemm_nt<true, false, false><<<dim3(1, 128, HEAD), 256, GSMEM>>>(
        eqn_h, eqn_l, DIM, HD, kn_h, kn_l, HD, (long long)SLOT * HD,
        p_ksim, nullptr, nullptr, HEAD * SLOT, SLOT, nullptr, SLOT, HD);
    softmax_key_split<<<NROWS, 256>>>(p_ksim, ka_h, ka_l);
    gemm_nt<false, true, false><<<dim3(4, 128, 1), 256, GSMEM>>>(
        ka_h, ka_l, HEAD * SLOT, 0, m2_h, m2_l, HEAD * SLOT, 0,
        p_virpre, nullptr, nullptr, DIM, 0, bl, DIM, HEAD * SLOT);
    fuse_te_kernel<<<NROWS, 128>>>(p_virpre, query, g1, b1, g2, b2, out_te);

    // --- write path ---
    gemm_nt<false, true, true><<<dim3(4, 128, 1), 256, GSMEM>>>(
        v_h, v_l, DIM, 0, wv_h, wv_l, DIM, 0,
        nullptr, ev_h, ev_l, DIM, 0, bv, DIM, DIM);
    row_invnorm_split<<<NROWS, 128>>>(ev_h, ev_l, p_invn);
    gemm_nt<true, false, false><<<dim3(1, 128, 1), 256, GSMEM>>>(
        ev_h, ev_l, DIM, 0, vn_h, vn_l, DIM, 0,
        p_vsim, nullptr, nullptr, 128, 0, nullptr, SLOT, DIM);
    softmax_val_split<<<NROWS / 8, 256>>>(p_vsim, p_invn, va_h, va_l);
    gemm_nt<false, false, false><<<dim3(4, 128, 1), 256, GSMEM>>>(
        va_h, va_l, 128, 0, vt_h, vt_l, 128, 0,
        p_aud, nullptr, nullptr, DIM, 0, nullptr, DIM, 128);
    fuse_tr_kernel<<<NROWS, 128>>>(p_aud, query, value, g1, b1, g3, b3, out_tr, p_cos);
    recon_reduce_kernel<<<32, 128>>>(p_cos, out_recon);
}

// round 4
// speedup vs baseline: 2.3397x; 1.0151x over previous
#include <cuda_runtime.h>
#include <cuda_bf16.h>
#include <cstdint>

#define NROWS 16384   // B*S
#define DIM 512
#define HEAD 8
#define SLOT 112
#define HD 64
#define RADIUSF 16.0f

// ---------------- scratch (device globals) ----------------
__device__ float g_virpre[NROWS * DIM];
__device__ float g_aud[NROWS * DIM];
__device__ float g_vnorm[SLOT * DIM];
__device__ float g_invn[NROWS];
__device__ float g_invkn[NROWS * HEAD];
__device__ float g_gpart[NROWS * 4];
__device__ float g_cosbuf[NROWS];
__device__ float g_cpart[SLOT];
// bf16 split pairs
__device__ __nv_bfloat16 g_q_h[NROWS * DIM],  g_q_l[NROWS * DIM];
__device__ __nv_bfloat16 g_v_h[NROWS * DIM],  g_v_l[NROWS * DIM];
__device__ __nv_bfloat16 g_wq_h[DIM * DIM],   g_wq_l[DIM * DIM];
__device__ __nv_bfloat16 g_wv_h[DIM * DIM],   g_wv_l[DIM * DIM];
__device__ __nv_bfloat16 g_wl_h[DIM * DIM * HEAD], g_wl_l[DIM * DIM * HEAD];
__device__ __nv_bfloat16 g_vm_h[SLOT * DIM],  g_vm_l[SLOT * DIM];
__device__ __nv_bfloat16 g_eqn_h[NROWS * DIM], g_eqn_l[NROWS * DIM];
__device__ __nv_bfloat16 g_kn_h[HEAD * SLOT * HD], g_kn_l[HEAD * SLOT * HD];
__device__ __nv_bfloat16 g_ka_h[NROWS * HEAD * SLOT], g_ka_l[NROWS * HEAD * SLOT];
__device__ __nv_bfloat16 g_m2_h[DIM * HEAD * SLOT],   g_m2_l[DIM * HEAD * SLOT];
__device__ __nv_bfloat16 g_ev_h[NROWS * DIM], g_ev_l[NROWS * DIM];
__device__ __nv_bfloat16 g_vn_h[SLOT * DIM],  g_vn_l[SLOT * DIM];
__device__ __nv_bfloat16 g_va_h[NROWS * 128], g_va_l[NROWS * 128];
__device__ __nv_bfloat16 g_vt_h[DIM * 128],   g_vt_l[DIM * 128];

// ---------------- helpers ----------------
__device__ __forceinline__ uint32_t smem_u32(const void* p) {
    uint32_t a;
    asm("{ .reg .u64 t; cvta.to.shared.u64 t, %1; cvt.u32.u64 %0, t; }" : "=r"(a) : "l"(p));
    return a;
}
__device__ __forceinline__ void cp16(uint32_t dst, const void* src, int sz) {
    asm volatile("cp.async.cg.shared.global [%0], [%1], 16, %2;"
                 :: "r"(dst), "l"(src), "r"(sz));
}
__device__ __forceinline__ void cp_commit() { asm volatile("cp.async.commit_group;" ::: "memory"); }
__device__ __forceinline__ void cp_wait1()  { asm volatile("cp.async.wait_group 1;"  ::: "memory"); }

__device__ __forceinline__ void ldm4(uint32_t (&r)[4], uint32_t a) {
    asm volatile("ldmatrix.sync.aligned.m8n8.x4.shared.b16 {%0,%1,%2,%3}, [%4];"
                 : "=r"(r[0]), "=r"(r[1]), "=r"(r[2]), "=r"(r[3]) : "r"(a));
}
__device__ __forceinline__ void mma16816(float (&c)[4], const uint32_t (&a)[4],
                                         uint32_t b0, uint32_t b1) {
    asm volatile(
        "mma.sync.aligned.m16n8k16.row.col.f32.bf16.bf16.f32 "
        "{%0,%1,%2,%3}, {%4,%5,%6,%7}, {%8,%9}, {%0,%1,%2,%3};"
        : "+f"(c[0]), "+f"(c[1]), "+f"(c[2]), "+f"(c[3])
        : "r"(a[0]), "r"(a[1]), "r"(a[2]), "r"(a[3]), "r"(b0), "r"(b1));
}
__device__ __forceinline__ void wsplit(__nv_bfloat16* h, __nv_bfloat16* l, long long i, float v) {
    __nv_bfloat16 hh = __float2bfloat16_rn(v);
    h[i] = hh;
    l[i] = __float2bfloat16_rn(v - __bfloat162float(hh));
}
__device__ __forceinline__ void spair(__nv_bfloat16* H, __nv_bfloat16* L, long long i,
                                      float a, float b) {
    __nv_bfloat16 h0 = __float2bfloat16_rn(a), h1 = __float2bfloat16_rn(b);
    *(__nv_bfloat162*)(H + i) = __halves2bfloat162(h0, h1);
    *(__nv_bfloat162*)(L + i) = __halves2bfloat162(
        __float2bfloat16_rn(a - __bfloat162float(h0)),
        __float2bfloat16_rn(b - __bfloat162float(h1)));
}
__device__ __forceinline__ float qred_sum(float v) {
    v += __shfl_xor_sync(0xffffffffu, v, 1);
    v += __shfl_xor_sync(0xffffffffu, v, 2);
    return v;
}
__device__ __forceinline__ float qred_max(float v) {
    v = fmaxf(v, __shfl_xor_sync(0xffffffffu, v, 1));
    v = fmaxf(v, __shfl_xor_sync(0xffffffffu, v, 2));
    return v;
}

// ---------------- bf16-split HMMA GEMM with fused epilogues ----------------
// C[m,n] = sum_k (Ah+Al)[m,k]*(Bh+Bl)[n,k] (+bias[n])  via hh+hl+lh
// EPI: 0 = f32 out; 1 = split out; 2 = split out + per-64col-seg invnorm -> auxout
//      3 = fused key softmax (scale R*auxin[row*8+z]) -> split out
//      4 = split out + per-block row sumsq partial -> auxout[row*4+bx]
//      5 = fused val softmax (scale R*auxin[row]) -> split out incl zero pads
#define ROWB   80
#define HALFB  10240
#define STAGEB 40960
#define GSMEM  (3 * STAGEB)

template<int EPI, bool NGUARD, bool HASBIAS>
__global__ void __launch_bounds__(256, 1) gemm_nt(
    const __nv_bfloat16* __restrict__ Ah, const __nv_bfloat16* __restrict__ Al,
    int lda, long long sA,
    const __nv_bfloat16* __restrict__ Bh, const __nv_bfloat16* __restrict__ Bl,
    int ldb, long long sB,
    float* __restrict__ Cf, __nv_bfloat16* __restrict__ Ch, __nv_bfloat16* __restrict__ Cl,
    int ldc, long long sC,
    const float* __restrict__ bias,
    const float* __restrict__ auxin, float* __restrict__ auxout,
    int N, int K)
{
    extern __shared__ char smem[];
    const uint32_t sb = smem_u32(smem);
    const int tid = threadIdx.x, lane = tid & 31, wid = tid >> 5;
    const int wr = wid >> 2, wc = wid & 3;
    const long long z = blockIdx.z;
    const int blockRow = blockIdx.y * 128, blockCol = blockIdx.x * 128;

    Ah += z * sA + (long long)blockRow * lda;
    Al += z * sA + (long long)blockRow * lda;
    Bh += z * sB + (long long)blockCol * ldb;
    Bl += z * sB + (long long)blockCol * ldb;

    const int nvalid = N - blockCol;
    const int nc = K >> 5;

    auto issue = [&](int st, int c) {
        #pragma unroll
        for (int j = 0; j < 2; j++) {
            int id = tid + j * 256;
            int row = id >> 2, ch = id & 3;
            long long offa = (long long)row * lda + c * 32 + ch * 8;
            uint32_t d = sb + st * STAGEB + row * ROWB + ch * 16;
            cp16(d,         Ah + offa, 16);
            cp16(d + HALFB, Al + offa, 16);
            long long offb = (long long)row * ldb + c * 32 + ch * 8;
            int vb = (!NGUARD || row < nvalid) ? 16 : 0;
            if (vb == 0) offb = 0;
            cp16(d + 2 * HALFB, Bh + offb, vb);
            cp16(d + 3 * HALFB, Bl + offb, vb);
        }
    };

    float acc[4][4][4];
    #pragma unroll
    for (int i = 0; i < 4; i++)
        #pragma unroll
        for (int j = 0; j < 4; j++)
            #pragma unroll
            for (int t = 0; t < 4; t++) acc[i][j][t] = 0.0f;

    issue(0, 0); cp_commit();
    issue(1, 1); cp_commit();

    const int rA = lane & 15, cA = lane >> 4;
    const int rB = (lane & 7) + ((lane >> 4) << 3), cB = (lane >> 3) & 1;

    for (int c = 0; c < nc; c++) {
        cp_wait1();
        __syncthreads();
        const uint32_t base = sb + (c % 3) * STAGEB;
        #pragma unroll
        for (int k16 = 0; k16 < 2; k16++) {
            const int k2 = k16 * 2;
            uint32_t fAh[4][4], fAl[4][4], fBh[2][4], fBl[2][4];
            #pragma unroll
            for (int mi = 0; mi < 4; mi++) {
                uint32_t a = base + (uint32_t)((wr * 64 + mi * 16 + rA) * ROWB + (k2 + cA) * 16);
                ldm4(fAh[mi], a);
                ldm4(fAl[mi], a + HALFB);
            }
            #pragma unroll
            for (int ni = 0; ni < 2; ni++) {
                uint32_t b = base + 2 * HALFB +
                             (uint32_t)((wc * 32 + ni * 16 + rB) * ROWB + (k2 + cB) * 16);
                ldm4(fBh[ni], b);
                ldm4(fBl[ni], b + HALFB);
            }
            #pragma unroll
            for (int mi = 0; mi < 4; mi++)
                #pragma unroll
                for (int nj = 0; nj < 4; nj++) {
                    const int bi = nj >> 1, bs = (nj & 1) * 2;
                    mma16816(acc[mi][nj], fAh[mi], fBh[bi][bs], fBh[bi][bs + 1]);
                    mma16816(acc[mi][nj], fAh[mi], fBl[bi][bs], fBl[bi][bs + 1]);
                    mma16816(acc[mi][nj], fAl[mi], fBh[bi][bs], fBh[bi][bs + 1]);
                }
        }
        __syncthreads();
        int nxt = c + 2;
        if (nxt < nc) issue(nxt % 3, nxt);
        cp_commit();
    }

    // ---------------- epilogue ----------------
    float* sred = (float*)smem;        // 512 floats (per-row, per-wc partials)
    float* ssum = sred + 512;          // 512 floats

    if (HASBIAS) {
        #pragma unroll
        for (int nj = 0; nj < 4; nj++) {
            const int col = blockCol + wc * 32 + nj * 8 + (lane & 3) * 2;
            float b0 = bias[col], b1 = bias[col + 1];
            #pragma unroll
            for (int mi = 0; mi < 4; mi++) {
                acc[mi][nj][0] += b0; acc[mi][nj][1] += b1;
                acc[mi][nj][2] += b0; acc[mi][nj][3] += b1;
            }
        }
    }

    Cf += z * sC; Ch += z * sC; Cl += z * sC;

    if (EPI == 2 || EPI == 4) {
        // per (row) sumsq partial over this warp's 32 cols
        #pragma unroll
        for (int mi = 0; mi < 4; mi++) {
            float s0 = 0.f, s1 = 0.f;
            #pragma unroll
            for (int nj = 0; nj < 4; nj++) {
                s0 += acc[mi][nj][0] * acc[mi][nj][0] + acc[mi][nj][1] * acc[mi][nj][1];
                s1 += acc[mi][nj][2] * acc[mi][nj][2] + acc[mi][nj][3] * acc[mi][nj][3];
            }
            s0 = qred_sum(s0); s1 = qred_sum(s1);
            if ((lane & 3) == 0) {
                int r0 = wr * 64 + mi * 16 + (lane >> 2);
                sred[r0 * 4 + wc] = s0;
                sred[(r0 + 8) * 4 + wc] = s1;
            }
        }
        __syncthreads();
        if (EPI == 2) {
            if ((wc == 0 || wc == 2) && (lane & 3) == 0) {
                #pragma unroll
                for (int mi = 0; mi < 4; mi++)
                    #pragma unroll
                    for (int half = 0; half < 2; half++) {
                        int r = wr * 64 + mi * 16 + (lane >> 2) + half * 8;
                        float s = sred[r * 4 + wc] + sred[r * 4 + wc + 1];
                        auxout[(long long)(blockRow + r) * HEAD + blockIdx.x * 2 + (wc >> 1)]
                            = 1.0f / fmaxf(sqrtf(s), 1e-12f);
                    }
            }
        } else {
            if (wc == 0 && (lane & 3) == 0) {
                #pragma unroll
                for (int mi = 0; mi < 4; mi++)
                    #pragma unroll
                    for (int half = 0; half < 2; half++) {
                        int r = wr * 64 + mi * 16 + (lane >> 2) + half * 8;
                        float s = sred[r * 4] + sred[r * 4 + 1] + sred[r * 4 + 2] + sred[r * 4 + 3];
                        auxout[(long long)(blockRow + r) * 4 + blockIdx.x] = s;
                    }
            }
        }
    }

    if (EPI == 0 || EPI == 1 || EPI == 2 || EPI == 4) {
        #pragma unroll
        for (int mi = 0; mi < 4; mi++) {
            long long R0 = (long long)(blockRow + wr * 64 + mi * 16 + (lane >> 2)) * ldc;
            long long R1 = R0 + 8LL * ldc;
            #pragma unroll
            for (int nj = 0; nj < 4; nj++) {
                int col = blockCol + wc * 32 + nj * 8 + (lane & 3) * 2;
                if (NGUARD && col >= N) continue;
                if (EPI == 0) {
                    *(float2*)(Cf + R0 + col) = make_float2(acc[mi][nj][0], acc[mi][nj][1]);
                    *(float2*)(Cf + R1 + col) = make_float2(acc[mi][nj][2], acc[mi][nj][3]);
                } else {
                    spair(Ch, Cl, R0 + col, acc[mi][nj][0], acc[mi][nj][1]);
                    spair(Ch, Cl, R1 + col, acc[mi][nj][2], acc[mi][nj][3]);
                }
            }
        }
    }

    if (EPI == 3 || EPI == 5) {
        // fused softmax over the block's row (grid.x == 1, cols = 0..N-1 (+pads))
        float scl[4][2];
        #pragma unroll
        for (int mi = 0; mi < 4; mi++)
            #pragma unroll
            for (int half = 0; half < 2; half++) {
                int r = blockRow + wr * 64 + mi * 16 + (lane >> 2) + half * 8;
                scl[mi][half] = RADIUSF *
                    ((EPI == 3) ? auxin[(long long)r * HEAD + z] : auxin[r]);
            }
        // logits + row max
        #pragma unroll
        for (int mi = 0; mi < 4; mi++) {
            float m0 = -1e30f, m1 = -1e30f;
            #pragma unroll
            for (int nj = 0; nj < 4; nj++) {
                const int col = wc * 32 + nj * 8 + (lane & 3) * 2;
                bool ok = col < SLOT;
                float l0 = ok ? scl[mi][0] * acc[mi][nj][0] : -1e30f;
                float l1 = ok ? scl[mi][0] * acc[mi][nj][1] : -1e30f;
                float l2 = ok ? scl[mi][1] * acc[mi][nj][2] : -1e30f;
                float l3 = ok ? scl[mi][1] * acc[mi][nj][3] : -1e30f;
                acc[mi][nj][0] = l0; acc[mi][nj][1] = l1;
                acc[mi][nj][2] = l2; acc[mi][nj][3] = l3;
                m0 = fmaxf(m0, fmaxf(l0, l1)); m1 = fmaxf(m1, fmaxf(l2, l3));
            }
            m0 = qred_max(m0); m1 = qred_max(m1);
            if ((lane & 3) == 0) {
                int r0 = wr * 64 + mi * 16 + (lane >> 2);
                sred[r0 * 4 + wc] = m0;
                sred[(r0 + 8) * 4 + wc] = m1;
            }
        }
        __syncthreads();
        // exp + row sum
        #pragma unroll
        for (int mi = 0; mi < 4; mi++) {
            int r0 = wr * 64 + mi * 16 + (lane >> 2), r1 = r0 + 8;
            float M0 = fmaxf(fmaxf(sred[r0 * 4], sred[r0 * 4 + 1]),
                             fmaxf(sred[r0 * 4 + 2], sred[r0 * 4 + 3]));
            float M1 = fmaxf(fmaxf(sred[r1 * 4], sred[r1 * 4 + 1]),
                             fmaxf(sred[r1 * 4 + 2], sred[r1 * 4 + 3]));
            float s0 = 0.f, s1 = 0.f;
            #pragma unroll
            for (int nj = 0; nj < 4; nj++) {
                const int col = wc * 32 + nj * 8 + (lane & 3) * 2;
                bool ok = col < SLOT;
                float e0 = ok ? __expf(acc[mi][nj][0] - M0) : 0.f;
                float e1 = ok ? __expf(acc[mi][nj][1] - M0) : 0.f;
                float e2 = ok ? __expf(acc[mi][nj][2] - M1) : 0.f;
                float e3 = ok ? __expf(acc[mi][nj][3] - M1) : 0.f;
                acc[mi][nj][0] = e0; acc[mi][nj][1] = e1;
                acc[mi][nj][2] = e2; acc[mi][nj][3] = e3;
                s0 += e0 + e1; s1 += e2 + e3;
            }
            s0 = qred_sum(s0); s1 = qred_sum(s1);
            if ((lane & 3) == 0) {
                ssum[r0 * 4 + wc] = s0;
                ssum[r1 * 4 + wc] = s1;
            }
        }
        __syncthreads();
        // normalize + split store
        #pragma unroll
        for (int mi = 0; mi < 4; mi++) {
            int r0l = wr * 64 + mi * 16 + (lane >> 2), r1l = r0l + 8;
            float i0 = 1.0f / (ssum[r0l * 4] + ssum[r0l * 4 + 1] + ssum[r0l * 4 + 2] + ssum[r0l * 4 + 3]);
            float i1 = 1.0f / (ssum[r1l * 4] + ssum[r1l * 4 + 1] + ssum[r1l * 4 + 2] + ssum[r1l * 4 + 3]);
            long long R0 = (long long)(blockRow + r0l) * ldc;
            long long R1 = (long long)(blockRow + r1l) * ldc;
            #pragma unroll
            for (int nj = 0; nj < 4; nj++) {
                const int col = wc * 32 + nj * 8 + (lane & 3) * 2;
                if (EPI == 3 && col >= SLOT) continue;   // EPI 5 writes zero pads (e==0)
                spair(Ch, Cl, R0 + col, acc[mi][nj][0] * i0, acc[mi][nj][1] * i0);
                spair(Ch, Cl, R1 + col, acc[mi][nj][2] * i1, acc[mi][nj][3] * i1);
            }
        }
    }
}

// ---------------- reductions ----------------
__device__ __forceinline__ float blockReduceSum(float v, float* red) {
    int lane = threadIdx.x & 31, w = threadIdx.x >> 5;
    #pragma unroll
    for (int o = 16; o; o >>= 1) v += __shfl_down_sync(0xffffffffu, v, o);
    if (lane == 0) red[w] = v;
    __syncthreads();
    int nw = blockDim.x >> 5;
    float r = (threadIdx.x < nw) ? red[threadIdx.x] : 0.0f;
    if (w == 0) {
        #pragma unroll
        for (int o = 16; o; o >>= 1) r += __shfl_down_sync(0xffffffffu, r, o);
        if (lane == 0) red[0] = r;
    }
    __syncthreads();
    float out = red[0];
    __syncthreads();
    return out;
}

// ---------------- elementwise kernels ----------------
__global__ void split_kernel(const float4* __restrict__ src, __nv_bfloat16* __restrict__ h,
                             __nv_bfloat16* __restrict__ l, long long n4) {
    long long i = (long long)blockIdx.x * 256 + threadIdx.x;
    if (i >= n4) return;
    float4 v = src[i];
    __nv_bfloat16 h0 = __float2bfloat16_rn(v.x), h1 = __float2bfloat16_rn(v.y);
    __nv_bfloat16 h2 = __float2bfloat16_rn(v.z), h3 = __float2bfloat16_rn(v.w);
    *(__nv_bfloat162*)(h + i * 4)     = __halves2bfloat162(h0, h1);
    *(__nv_bfloat162*)(h + i * 4 + 2) = __halves2bfloat162(h2, h3);
    *(__nv_bfloat162*)(l + i * 4) = __halves2bfloat162(
        __float2bfloat16_rn(v.x - __bfloat162float(h0)),
        __float2bfloat16_rn(v.y - __bfloat162float(h1)));
    *(__nv_bfloat162*)(l + i * 4 + 2) = __halves2bfloat162(
        __float2bfloat16_rn(v.z - __bfloat162float(h2)),
        __float2bfloat16_rn(v.w - __bfloat162float(h3)));
}

__global__ void l2norm64_split(const float* __restrict__ src,
                               __nv_bfloat16* __restrict__ h, __nv_bfloat16* __restrict__ l,
                               int nseg) {
    int seg = blockIdx.x * 8 + (threadIdx.x >> 5);
    if (seg >= nseg) return;
    int lane = threadIdx.x & 31;
    long long base = (long long)seg * 64;
    float a = src[base + lane], b = src[base + lane + 32];
    float s = a * a + b * b;
    #pragma unroll
    for (int o = 16; o; o >>= 1) s += __shfl_xor_sync(0xffffffffu, s, o);
    float inv = 1.0f / fmaxf(sqrtf(s), 1e-12f);
    wsplit(h, l, base + lane, a * inv);
    wsplit(h, l, base + lane + 32, b * inv);
}

__global__ void vnorm_split_kernel(const float* __restrict__ src, float* __restrict__ dst,
                                   __nv_bfloat16* __restrict__ h, __nv_bfloat16* __restrict__ l) {
    __shared__ float red[32];
    long long r = blockIdx.x;
    float x[4], s = 0.0f;
    #pragma unroll
    for (int i = 0; i < 4; i++) {
        x[i] = src[r * DIM + threadIdx.x + 128 * i];
        s += x[i] * x[i];
    }
    s = blockReduceSum(s, red);
    float inv = 1.0f / fmaxf(sqrtf(s), 1e-12f);
    #pragma unroll
    for (int i = 0; i < 4; i++) {
        long long idx = r * DIM + threadIdx.x + 128 * i;
        float v = x[i] * inv;
        dst[idx] = v;
        wsplit(h, l, idx, v);
    }
}

__global__ void vmemT_split(const float* __restrict__ vm,
                            __nv_bfloat16* __restrict__ h, __nv_bfloat16* __restrict__ l) {
    int idx = blockIdx.x * 256 + threadIdx.x;
    if (idx < DIM * 128) {
        int j = idx >> 7, s = idx & 127;
        float v = (s < SLOT) ? vm[(long long)s * DIM + j] : 0.0f;
        wsplit(h, l, idx, v);
    }
}

__global__ void invn_combine(const float* __restrict__ gpart, float* __restrict__ invn) {
    int i = blockIdx.x * 256 + threadIdx.x;
    if (i < NROWS) {
        float s = gpart[i * 4] + gpart[i * 4 + 1] + gpart[i * 4 + 2] + gpart[i * 4 + 3];
        invn[i] = 1.0f / fmaxf(sqrtf(s), 1e-12f);
    }
}

__global__ void fuse_te_kernel(const float* __restrict__ virpre, const float* __restrict__ query,
                               const float* __restrict__ g1, const float* __restrict__ b1,
                               const float* __restrict__ g2, const float* __restrict__ b2,
                               float* __restrict__ out_te)
{
    __shared__ float red[32];
    long long r = blockIdx.x;
    const float* vp = virpre + r * DIM;
    const float* q  = query  + r * DIM;
    float x[4], qv[4];
    float s = 0.f, s2 = 0.f;
    #pragma unroll
    for (int i = 0; i < 4; i++) {
        int c = threadIdx.x + 128 * i;
        x[i] = vp[c]; qv[i] = q[c];
        s += x[i]; s2 += x[i] * x[i];
    }
    s  = blockReduceSum(s,  red);
    s2 = blockReduceSum(s2, red);
    float mu = s * (1.0f / DIM);
    float var = s2 * (1.0f / DIM) - mu * mu;
    float inv = rsqrtf(var + 1e-5f);
    float t[4]; float ts = 0.f, ts2 = 0.f;
    #pragma unroll
    for (int i = 0; i < 4; i++) {
        int c = threadIdx.x + 128 * i;
        float ln = (x[i] - mu) * inv * g2[c] + b2[c];
        t[i] = qv[i] + ln; ts += t[i]; ts2 += t[i] * t[i];
    }
    ts  = blockReduceSum(ts,  red);
    ts2 = blockReduceSum(ts2, red);
    mu = ts * (1.0f / DIM);
    var = ts2 * (1.0f / DIM) - mu * mu;
    inv = rsqrtf(var + 1e-5f);
    #pragma unroll
    for (int i = 0; i < 4; i++) {
        int c = threadIdx.x + 128 * i;
        out_te[r * DIM + c] = (t[i] - mu) * inv * g1[c] + b1[c];
    }
}

__global__ void fuse_tr_kernel(const float* __restrict__ aud, const float* __restrict__ query,
                               const float* __restrict__ value,
                               const float* __restrict__ g1, const float* __restrict__ b1,
                               const float* __restrict__ g3, const float* __restrict__ b3,
                               float* __restrict__ out_tr, float* __restrict__ cosbuf)
{
    __shared__ float red[32];
    long long r = blockIdx.x;
    const float* a = aud   + r * DIM;
    const float* q = query + r * DIM;
    const float* v = value + r * DIM;
    float av[4], qv[4], vv[4];
    float sa = 0.f, saa = 0.f, sav = 0.f, svv = 0.f;
    #pragma unroll
    for (int i = 0; i < 4; i++) {
        int c = threadIdx.x + 128 * i;
        av[i] = a[c]; qv[i] = q[c]; vv[i] = v[c];
        sa += av[i]; saa += av[i] * av[i]; sav += av[i] * vv[i]; svv += vv[i] * vv[i];
    }
    sa  = blockReduceSum(sa,  red);
    saa = blockReduceSum(saa, red);
    sav = blockReduceSum(sav, red);
    svv = blockReduceSum(svv, red);
    if (threadIdx.x == 0) {
        float cosv = sav / fmaxf(sqrtf(saa) * sqrtf(svv), 1e-8f);
        cosbuf[r] = fabsf(1.0f - cosv);
    }
    float mu = sa * (1.0f / DIM);
    float var = saa * (1.0f / DIM) - mu * mu;
    float inv = rsqrtf(var + 1e-5f);
    float t[4]; float ts = 0.f, ts2 = 0.f;
    #pragma unroll
    for (int i = 0; i < 4; i++) {
        int c = threadIdx.x + 128 * i;
        float ln = (av[i] - mu) * inv * g3[c] + b3[c];
        t[i] = qv[i] + ln; ts += t[i]; ts2 += t[i] * t[i];
    }
    ts  = blockReduceSum(ts,  red);
    ts2 = blockReduceSum(ts2, red);
    mu = ts * (1.0f / DIM);
    var = ts2 * (1.0f / DIM) - mu * mu;
    inv = rsqrtf(var + 1e-5f);
    #pragma unroll
    for (int i = 0; i < 4; i++) {
        int c = threadIdx.x + 128 * i;
        out_tr[r * DIM + c] = (t[i] - mu) * inv * g1[c] + b1[c];
    }
}

__global__ void recon_reduce_kernel(const float* __restrict__ cosbuf, float* __restrict__ recon) {
    __shared__ float red[32];
    int b = blockIdx.x;
    float s = 0.0f;
    for (int i = threadIdx.x; i < 512; i += blockDim.x) s += cosbuf[b * 512 + i];
    s = blockReduceSum(s, red);
    if (threadIdx.x == 0) recon[b] = s;
}

__global__ void contrastive_partial_kernel(const float* __restrict__ vnorm, float* __restrict__ part) {
    __shared__ float vi[DIM];
    __shared__ float red[32];
    int i = blockIdx.x;
    for (int c = threadIdx.x; c < DIM; c += blockDim.x) vi[c] = vnorm[(long long)i * DIM + c];
    __syncthreads();
    int w = threadIdx.x >> 5, lane = threadIdx.x & 31;
    float s = 0.0f;
    for (int j = w; j < SLOT; j += 4) {
        float d = 0.0f;
        for (int c = lane; c < DIM; c += 32) d += vi[c] * vnorm[(long long)j * DIM + c];
        #pragma unroll
        for (int o = 16; o; o >>= 1) d += __shfl_down_sync(0xffffffffu, d, o);
        if (lane == 0) s += fabsf(((i == j) ? 1.0f : 0.0f) - d);
    }
    s = blockReduceSum(s, red);
    if (threadIdx.x == 0) part[i] = s;
}

__global__ void contrastive_final_kernel(const float* __restrict__ part, float* __restrict__ out) {
    if (threadIdx.x == 0) {
        float s = 0.0f;
        for (int i = 0; i < SLOT; i++) s += part[i];
        out[0] = 0.5f * s;
    }
}

// ---------------- launch ----------------
#define SYM(p, s) cudaGetSymbolAddress((void**)&p, s)

extern "C" void kernel_launch(void* const* d_in, const int* in_sizes, int n_in,
                              void* d_out, int out_size)
{
    const float* query     = (const float*)d_in[0];
    const float* value     = (const float*)d_in[1];
    const float* key_mem   = (const float*)d_in[2];
    const float* value_mem = (const float*)d_in[3];
    const float* Wq = (const float*)d_in[4];
    const float* bq = (const float*)d_in[5];
    const float* Wv = (const float*)d_in[6];
    const float* bv = (const float*)d_in[7];
    const float* Wl = (const float*)d_in[8];
    const float* bl = (const float*)d_in[9];
    const float* g1 = (const float*)d_in[10];
    const float* b1 = (const float*)d_in[11];
    const float* g2 = (const float*)d_in[12];
    const float* b2 = (const float*)d_in[13];
    const float* g3 = (const float*)d_in[14];
    const float* b3 = (const float*)d_in[15];

    float* out        = (float*)d_out;
    float* out_te     = out;
    float* out_tr     = out + (long long)NROWS * DIM;
    float* out_recon  = out + 2ll * NROWS * DIM;
    float* out_contr  = out_recon + 32;

    float *p_virpre, *p_aud, *p_vnorm, *p_invn, *p_invkn, *p_gpart, *p_cos, *p_cpart;
    SYM(p_virpre, g_virpre); SYM(p_aud, g_aud); SYM(p_vnorm, g_vnorm);
    SYM(p_invn, g_invn); SYM(p_invkn, g_invkn); SYM(p_gpart, g_gpart);
    SYM(p_cos, g_cosbuf); SYM(p_cpart, g_cpart);

    __nv_bfloat16 *q_h, *q_l, *v_h, *v_l, *wq_h, *wq_l, *wv_h, *wv_l, *wl_h, *wl_l;
    __nv_bfloat16 *vm_h, *vm_l, *eqn_h, *eqn_l, *kn_h, *kn_l, *ka_h, *ka_l, *m2_h, *m2_l;
    __nv_bfloat16 *ev_h, *ev_l, *vn_h, *vn_l, *va_h, *va_l, *vt_h, *vt_l;
    SYM(q_h, g_q_h); SYM(q_l, g_q_l); SYM(v_h, g_v_h); SYM(v_l, g_v_l);
    SYM(wq_h, g_wq_h); SYM(wq_l, g_wq_l); SYM(wv_h, g_wv_h); SYM(wv_l, g_wv_l);
    SYM(wl_h, g_wl_h); SYM(wl_l, g_wl_l); SYM(vm_h, g_vm_h); SYM(vm_l, g_vm_l);
    SYM(eqn_h, g_eqn_h); SYM(eqn_l, g_eqn_l); SYM(kn_h, g_kn_h); SYM(kn_l, g_kn_l);
    SYM(ka_h, g_ka_h); SYM(ka_l, g_ka_l); SYM(m2_h, g_m2_h); SYM(m2_l, g_m2_l);
    SYM(ev_h, g_ev_h); SYM(ev_l, g_ev_l); SYM(vn_h, g_vn_h); SYM(vn_l, g_vn_l);
    SYM(va_h, g_va_h); SYM(va_l, g_va_l); SYM(vt_h, g_vt_h); SYM(vt_l, g_vt_l);

    cudaFuncSetAttribute(gemm_nt<0, false, true >, cudaFuncAttributeMaxDynamicSharedMemorySize, GSMEM);
    cudaFuncSetAttribute(gemm_nt<0, false, false>, cudaFuncAttributeMaxDynamicSharedMemorySize, GSMEM);
    cudaFuncSetAttribute(gemm_nt<1, true,  false>, cudaFuncAttributeMaxDynamicSharedMemorySize, GSMEM);
    cudaFuncSetAttribute(gemm_nt<2, false, true >, cudaFuncAttributeMaxDynamicSharedMemorySize, GSMEM);
    cudaFuncSetAttribute(gemm_nt<3, true,  false>, cudaFuncAttributeMaxDynamicSharedMemorySize, GSMEM);
    cudaFuncSetAttribute(gemm_nt<4, false, true >, cudaFuncAttributeMaxDynamicSharedMemorySize, GSMEM);
    cudaFuncSetAttribute(gemm_nt<5, true,  false>, cudaFuncAttributeMaxDynamicSharedMemorySize, GSMEM);

    // launches 0-4: splits feeding the eq GEMM (ncu -s 5 captures launch #5 = eq GEMM)
    split_kernel<<<(NROWS * DIM / 4 + 255) / 256, 256>>>((const float4*)query, q_h, q_l, NROWS * DIM / 4);
    split_kernel<<<(DIM * DIM / 4 + 255) / 256, 256>>>((const float4*)Wq, wq_h, wq_l, DIM * DIM / 4);
    split_kernel<<<(NROWS * DIM / 4 + 255) / 256, 256>>>((const float4*)value, v_h, v_l, NROWS * DIM / 4);
    split_kernel<<<(DIM * DIM / 4 + 255) / 256, 256>>>((const float4*)Wv, wv_h, wv_l, DIM * DIM / 4);
    split_kernel<<<(DIM * DIM * HEAD / 4 + 255) / 256, 256>>>((const float4*)Wl, wl_h, wl_l, DIM * DIM * HEAD / 4);

    // launch 5: eq = q@Wq^T + bq, epilogue: split out + per-head invnorm
    gemm_nt<2, false, true><<<dim3(4, 128, 1), 256, GSMEM>>>(
        q_h, q_l, DIM, 0, wq_h, wq_l, DIM, 0,
        nullptr, eqn_h, eqn_l, DIM, 0, bq, nullptr, p_invkn, DIM, DIM);

    // small precomputes
    split_kernel<<<(SLOT * DIM / 4 + 255) / 256, 256>>>((const float4*)value_mem, vm_h, vm_l, SLOT * DIM / 4);
    l2norm64_split<<<HEAD * SLOT / 8, 256>>>(key_mem, kn_h, kn_l, HEAD * SLOT);
    vnorm_split_kernel<<<SLOT, 128>>>(value_mem, p_vnorm, vn_h, vn_l);
    contrastive_partial_kernel<<<SLOT, 128>>>(p_vnorm, p_cpart);
    contrastive_final_kernel<<<1, 32>>>(p_cpart, out_contr);
    vmemT_split<<<(DIM * 128) / 256, 256>>>(value_mem, vt_h, vt_l);

    // M2T[j, h*112+s] = sum_d Wl[j, h*512+d] * value_mem[s, d]
    gemm_nt<1, true, false><<<dim3(1, 4, HEAD), 256, GSMEM>>>(
        wl_h, wl_l, HEAD * DIM, 512, vm_h, vm_l, DIM, 0,
        nullptr, m2_h, m2_l, HEAD * SLOT, 112, nullptr, nullptr, nullptr, SLOT, DIM);

    // key_sim + fused softmax -> ka split
    gemm_nt<3, true, false><<<dim3(1, 128, HEAD), 256, GSMEM>>>(
        eqn_h, eqn_l, DIM, HD, kn_h, kn_l, HD, (long long)SLOT * HD,
        nullptr, ka_h, ka_l, HEAD * SLOT, SLOT, nullptr, p_invkn, nullptr, SLOT, HD);

    // virpre = ka @ M2 + bl
    gemm_nt<0, false, true><<<dim3(4, 128, 1), 256, GSMEM>>>(
        ka_h, ka_l, HEAD * SLOT, 0, m2_h, m2_l, HEAD * SLOT, 0,
        p_virpre, nullptr, nullptr, DIM, 0, bl, nullptr, nullptr, DIM, HEAD * SLOT);
    fuse_te_kernel<<<NROWS, 128>>>(p_virpre, query, g1, b1, g2, b2, out_te);

    // ev = v@Wv^T + bv, epilogue: split out + row sumsq partials
    gemm_nt<4, false, true><<<dim3(4, 128, 1), 256, GSMEM>>>(
        v_h, v_l, DIM, 0, wv_h, wv_l, DIM, 0,
        nullptr, ev_h, ev_l, DIM, 0, bv, nullptr, p_gpart, DIM, DIM);
    invn_combine<<<(NROWS + 255) / 256, 256>>>(p_gpart, p_invn);

    // value_sim + fused softmax -> va split (stride 128, zero pads)
    gemm_nt<5, true, false><<<dim3(1, 128, 1), 256, GSMEM>>>(
        ev_h, ev_l, DIM, 0, vn_h, vn_l, DIM, 0,
        nullptr, va_h, va_l, 128, 0, nullptr, p_invn, nullptr, SLOT, DIM);

    // aud = va @ vmemT^T
    gemm_nt<0, false, false><<<dim3(4, 128, 1), 256, GSMEM>>>(
        va_h, va_l, 128, 0, vt_h, vt_l, 128, 0,
        p_aud, nullptr, nullptr, DIM, 0, nullptr, nullptr, nullptr, DIM, 128);
    fuse_tr_kernel<<<NROWS, 128>>>(p_aud, query, value, g1, b1, g3, b3, out_tr, p_cos);
    recon_reduce_kernel<<<32, 128>>>(p_cos, out_recon);
}

// round 5
// speedup vs baseline: 2.5199x; 1.0770x over previous
#include <cuda_runtime.h>
#include <cuda_bf16.h>
#include <cstdint>

#define NROWS 16384   // B*S
#define DIM 512
#define HEAD 8
#define SLOT 112
#define HD 64
#define RADIUSF 16.0f

// ---------------- scratch (device globals) ----------------
__device__ float g_virpre[NROWS * DIM];
__device__ float g_aud[NROWS * DIM];
__device__ float g_invkn[NROWS * HEAD];
__device__ float g_gpart[NROWS * 4];
__device__ float g_cosbuf[NROWS];
__device__ float g_cpart[SLOT];
// bf16 split pairs
__device__ __nv_bfloat16 g_q_h[NROWS * DIM],  g_q_l[NROWS * DIM];
__device__ __nv_bfloat16 g_v_h[NROWS * DIM],  g_v_l[NROWS * DIM];
__device__ __nv_bfloat16 g_wq_h[DIM * DIM],   g_wq_l[DIM * DIM];
__device__ __nv_bfloat16 g_wv_h[DIM * DIM],   g_wv_l[DIM * DIM];
__device__ __nv_bfloat16 g_wl_h[DIM * DIM * HEAD], g_wl_l[DIM * DIM * HEAD];
__device__ __nv_bfloat16 g_vm_h[SLOT * DIM],  g_vm_l[SLOT * DIM];
__device__ __nv_bfloat16 g_eqn_h[NROWS * DIM], g_eqn_l[NROWS * DIM];
__device__ __nv_bfloat16 g_kn_h[HEAD * SLOT * HD], g_kn_l[HEAD * SLOT * HD];
__device__ __nv_bfloat16 g_ka_h[NROWS * HEAD * SLOT], g_ka_l[NROWS * HEAD * SLOT];
__device__ __nv_bfloat16 g_m2_h[DIM * HEAD * SLOT],   g_m2_l[DIM * HEAD * SLOT];
__device__ __nv_bfloat16 g_ev_h[NROWS * DIM], g_ev_l[NROWS * DIM];
__device__ __nv_bfloat16 g_vn_h[SLOT * DIM],  g_vn_l[SLOT * DIM];
__device__ __nv_bfloat16 g_va_h[NROWS * 128], g_va_l[NROWS * 128];
__device__ __nv_bfloat16 g_vt_h[DIM * 128],   g_vt_l[DIM * 128];

// ---------------- helpers ----------------
__device__ __forceinline__ uint32_t smem_u32(const void* p) {
    uint32_t a;
    asm("{ .reg .u64 t; cvta.to.shared.u64 t, %1; cvt.u32.u64 %0, t; }" : "=r"(a) : "l"(p));
    return a;
}
__device__ __forceinline__ void cp16(uint32_t dst, const void* src, int sz) {
    asm volatile("cp.async.cg.shared.global [%0], [%1], 16, %2;"
                 :: "r"(dst), "l"(src), "r"(sz));
}
__device__ __forceinline__ void cp_commit() { asm volatile("cp.async.commit_group;" ::: "memory"); }
__device__ __forceinline__ void cp_wait2()  { asm volatile("cp.async.wait_group 2;"  ::: "memory"); }

__device__ __forceinline__ void ldm4(uint32_t (&r)[4], uint32_t a) {
    asm volatile("ldmatrix.sync.aligned.m8n8.x4.shared.b16 {%0,%1,%2,%3}, [%4];"
                 : "=r"(r[0]), "=r"(r[1]), "=r"(r[2]), "=r"(r[3]) : "r"(a));
}
__device__ __forceinline__ void mma16816(float (&c)[4], const uint32_t (&a)[4],
                                         uint32_t b0, uint32_t b1) {
    asm volatile(
        "mma.sync.aligned.m16n8k16.row.col.f32.bf16.bf16.f32 "
        "{%0,%1,%2,%3}, {%4,%5,%6,%7}, {%8,%9}, {%0,%1,%2,%3};"
        : "+f"(c[0]), "+f"(c[1]), "+f"(c[2]), "+f"(c[3])
        : "r"(a[0]), "r"(a[1]), "r"(a[2]), "r"(a[3]), "r"(b0), "r"(b1));
}
__device__ __forceinline__ void wsplit(__nv_bfloat16* h, __nv_bfloat16* l, long long i, float v) {
    __nv_bfloat16 hh = __float2bfloat16_rn(v);
    h[i] = hh;
    l[i] = __float2bfloat16_rn(v - __bfloat162float(hh));
}
__device__ __forceinline__ void spair(__nv_bfloat16* H, __nv_bfloat16* L, long long i,
                                      float a, float b) {
    __nv_bfloat16 h0 = __float2bfloat16_rn(a), h1 = __float2bfloat16_rn(b);
    *(__nv_bfloat162*)(H + i) = __halves2bfloat162(h0, h1);
    *(__nv_bfloat162*)(L + i) = __halves2bfloat162(
        __float2bfloat16_rn(a - __bfloat162float(h0)),
        __float2bfloat16_rn(b - __bfloat162float(h1)));
}
__device__ __forceinline__ float qred_sum(float v) {
    v += __shfl_xor_sync(0xffffffffu, v, 1);
    v += __shfl_xor_sync(0xffffffffu, v, 2);
    return v;
}
__device__ __forceinline__ float qred_max(float v) {
    v = fmaxf(v, __shfl_xor_sync(0xffffffffu, v, 1));
    v = fmaxf(v, __shfl_xor_sync(0xffffffffu, v, 2));
    return v;
}
__device__ __forceinline__ float blockReduceSum(float v, float* red) {
    int lane = threadIdx.x & 31, w = threadIdx.x >> 5;
    #pragma unroll
    for (int o = 16; o; o >>= 1) v += __shfl_down_sync(0xffffffffu, v, o);
    if (lane == 0) red[w] = v;
    __syncthreads();
    int nw = blockDim.x >> 5;
    float r = (threadIdx.x < nw) ? red[threadIdx.x] : 0.0f;
    if (w == 0) {
        #pragma unroll
        for (int o = 16; o; o >>= 1) r += __shfl_down_sync(0xffffffffu, r, o);
        if (lane == 0) red[0] = r;
    }
    __syncthreads();
    float out = red[0];
    __syncthreads();
    return out;
}

// ---------------- bf16-split HMMA GEMM with fused epilogues ----------------
// C[m,n] = sum_k (Ah+Al)[m,k]*(Bh+Bl)[n,k] (+bias[n])  via hh+hl+lh
// EPI: 0 = f32 out; 1 = split out
//      3 = fused key softmax (scale R*auxin[row*8+z]) -> split out
//      5 = fused val softmax (scale R*rsqrt(sum4 auxin[row*4+...])) -> split out + zero pads
//      6 = batched qv: z==0 split out + per-64seg invnorm->auxout; z==1 split out + row sumsq partials->auxout2
#define ROWB   80
#define HALFB  10240
#define STAGEB 40960
#define NST    4
#define GSMEM  (NST * STAGEB)

template<int EPI, bool NGUARD, bool HASBIAS>
__global__ void __launch_bounds__(256, 1) gemm_nt(
    const __nv_bfloat16* __restrict__ Ah, const __nv_bfloat16* __restrict__ Al,
    int lda, long long sA,
    const __nv_bfloat16* __restrict__ Bh, const __nv_bfloat16* __restrict__ Bl,
    int ldb, long long sB,
    float* __restrict__ Cf, __nv_bfloat16* __restrict__ Ch, __nv_bfloat16* __restrict__ Cl,
    int ldc, long long sC,
    const float* __restrict__ bias,
    const float* __restrict__ auxin, float* __restrict__ auxout,
    int N, int K,
    const __nv_bfloat16* Ah2, const __nv_bfloat16* Al2,
    const __nv_bfloat16* Bh2, const __nv_bfloat16* Bl2,
    __nv_bfloat16* Ch2, __nv_bfloat16* Cl2,
    const float* bias2, float* auxout2)
{
    extern __shared__ char smem[];
    const uint32_t sb = smem_u32(smem);
    const int tid = threadIdx.x, lane = tid & 31, wid = tid >> 5;
    const int wr = wid >> 2, wc = wid & 3;
    const long long z = blockIdx.z;
    const int blockRow = blockIdx.y * 128, blockCol = blockIdx.x * 128;

    if (EPI == 6 && z == 1) {
        Ah = Ah2; Al = Al2; Bh = Bh2; Bl = Bl2;
        Ch = Ch2; Cl = Cl2; bias = bias2; auxout = auxout2;
    }

    Ah += z * sA + (long long)blockRow * lda;
    Al += z * sA + (long long)blockRow * lda;
    Bh += z * sB + (long long)blockCol * ldb;
    Bl += z * sB + (long long)blockCol * ldb;

    const int nvalid = N - blockCol;
    const int nc = K >> 5;

    auto issue = [&](int st, int c) {
        #pragma unroll
        for (int j = 0; j < 2; j++) {
            int id = tid + j * 256;
            int row = id >> 2, ch = id & 3;
            long long offa = (long long)row * lda + c * 32 + ch * 8;
            uint32_t d = sb + st * STAGEB + row * ROWB + ch * 16;
            cp16(d,         Ah + offa, 16);
            cp16(d + HALFB, Al + offa, 16);
            long long offb = (long long)row * ldb + c * 32 + ch * 8;
            int vb = (!NGUARD || row < nvalid) ? 16 : 0;
            if (vb == 0) offb = 0;
            cp16(d + 2 * HALFB, Bh + offb, vb);
            cp16(d + 3 * HALFB, Bl + offb, vb);
        }
    };

    float acc[4][4][4];
    #pragma unroll
    for (int i = 0; i < 4; i++)
        #pragma unroll
        for (int j = 0; j < 4; j++)
            #pragma unroll
            for (int t = 0; t < 4; t++) acc[i][j][t] = 0.0f;

    #pragma unroll
    for (int p = 0; p < NST - 1; p++) {
        if (p < nc) issue(p, p);
        cp_commit();
    }

    const int rA = lane & 15, cA = lane >> 4;
    const int rB = (lane & 7) + ((lane >> 4) << 3), cB = (lane >> 3) & 1;

    for (int c = 0; c < nc; c++) {
        cp_wait2();
        __syncthreads();
        const uint32_t base = sb + (c & (NST - 1)) * STAGEB;
        #pragma unroll
        for (int k16 = 0; k16 < 2; k16++) {
            const int k2 = k16 * 2;
            uint32_t fAh[4][4], fAl[4][4], fBh[2][4], fBl[2][4];
            #pragma unroll
            for (int mi = 0; mi < 4; mi++) {
                uint32_t a = base + (uint32_t)((wr * 64 + mi * 16 + rA) * ROWB + (k2 + cA) * 16);
                ldm4(fAh[mi], a);
                ldm4(fAl[mi], a + HALFB);
            }
            #pragma unroll
            for (int ni = 0; ni < 2; ni++) {
                uint32_t b = base + 2 * HALFB +
                             (uint32_t)((wc * 32 + ni * 16 + rB) * ROWB + (k2 + cB) * 16);
                ldm4(fBh[ni], b);
                ldm4(fBl[ni], b + HALFB);
            }
            #pragma unroll
            for (int mi = 0; mi < 4; mi++)
                #pragma unroll
                for (int nj = 0; nj < 4; nj++) {
                    const int bi = nj >> 1, bs = (nj & 1) * 2;
                    mma16816(acc[mi][nj], fAh[mi], fBh[bi][bs], fBh[bi][bs + 1]);
                    mma16816(acc[mi][nj], fAh[mi], fBl[bi][bs], fBl[bi][bs + 1]);
                    mma16816(acc[mi][nj], fAl[mi], fBh[bi][bs], fBh[bi][bs + 1]);
                }
        }
        __syncthreads();
        int nxt = c + NST - 1;
        if (nxt < nc) issue(nxt & (NST - 1), nxt);
        cp_commit();
    }

    // ---------------- epilogue ----------------
    float* sred = (float*)smem;
    float* ssum = sred + 512;

    if (HASBIAS) {
        #pragma unroll
        for (int nj = 0; nj < 4; nj++) {
            const int col = blockCol + wc * 32 + nj * 8 + (lane & 3) * 2;
            float b0 = bias[col], b1 = bias[col + 1];
            #pragma unroll
            for (int mi = 0; mi < 4; mi++) {
                acc[mi][nj][0] += b0; acc[mi][nj][1] += b1;
                acc[mi][nj][2] += b0; acc[mi][nj][3] += b1;
            }
        }
    }

    Cf += z * sC; Ch += z * sC; Cl += z * sC;

    if (EPI == 6) {
        #pragma unroll
        for (int mi = 0; mi < 4; mi++) {
            float s0 = 0.f, s1 = 0.f;
            #pragma unroll
            for (int nj = 0; nj < 4; nj++) {
                s0 += acc[mi][nj][0] * acc[mi][nj][0] + acc[mi][nj][1] * acc[mi][nj][1];
                s1 += acc[mi][nj][2] * acc[mi][nj][2] + acc[mi][nj][3] * acc[mi][nj][3];
            }
            s0 = qred_sum(s0); s1 = qred_sum(s1);
            if ((lane & 3) == 0) {
                int r0 = wr * 64 + mi * 16 + (lane >> 2);
                sred[r0 * 4 + wc] = s0;
                sred[(r0 + 8) * 4 + wc] = s1;
            }
        }
        __syncthreads();
        if (z == 0) {
            if ((wc == 0 || wc == 2) && (lane & 3) == 0) {
                #pragma unroll
                for (int mi = 0; mi < 4; mi++)
                    #pragma unroll
                    for (int half = 0; half < 2; half++) {
                        int r = wr * 64 + mi * 16 + (lane >> 2) + half * 8;
                        float s = sred[r * 4 + wc] + sred[r * 4 + wc + 1];
                        auxout[(long long)(blockRow + r) * HEAD + blockIdx.x * 2 + (wc >> 1)]
                            = 1.0f / fmaxf(sqrtf(s), 1e-12f);
                    }
            }
        } else {
            if (wc == 0 && (lane & 3) == 0) {
                #pragma unroll
                for (int mi = 0; mi < 4; mi++)
                    #pragma unroll
                    for (int half = 0; half < 2; half++) {
                        int r = wr * 64 + mi * 16 + (lane >> 2) + half * 8;
                        float s = sred[r * 4] + sred[r * 4 + 1] + sred[r * 4 + 2] + sred[r * 4 + 3];
                        auxout[(long long)(blockRow + r) * 4 + blockIdx.x] = s;
                    }
            }
        }
    }

    if (EPI == 0 || EPI == 1 || EPI == 6) {
        #pragma unroll
        for (int mi = 0; mi < 4; mi++) {
            long long R0 = (long long)(blockRow + wr * 64 + mi * 16 + (lane >> 2)) * ldc;
            long long R1 = R0 + 8LL * ldc;
            #pragma unroll
            for (int nj = 0; nj < 4; nj++) {
                int col = blockCol + wc * 32 + nj * 8 + (lane & 3) * 2;
                if (NGUARD && col >= N) continue;
                if (EPI == 0) {
                    *(float2*)(Cf + R0 + col) = make_float2(acc[mi][nj][0], acc[mi][nj][1]);
                    *(float2*)(Cf + R1 + col) = make_float2(acc[mi][nj][2], acc[mi][nj][3]);
                } else {
                    spair(Ch, Cl, R0 + col, acc[mi][nj][0], acc[mi][nj][1]);
                    spair(Ch, Cl, R1 + col, acc[mi][nj][2], acc[mi][nj][3]);
                }
            }
        }
    }

    if (EPI == 3 || EPI == 5) {
        float scl[4][2];
        #pragma unroll
        for (int mi = 0; mi < 4; mi++)
            #pragma unroll
            for (int half = 0; half < 2; half++) {
                int r = blockRow + wr * 64 + mi * 16 + (lane >> 2) + half * 8;
                float iv;
                if (EPI == 3) iv = auxin[(long long)r * HEAD + z];
                else {
                    float s4 = auxin[r * 4] + auxin[r * 4 + 1] + auxin[r * 4 + 2] + auxin[r * 4 + 3];
                    iv = 1.0f / fmaxf(sqrtf(s4), 1e-12f);
                }
                scl[mi][half] = RADIUSF * iv;
            }
        #pragma unroll
        for (int mi = 0; mi < 4; mi++) {
            float m0 = -1e30f, m1 = -1e30f;
            #pragma unroll
            for (int nj = 0; nj < 4; nj++) {
                const int col = wc * 32 + nj * 8 + (lane & 3) * 2;
                bool ok = col < SLOT;
                float l0 = ok ? scl[mi][0] * acc[mi][nj][0] : -1e30f;
                float l1 = ok ? scl[mi][0] * acc[mi][nj][1] : -1e30f;
                float l2 = ok ? scl[mi][1] * acc[mi][nj][2] : -1e30f;
                float l3 = ok ? scl[mi][1] * acc[mi][nj][3] : -1e30f;
                acc[mi][nj][0] = l0; acc[mi][nj][1] = l1;
                acc[mi][nj][2] = l2; acc[mi][nj][3] = l3;
                m0 = fmaxf(m0, fmaxf(l0, l1)); m1 = fmaxf(m1, fmaxf(l2, l3));
            }
            m0 = qred_max(m0); m1 = qred_max(m1);
            if ((lane & 3) == 0) {
                int r0 = wr * 64 + mi * 16 + (lane >> 2);
                sred[r0 * 4 + wc] = m0;
                sred[(r0 + 8) * 4 + wc] = m1;
            }
        }
        __syncthreads();
        #pragma unroll
        for (int mi = 0; mi < 4; mi++) {
            int r0 = wr * 64 + mi * 16 + (lane >> 2), r1 = r0 + 8;
            float M0 = fmaxf(fmaxf(sred[r0 * 4], sred[r0 * 4 + 1]),
                             fmaxf(sred[r0 * 4 + 2], sred[r0 * 4 + 3]));
            float M1 = fmaxf(fmaxf(sred[r1 * 4], sred[r1 * 4 + 1]),
                             fmaxf(sred[r1 * 4 + 2], sred[r1 * 4 + 3]));
            float s0 = 0.f, s1 = 0.f;
            #pragma unroll
            for (int nj = 0; nj < 4; nj++) {
                const int col = wc * 32 + nj * 8 + (lane & 3) * 2;
                bool ok = col < SLOT;
                float e0 = ok ? __expf(acc[mi][nj][0] - M0) : 0.f;
                float e1 = ok ? __expf(acc[mi][nj][1] - M0) : 0.f;
                float e2 = ok ? __expf(acc[mi][nj][2] - M1) : 0.f;
                float e3 = ok ? __expf(acc[mi][nj][3] - M1) : 0.f;
                acc[mi][nj][0] = e0; acc[mi][nj][1] = e1;
                acc[mi][nj][2] = e2; acc[mi][nj][3] = e3;
                s0 += e0 + e1; s1 += e2 + e3;
            }
            s0 = qred_sum(s0); s1 = qred_sum(s1);
            if ((lane & 3) == 0) {
                ssum[r0 * 4 + wc] = s0;
                ssum[r1 * 4 + wc] = s1;
            }
        }
        __syncthreads();
        #pragma unroll
        for (int mi = 0; mi < 4; mi++) {
            int r0l = wr * 64 + mi * 16 + (lane >> 2), r1l = r0l + 8;
            float i0 = 1.0f / (ssum[r0l * 4] + ssum[r0l * 4 + 1] + ssum[r0l * 4 + 2] + ssum[r0l * 4 + 3]);
            float i1 = 1.0f / (ssum[r1l * 4] + ssum[r1l * 4 + 1] + ssum[r1l * 4 + 2] + ssum[r1l * 4 + 3]);
            long long R0 = (long long)(blockRow + r0l) * ldc;
            long long R1 = (long long)(blockRow + r1l) * ldc;
            #pragma unroll
            for (int nj = 0; nj < 4; nj++) {
                const int col = wc * 32 + nj * 8 + (lane & 3) * 2;
                if (EPI == 3 && col >= SLOT) continue;   // EPI 5 writes zero pads
                spair(Ch, Cl, R0 + col, acc[mi][nj][0] * i0, acc[mi][nj][1] * i0);
                spair(Ch, Cl, R1 + col, acc[mi][nj][2] * i1, acc[mi][nj][3] * i1);
            }
        }
    }
}

// ---------------- mega prep: all splits + norms + contrastive partials ----------------
#define NB_Q  8192
#define NB_V  8192
#define NB_WQ 256
#define NB_WV 256
#define NB_WL 2048
#define NB_VM 56
#define NB_KN 112
#define NB_VN 112
#define NB_VT 256
#define NB_CP 112
#define NB_TOTAL (NB_Q+NB_V+NB_WQ+NB_WV+NB_WL+NB_VM+NB_KN+NB_VN+NB_VT+NB_CP)

__device__ __forceinline__ void do_split4(const float4* src, __nv_bfloat16* h,
                                          __nv_bfloat16* l, long long i) {
    float4 v = src[i];
    __nv_bfloat16 h0 = __float2bfloat16_rn(v.x), h1 = __float2bfloat16_rn(v.y);
    __nv_bfloat16 h2 = __float2bfloat16_rn(v.z), h3 = __float2bfloat16_rn(v.w);
    *(__nv_bfloat162*)(h + i * 4)     = __halves2bfloat162(h0, h1);
    *(__nv_bfloat162*)(h + i * 4 + 2) = __halves2bfloat162(h2, h3);
    *(__nv_bfloat162*)(l + i * 4) = __halves2bfloat162(
        __float2bfloat16_rn(v.x - __bfloat162float(h0)),
        __float2bfloat16_rn(v.y - __bfloat162float(h1)));
    *(__nv_bfloat162*)(l + i * 4 + 2) = __halves2bfloat162(
        __float2bfloat16_rn(v.z - __bfloat162float(h2)),
        __float2bfloat16_rn(v.w - __bfloat162float(h3)));
}

__global__ void mega_prep(
    const float* __restrict__ query, const float* __restrict__ value,
    const float* __restrict__ key_mem, const float* __restrict__ value_mem,
    const float* __restrict__ Wq, const float* __restrict__ Wv, const float* __restrict__ Wl,
    __nv_bfloat16* q_h, __nv_bfloat16* q_l, __nv_bfloat16* v_h, __nv_bfloat16* v_l,
    __nv_bfloat16* wq_h, __nv_bfloat16* wq_l, __nv_bfloat16* wv_h, __nv_bfloat16* wv_l,
    __nv_bfloat16* wl_h, __nv_bfloat16* wl_l, __nv_bfloat16* vm_h, __nv_bfloat16* vm_l,
    __nv_bfloat16* kn_h, __nv_bfloat16* kn_l, __nv_bfloat16* vn_h, __nv_bfloat16* vn_l,
    __nv_bfloat16* vt_h, __nv_bfloat16* vt_l, float* cpart)
{
    __shared__ float sh[544];
    int b = blockIdx.x, tid = threadIdx.x;

    if (b < NB_Q) { do_split4((const float4*)query, q_h, q_l, (long long)b * 256 + tid); return; }
    b -= NB_Q;
    if (b < NB_V) { do_split4((const float4*)value, v_h, v_l, (long long)b * 256 + tid); return; }
    b -= NB_V;
    if (b < NB_WQ) { do_split4((const float4*)Wq, wq_h, wq_l, (long long)b * 256 + tid); return; }
    b -= NB_WQ;
    if (b < NB_WV) { do_split4((const float4*)Wv, wv_h, wv_l, (long long)b * 256 + tid); return; }
    b -= NB_WV;
    if (b < NB_WL) { do_split4((const float4*)Wl, wl_h, wl_l, (long long)b * 256 + tid); return; }
    b -= NB_WL;
    if (b < NB_VM) { do_split4((const float4*)value_mem, vm_h, vm_l, (long long)b * 256 + tid); return; }
    b -= NB_VM;
    if (b < NB_KN) {  // key_mem l2norm per 64-seg, 8 segs/block
        int seg = b * 8 + (tid >> 5), lane = tid & 31;
        long long base = (long long)seg * 64;
        float a = key_mem[base + lane], c = key_mem[base + lane + 32];
        float s = a * a + c * c;
        #pragma unroll
        for (int o = 16; o; o >>= 1) s += __shfl_xor_sync(0xffffffffu, s, o);
        float inv = 1.0f / fmaxf(sqrtf(s), 1e-12f);
        wsplit(kn_h, kn_l, base + lane, a * inv);
        wsplit(kn_h, kn_l, base + lane + 32, c * inv);
        return;
    }
    b -= NB_KN;
    if (b < NB_VN) {  // value_mem row l2norm -> split
        long long r = b;
        float a = value_mem[r * DIM + tid], c = value_mem[r * DIM + tid + 256];
        float s = blockReduceSum(a * a + c * c, sh);
        float inv = 1.0f / fmaxf(sqrtf(s), 1e-12f);
        wsplit(vn_h, vn_l, r * DIM + tid, a * inv);
        wsplit(vn_h, vn_l, r * DIM + tid + 256, c * inv);
        return;
    }
    b -= NB_VN;
    if (b < NB_VT) {  // vmemT[j,s] = value_mem[s,j], pad s>=112 with 0
        int idx = b * 256 + tid;
        int j = idx >> 7, s = idx & 127;
        float v = (s < SLOT) ? value_mem[(long long)s * DIM + j] : 0.0f;
        wsplit(vt_h, vt_l, idx, v);
        return;
    }
    b -= NB_VT;
    {   // contrastive partial, self-normalizing: row i vs all j
        int i = b;
        float* vi = sh;
        float* red = sh + 512;
        for (int c = tid; c < DIM; c += 256) vi[c] = value_mem[(long long)i * DIM + c];
        __syncthreads();
        float s = 0.f;
        for (int c = tid; c < DIM; c += 256) s += vi[c] * vi[c];
        s = blockReduceSum(s, red);
        float ni = fmaxf(sqrtf(s), 1e-12f);
        int w = tid >> 5, lane = tid & 31;
        float acc = 0.f;
        for (int j = w; j < SLOT; j += 8) {
            float d = 0.f, jj = 0.f;
            for (int c = lane; c < DIM; c += 32) {
                float vj = value_mem[(long long)j * DIM + c];
                d += vi[c] * vj; jj += vj * vj;
            }
            #pragma unroll
            for (int o = 16; o; o >>= 1) {
                d += __shfl_down_sync(0xffffffffu, d, o);
                jj += __shfl_down_sync(0xffffffffu, jj, o);
            }
            if (lane == 0) {
                float nj = fmaxf(sqrtf(jj), 1e-12f);
                acc += fabsf(((i == j) ? 1.0f : 0.0f) - d / (ni * nj));
            }
        }
        acc = blockReduceSum(acc, red);
        if (tid == 0) cpart[i] = acc;
    }
}

// ---------------- fused te+tr layernorm kernel ----------------
__global__ void fuse_tetr(const float* __restrict__ virpre, const float* __restrict__ aud,
                          const float* __restrict__ query, const float* __restrict__ value,
                          const float* __restrict__ g1, const float* __restrict__ b1,
                          const float* __restrict__ g2, const float* __restrict__ b2,
                          const float* __restrict__ g3, const float* __restrict__ b3,
                          float* __restrict__ out_te, float* __restrict__ out_tr,
                          float* __restrict__ cosbuf)
{
    __shared__ float red[32];
    bool is_tr = blockIdx.x >= NROWS;
    long long r = is_tr ? (blockIdx.x - NROWS) : blockIdx.x;
    const float* src = (is_tr ? aud : virpre) + r * DIM;
    const float* q = query + r * DIM;
    const float* gx = is_tr ? g3 : g2;
    const float* bx = is_tr ? b3 : b2;
    float* o = (is_tr ? out_tr : out_te) + r * DIM;

    float x[4], qv[4];
    float s = 0.f, s2 = 0.f;
    #pragma unroll
    for (int i = 0; i < 4; i++) {
        int c = threadIdx.x + 128 * i;
        x[i] = src[c]; qv[i] = q[c];
        s += x[i]; s2 += x[i] * x[i];
    }
    s  = blockReduceSum(s,  red);
    s2 = blockReduceSum(s2, red);
    if (is_tr) {  // cos/recon needs aud . value
        const float* v = value + r * DIM;
        float sav = 0.f, svv = 0.f;
        #pragma unroll
        for (int i = 0; i < 4; i++) {
            int c = threadIdx.x + 128 * i;
            float vv = v[c];
            sav += x[i] * vv; svv += vv * vv;
        }
        sav = blockReduceSum(sav, red);
        svv = blockReduceSum(svv, red);
        if (threadIdx.x == 0) {
            float cosv = sav / fmaxf(sqrtf(s2) * sqrtf(svv), 1e-8f);
            cosbuf[r] = fabsf(1.0f - cosv);
        }
    }
    float mu = s * (1.0f / DIM);
    float var = s2 * (1.0f / DIM) - mu * mu;
    float inv = rsqrtf(var + 1e-5f);
    float t[4]; float ts = 0.f, ts2 = 0.f;
    #pragma unroll
    for (int i = 0; i < 4; i++) {
        int c = threadIdx.x + 128 * i;
        float ln = (x[i] - mu) * inv * gx[c] + bx[c];
        t[i] = qv[i] + ln; ts += t[i]; ts2 += t[i] * t[i];
    }
    ts  = blockReduceSum(ts,  red);
    ts2 = blockReduceSum(ts2, red);
    mu = ts * (1.0f / DIM);
    var = ts2 * (1.0f / DIM) - mu * mu;
    inv = rsqrtf(var + 1e-5f);
    #pragma unroll
    for (int i = 0; i < 4; i++) {
        int c = threadIdx.x + 128 * i;
        o[c] = (t[i] - mu) * inv * g1[c] + b1[c];
    }
}

// ---------------- final reductions (recon + contrastive) ----------------
__global__ void final_reduce(const float* __restrict__ cosbuf, const float* __restrict__ cpart,
                             float* __restrict__ recon, float* __restrict__ contr)
{
    __shared__ float red[32];
    int b = blockIdx.x;
    if (b < 32) {
        float s = 0.0f;
        for (int i = threadIdx.x; i < 512; i += blockDim.x) s += cosbuf[b * 512 + i];
        s = blockReduceSum(s, red);
        if (threadIdx.x == 0) recon[b] = s;
    } else {
        float s = 0.0f;
        for (int i = threadIdx.x; i < SLOT; i += blockDim.x) s += cpart[i];
        s = blockReduceSum(s, red);
        if (threadIdx.x == 0) contr[0] = 0.5f * s;
    }
}

// ---------------- launch ----------------
#define SYM(p, s) cudaGetSymbolAddress((void**)&p, s)

extern "C" void kernel_launch(void* const* d_in, const int* in_sizes, int n_in,
                              void* d_out, int out_size)
{
    const float* query     = (const float*)d_in[0];
    const float* value     = (const float*)d_in[1];
    const float* key_mem   = (const float*)d_in[2];
    const float* value_mem = (const float*)d_in[3];
    const float* Wq = (const float*)d_in[4];
    const float* bq = (const float*)d_in[5];
    const float* Wv = (const float*)d_in[6];
    const float* bv = (const float*)d_in[7];
    const float* Wl = (const float*)d_in[8];
    const float* bl = (const float*)d_in[9];
    const float* g1 = (const float*)d_in[10];
    const float* b1 = (const float*)d_in[11];
    const float* g2 = (const float*)d_in[12];
    const float* b2 = (const float*)d_in[13];
    const float* g3 = (const float*)d_in[14];
    const float* b3 = (const float*)d_in[15];

    float* out        = (float*)d_out;
    float* out_te     = out;
    float* out_tr     = out + (long long)NROWS * DIM;
    float* out_recon  = out + 2ll * NROWS * DIM;
    float* out_contr  = out_recon + 32;

    float *p_virpre, *p_aud, *p_invkn, *p_gpart, *p_cos, *p_cpart;
    SYM(p_virpre, g_virpre); SYM(p_aud, g_aud);
    SYM(p_invkn, g_invkn); SYM(p_gpart, g_gpart);
    SYM(p_cos, g_cosbuf); SYM(p_cpart, g_cpart);

    __nv_bfloat16 *q_h, *q_l, *v_h, *v_l, *wq_h, *wq_l, *wv_h, *wv_l, *wl_h, *wl_l;
    __nv_bfloat16 *vm_h, *vm_l, *eqn_h, *eqn_l, *kn_h, *kn_l, *ka_h, *ka_l, *m2_h, *m2_l;
    __nv_bfloat16 *ev_h, *ev_l, *vn_h, *vn_l, *va_h, *va_l, *vt_h, *vt_l;
    SYM(q_h, g_q_h); SYM(q_l, g_q_l); SYM(v_h, g_v_h); SYM(v_l, g_v_l);
    SYM(wq_h, g_wq_h); SYM(wq_l, g_wq_l); SYM(wv_h, g_wv_h); SYM(wv_l, g_wv_l);
    SYM(wl_h, g_wl_h); SYM(wl_l, g_wl_l); SYM(vm_h, g_vm_h); SYM(vm_l, g_vm_l);
    SYM(eqn_h, g_eqn_h); SYM(eqn_l, g_eqn_l); SYM(kn_h, g_kn_h); SYM(kn_l, g_kn_l);
    SYM(ka_h, g_ka_h); SYM(ka_l, g_ka_l); SYM(m2_h, g_m2_h); SYM(m2_l, g_m2_l);
    SYM(ev_h, g_ev_h); SYM(ev_l, g_ev_l); SYM(vn_h, g_vn_h); SYM(vn_l, g_vn_l);
    SYM(va_h, g_va_h); SYM(va_l, g_va_l); SYM(vt_h, g_vt_h); SYM(vt_l, g_vt_l);

    cudaFuncSetAttribute(gemm_nt<6, false, true >, cudaFuncAttributeMaxDynamicSharedMemorySize, GSMEM);
    cudaFuncSetAttribute(gemm_nt<1, true,  false>, cudaFuncAttributeMaxDynamicSharedMemorySize, GSMEM);
    cudaFuncSetAttribute(gemm_nt<3, true,  false>, cudaFuncAttributeMaxDynamicSharedMemorySize, GSMEM);
    cudaFuncSetAttribute(gemm_nt<5, true,  false>, cudaFuncAttributeMaxDynamicSharedMemorySize, GSMEM);
    cudaFuncSetAttribute(gemm_nt<0, false, true >, cudaFuncAttributeMaxDynamicSharedMemorySize, GSMEM);
    cudaFuncSetAttribute(gemm_nt<0, false, false>, cudaFuncAttributeMaxDynamicSharedMemorySize, GSMEM);

    // 0: all prep (splits, norms, contrastive partials)
    mega_prep<<<NB_TOTAL, 256>>>(query, value, key_mem, value_mem, Wq, Wv, Wl,
                                 q_h, q_l, v_h, v_l, wq_h, wq_l, wv_h, wv_l,
                                 wl_h, wl_l, vm_h, vm_l, kn_h, kn_l, vn_h, vn_l,
                                 vt_h, vt_l, p_cpart);

    // 1: M2T[j, h*112+s] = sum_d Wl[j, h*512+d] * value_mem[s, d]
    gemm_nt<1, true, false><<<dim3(1, 4, HEAD), 256, GSMEM>>>(
        wl_h, wl_l, HEAD * DIM, 512, vm_h, vm_l, DIM, 0,
        nullptr, m2_h, m2_l, HEAD * SLOT, 112, nullptr, nullptr, nullptr, SLOT, DIM,
        nullptr, nullptr, nullptr, nullptr, nullptr, nullptr, nullptr, nullptr);

    // 2: batched eq/ev GEMM.  z=0: eq=q@Wq^T+bq -> split + invkn.  z=1: ev=v@Wv^T+bv -> split + gpart
    gemm_nt<6, false, true><<<dim3(4, 128, 2), 256, GSMEM>>>(
        q_h, q_l, DIM, 0, wq_h, wq_l, DIM, 0,
        nullptr, eqn_h, eqn_l, DIM, 0, bq, nullptr, p_invkn, DIM, DIM,
        v_h, v_l, wv_h, wv_l, ev_h, ev_l, bv, p_gpart);

    // 3: key_sim + fused softmax -> ka split
    gemm_nt<3, true, false><<<dim3(1, 128, HEAD), 256, GSMEM>>>(
        eqn_h, eqn_l, DIM, HD, kn_h, kn_l, HD, (long long)SLOT * HD,
        nullptr, ka_h, ka_l, HEAD * SLOT, SLOT, nullptr, p_invkn, nullptr, SLOT, HD,
        nullptr, nullptr, nullptr, nullptr, nullptr, nullptr, nullptr, nullptr);

    // 4: value_sim + fused softmax (invn computed inline from gpart) -> va split
    gemm_nt<5, true, false><<<dim3(1, 128, 1), 256, GSMEM>>>(
        ev_h, ev_l, DIM, 0, vn_h, vn_l, DIM, 0,
        nullptr, va_h, va_l, 128, 0, nullptr, p_gpart, nullptr, SLOT, DIM,
        nullptr, nullptr, nullptr, nullptr, nullptr, nullptr, nullptr, nullptr);

    // 5: virpre = ka @ M2 + bl   (ncu -s 5 target: big K=896 GEMM)
    gemm_nt<0, false, true><<<dim3(4, 128, 1), 256, GSMEM>>>(
        ka_h, ka_l, HEAD * SLOT, 0, m2_h, m2_l, HEAD * SLOT, 0,
        p_virpre, nullptr, nullptr, DIM, 0, bl, nullptr, nullptr, DIM, HEAD * SLOT,
        nullptr, nullptr, nullptr, nullptr, nullptr, nullptr, nullptr, nullptr);

    // 6: aud = va @ vmemT^T
    gemm_nt<0, false, false><<<dim3(4, 128, 1), 256, GSMEM>>>(
        va_h, va_l, 128, 0, vt_h, vt_l, 128, 0,
        p_aud, nullptr, nullptr, DIM, 0, nullptr, nullptr, nullptr, DIM, 128,
        nullptr, nullptr, nullptr, nullptr, nullptr, nullptr, nullptr, nullptr);

    // 7: fused te + tr double-layernorm (+cos)
    fuse_tetr<<<2 * NROWS, 128>>>(p_virpre, p_aud, query, value,
                                  g1, b1, g2, b2, g3, b3, out_te, out_tr, p_cos);

    // 8: recon per-batch sums + contrastive final
    final_reduce<<<33, 128>>>(p_cos, p_cpart, out_recon, out_contr);
}

// round 6
// speedup vs baseline: 2.8350x; 1.1251x over previous
#include <cuda_runtime.h>
#include <cuda_bf16.h>
#include <cstdint>

#define NROWS 16384   // B*S
#define DIM 512
#define HEAD 8
#define SLOT 112
#define HD 64
#define RADIUSF 16.0f

// ---------------- scratch (device globals) ----------------
__device__ float g_virpre[NROWS * DIM];
__device__ float g_aud[NROWS * DIM];
__device__ float g_invkn[NROWS * HEAD];
__device__ float g_gpart[NROWS * 4];
__device__ float g_cosbuf[NROWS];
__device__ float g_cpart[SLOT];
// bf16 split pairs
__device__ __nv_bfloat16 g_q_h[NROWS * DIM],  g_q_l[NROWS * DIM];
__device__ __nv_bfloat16 g_v_h[NROWS * DIM],  g_v_l[NROWS * DIM];
__device__ __nv_bfloat16 g_wq_h[DIM * DIM],   g_wq_l[DIM * DIM];
__device__ __nv_bfloat16 g_wv_h[DIM * DIM],   g_wv_l[DIM * DIM];
__device__ __nv_bfloat16 g_wl_h[DIM * DIM * HEAD], g_wl_l[DIM * DIM * HEAD];
__device__ __nv_bfloat16 g_vm_h[SLOT * DIM],  g_vm_l[SLOT * DIM];
__device__ __nv_bfloat16 g_eqn_h[NROWS * DIM], g_eqn_l[NROWS * DIM];
__device__ __nv_bfloat16 g_kn_h[HEAD * SLOT * HD], g_kn_l[HEAD * SLOT * HD];
__device__ __nv_bfloat16 g_ka_h[NROWS * HEAD * SLOT], g_ka_l[NROWS * HEAD * SLOT];
__device__ __nv_bfloat16 g_m2_h[DIM * HEAD * SLOT],   g_m2_l[DIM * HEAD * SLOT];
__device__ __nv_bfloat16 g_ev_h[NROWS * DIM], g_ev_l[NROWS * DIM];
__device__ __nv_bfloat16 g_vn_h[SLOT * DIM],  g_vn_l[SLOT * DIM];
__device__ __nv_bfloat16 g_va_h[NROWS * 128], g_va_l[NROWS * 128];
__device__ __nv_bfloat16 g_vt_h[DIM * 128],   g_vt_l[DIM * 128];

// ---------------- helpers ----------------
__device__ __forceinline__ uint32_t smem_u32(const void* p) {
    uint32_t a;
    asm("{ .reg .u64 t; cvta.to.shared.u64 t, %1; cvt.u32.u64 %0, t; }" : "=r"(a) : "l"(p));
    return a;
}
__device__ __forceinline__ void cp16(uint32_t dst, const void* src, int sz) {
    asm volatile("cp.async.cg.shared.global [%0], [%1], 16, %2;"
                 :: "r"(dst), "l"(src), "r"(sz));
}
__device__ __forceinline__ void cp_commit() { asm volatile("cp.async.commit_group;" ::: "memory"); }
__device__ __forceinline__ void cp_wait2()  { asm volatile("cp.async.wait_group 2;"  ::: "memory"); }

__device__ __forceinline__ void ldm4(uint32_t (&r)[4], uint32_t a) {
    asm volatile("ldmatrix.sync.aligned.m8n8.x4.shared.b16 {%0,%1,%2,%3}, [%4];"
                 : "=r"(r[0]), "=r"(r[1]), "=r"(r[2]), "=r"(r[3]) : "r"(a));
}
__device__ __forceinline__ void mma16816(float (&c)[4], const uint32_t (&a)[4],
                                         uint32_t b0, uint32_t b1) {
    asm volatile(
        "mma.sync.aligned.m16n8k16.row.col.f32.bf16.bf16.f32 "
        "{%0,%1,%2,%3}, {%4,%5,%6,%7}, {%8,%9}, {%0,%1,%2,%3};"
        : "+f"(c[0]), "+f"(c[1]), "+f"(c[2]), "+f"(c[3])
        : "r"(a[0]), "r"(a[1]), "r"(a[2]), "r"(a[3]), "r"(b0), "r"(b1));
}
__device__ __forceinline__ void wsplit(__nv_bfloat16* h, __nv_bfloat16* l, long long i, float v) {
    __nv_bfloat16 hh = __float2bfloat16_rn(v);
    h[i] = hh;
    l[i] = __float2bfloat16_rn(v - __bfloat162float(hh));
}
__device__ __forceinline__ void spair(__nv_bfloat16* H, __nv_bfloat16* L, long long i,
                                      float a, float b) {
    __nv_bfloat16 h0 = __float2bfloat16_rn(a), h1 = __float2bfloat16_rn(b);
    *(__nv_bfloat162*)(H + i) = __halves2bfloat162(h0, h1);
    *(__nv_bfloat162*)(L + i) = __halves2bfloat162(
        __float2bfloat16_rn(a - __bfloat162float(h0)),
        __float2bfloat16_rn(b - __bfloat162float(h1)));
}
__device__ __forceinline__ float qred_sum(float v) {
    v += __shfl_xor_sync(0xffffffffu, v, 1);
    v += __shfl_xor_sync(0xffffffffu, v, 2);
    return v;
}
__device__ __forceinline__ float qred_max(float v) {
    v = fmaxf(v, __shfl_xor_sync(0xffffffffu, v, 1));
    v = fmaxf(v, __shfl_xor_sync(0xffffffffu, v, 2));
    return v;
}
__device__ __forceinline__ float blockReduceSum(float v, float* red) {
    int lane = threadIdx.x & 31, w = threadIdx.x >> 5;
    #pragma unroll
    for (int o = 16; o; o >>= 1) v += __shfl_down_sync(0xffffffffu, v, o);
    if (lane == 0) red[w] = v;
    __syncthreads();
    int nw = blockDim.x >> 5;
    float r = (threadIdx.x < nw) ? red[threadIdx.x] : 0.0f;
    if (w == 0) {
        #pragma unroll
        for (int o = 16; o; o >>= 1) r += __shfl_down_sync(0xffffffffu, r, o);
        if (lane == 0) red[0] = r;
    }
    __syncthreads();
    float out = red[0];
    __syncthreads();
    return out;
}

// ---------------- GEMM core (128x128 tile, bf16 3-split, single-sync mainloop) ----------------
#define ROWB   80
#define HALFB  10240
#define STAGEB 40960
#define NST    4
#define GSMEM  (NST * STAGEB)

__device__ __forceinline__ void gemm_core(
    uint32_t sb, int tid,
    const __nv_bfloat16* __restrict__ Ah, const __nv_bfloat16* __restrict__ Al, int lda,
    const __nv_bfloat16* __restrict__ Bh, const __nv_bfloat16* __restrict__ Bl, int ldb,
    int K, int nvalid, float (&acc)[4][4][4])
{
    const int lane = tid & 31, wid = tid >> 5;
    const int wr = wid >> 2, wc = wid & 3;
    const int nc = K >> 5;

    auto issue = [&](int st, int c) {
        #pragma unroll
        for (int j = 0; j < 2; j++) {
            int id = tid + j * 256;
            int row = id >> 2, ch = id & 3;
            long long offa = (long long)row * lda + c * 32 + ch * 8;
            uint32_t d = sb + st * STAGEB + row * ROWB + ch * 16;
            cp16(d,         Ah + offa, 16);
            cp16(d + HALFB, Al + offa, 16);
            long long offb = (long long)row * ldb + c * 32 + ch * 8;
            int vb = (row < nvalid) ? 16 : 0;
            if (vb == 0) offb = 0;
            cp16(d + 2 * HALFB, Bh + offb, vb);
            cp16(d + 3 * HALFB, Bl + offb, vb);
        }
    };

    #pragma unroll
    for (int i = 0; i < 4; i++)
        #pragma unroll
        for (int j = 0; j < 4; j++)
            #pragma unroll
            for (int t = 0; t < 4; t++) acc[i][j][t] = 0.0f;

    #pragma unroll
    for (int p = 0; p < NST - 1; p++) {
        if (p < nc) issue(p, p);
        cp_commit();
    }

    const int rA = lane & 15, cA = lane >> 4;
    const int rB = (lane & 7) + ((lane >> 4) << 3), cB = (lane >> 3) & 1;

    for (int c = 0; c < nc; c++) {
        cp_wait2();
        __syncthreads();
        int nxt = c + NST - 1;
        if (nxt < nc) issue(nxt & (NST - 1), nxt);   // prefetch before MMA; writes stage != current
        cp_commit();
        const uint32_t base = sb + (c & (NST - 1)) * STAGEB;
        #pragma unroll
        for (int k16 = 0; k16 < 2; k16++) {
            const int k2 = k16 * 2;
            uint32_t fAh[4][4], fAl[4][4], fBh[2][4], fBl[2][4];
            #pragma unroll
            for (int mi = 0; mi < 4; mi++) {
                uint32_t a = base + (uint32_t)((wr * 64 + mi * 16 + rA) * ROWB + (k2 + cA) * 16);
                ldm4(fAh[mi], a);
                ldm4(fAl[mi], a + HALFB);
            }
            #pragma unroll
            for (int ni = 0; ni < 2; ni++) {
                uint32_t b = base + 2 * HALFB +
                             (uint32_t)((wc * 32 + ni * 16 + rB) * ROWB + (k2 + cB) * 16);
                ldm4(fBh[ni], b);
                ldm4(fBl[ni], b + HALFB);
            }
            #pragma unroll
            for (int mi = 0; mi < 4; mi++)
                #pragma unroll
                for (int nj = 0; nj < 4; nj++) {
                    const int bi = nj >> 1, bs = (nj & 1) * 2;
                    mma16816(acc[mi][nj], fAh[mi], fBh[bi][bs], fBh[bi][bs + 1]);
                    mma16816(acc[mi][nj], fAh[mi], fBl[bi][bs], fBl[bi][bs + 1]);
                    mma16816(acc[mi][nj], fAl[mi], fBh[bi][bs], fBh[bi][bs + 1]);
                }
        }
    }
    __syncthreads();   // protect smem reuse by epilogue
}

__device__ __forceinline__ void epi_bias(float (&acc)[4][4][4], const float* bias,
                                         int blockCol, int wc, int lane) {
    #pragma unroll
    for (int nj = 0; nj < 4; nj++) {
        const int col = blockCol + wc * 32 + nj * 8 + (lane & 3) * 2;
        float b0 = bias[col], b1 = bias[col + 1];
        #pragma unroll
        for (int mi = 0; mi < 4; mi++) {
            acc[mi][nj][0] += b0; acc[mi][nj][1] += b1;
            acc[mi][nj][2] += b0; acc[mi][nj][3] += b1;
        }
    }
}

// split store, optional col guard
__device__ __forceinline__ void epi_split_store(
    float (&acc)[4][4][4], __nv_bfloat16* Ch, __nv_bfloat16* Cl, int ldc,
    int blockRow, int blockCol, int ncols, int wr, int wc, int lane)
{
    #pragma unroll
    for (int mi = 0; mi < 4; mi++) {
        long long R0 = (long long)(blockRow + wr * 64 + mi * 16 + (lane >> 2)) * ldc;
        long long R1 = R0 + 8LL * ldc;
        #pragma unroll
        for (int nj = 0; nj < 4; nj++) {
            int col = blockCol + wc * 32 + nj * 8 + (lane & 3) * 2;
            if (col >= ncols) continue;
            spair(Ch, Cl, R0 + col, acc[mi][nj][0], acc[mi][nj][1]);
            spair(Ch, Cl, R1 + col, acc[mi][nj][2], acc[mi][nj][3]);
        }
    }
}

__device__ __forceinline__ void epi_f32_store(
    float (&acc)[4][4][4], float* Cf, int ldc,
    int blockRow, int blockCol, int wr, int wc, int lane)
{
    #pragma unroll
    for (int mi = 0; mi < 4; mi++) {
        long long R0 = (long long)(blockRow + wr * 64 + mi * 16 + (lane >> 2)) * ldc;
        long long R1 = R0 + 8LL * ldc;
        #pragma unroll
        for (int nj = 0; nj < 4; nj++) {
            int col = blockCol + wc * 32 + nj * 8 + (lane & 3) * 2;
            *(float2*)(Cf + R0 + col) = make_float2(acc[mi][nj][0], acc[mi][nj][1]);
            *(float2*)(Cf + R1 + col) = make_float2(acc[mi][nj][2], acc[mi][nj][3]);
        }
    }
}

// ---------------- stage 1: eq (z=0), ev (z=1), m2t (z=2) ----------------
__global__ void __launch_bounds__(256, 1) gemm_stage1(
    const __nv_bfloat16* __restrict__ q_h, const __nv_bfloat16* __restrict__ q_l,
    const __nv_bfloat16* __restrict__ wq_h, const __nv_bfloat16* __restrict__ wq_l,
    const __nv_bfloat16* __restrict__ v_h, const __nv_bfloat16* __restrict__ v_l,
    const __nv_bfloat16* __restrict__ wv_h, const __nv_bfloat16* __restrict__ wv_l,
    const __nv_bfloat16* __restrict__ wl_h, const __nv_bfloat16* __restrict__ wl_l,
    const __nv_bfloat16* __restrict__ vm_h, const __nv_bfloat16* __restrict__ vm_l,
    __nv_bfloat16* eqn_h, __nv_bfloat16* eqn_l,
    __nv_bfloat16* ev_h, __nv_bfloat16* ev_l,
    __nv_bfloat16* m2_h, __nv_bfloat16* m2_l,
    const float* __restrict__ bq, const float* __restrict__ bv,
    float* __restrict__ invkn, float* __restrict__ gpart)
{
    extern __shared__ char smem[];
    const uint32_t sb = smem_u32(smem);
    const int tid = threadIdx.x, lane = tid & 31, wid = tid >> 5;
    const int wr = wid >> 2, wc = wid & 3;
    const int z = blockIdx.z;
    float acc[4][4][4];

    if (z == 2) {
        if (blockIdx.x != 0 || blockIdx.y >= 32) return;
        int h = blockIdx.y & 7, mb = blockIdx.y >> 3;
        gemm_core(sb, tid, wl_h + h * 512 + (long long)mb * 128 * (HEAD * DIM),
                  wl_l + h * 512 + (long long)mb * 128 * (HEAD * DIM), HEAD * DIM,
                  vm_h, vm_l, DIM, DIM, SLOT, acc);
        epi_split_store(acc, m2_h + h * SLOT, m2_l + h * SLOT, HEAD * SLOT,
                        mb * 128, 0, SLOT, wr, wc, lane);
        return;
    }

    const int blockRow = blockIdx.y * 128, blockCol = blockIdx.x * 128;
    if (z == 0)
        gemm_core(sb, tid, q_h + (long long)blockRow * DIM, q_l + (long long)blockRow * DIM, DIM,
                  wq_h + (long long)blockCol * DIM, wq_l + (long long)blockCol * DIM, DIM,
                  DIM, 128, acc);
    else
        gemm_core(sb, tid, v_h + (long long)blockRow * DIM, v_l + (long long)blockRow * DIM, DIM,
                  wv_h + (long long)blockCol * DIM, wv_l + (long long)blockCol * DIM, DIM,
                  DIM, 128, acc);

    epi_bias(acc, z == 0 ? bq : bv, blockCol, wc, lane);

    float* sred = (float*)smem;
    #pragma unroll
    for (int mi = 0; mi < 4; mi++) {
        float s0 = 0.f, s1 = 0.f;
        #pragma unroll
        for (int nj = 0; nj < 4; nj++) {
            s0 += acc[mi][nj][0] * acc[mi][nj][0] + acc[mi][nj][1] * acc[mi][nj][1];
            s1 += acc[mi][nj][2] * acc[mi][nj][2] + acc[mi][nj][3] * acc[mi][nj][3];
        }
        s0 = qred_sum(s0); s1 = qred_sum(s1);
        if ((lane & 3) == 0) {
            int r0 = wr * 64 + mi * 16 + (lane >> 2);
            sred[r0 * 4 + wc] = s0;
            sred[(r0 + 8) * 4 + wc] = s1;
        }
    }
    __syncthreads();
    if (z == 0) {
        if ((wc == 0 || wc == 2) && (lane & 3) == 0) {
            #pragma unroll
            for (int mi = 0; mi < 4; mi++)
                #pragma unroll
                for (int half = 0; half < 2; half++) {
                    int r = wr * 64 + mi * 16 + (lane >> 2) + half * 8;
                    float s = sred[r * 4 + wc] + sred[r * 4 + wc + 1];
                    invkn[(long long)(blockRow + r) * HEAD + blockIdx.x * 2 + (wc >> 1)]
                        = 1.0f / fmaxf(sqrtf(s), 1e-12f);
                }
        }
    } else {
        if (wc == 0 && (lane & 3) == 0) {
            #pragma unroll
            for (int mi = 0; mi < 4; mi++)
                #pragma unroll
                for (int half = 0; half < 2; half++) {
                    int r = wr * 64 + mi * 16 + (lane >> 2) + half * 8;
                    float s = sred[r * 4] + sred[r * 4 + 1] + sred[r * 4 + 2] + sred[r * 4 + 3];
                    gpart[(long long)(blockRow + r) * 4 + blockIdx.x] = s;
                }
        }
    }
    epi_split_store(acc, z == 0 ? eqn_h : ev_h, z == 0 ? eqn_l : ev_l, DIM,
                    blockRow, blockCol, 1 << 30, wr, wc, lane);
}

// ---------------- stage 2: vsim (z=0, longest first) + ksim heads (z=1..8) ----------------
__global__ void __launch_bounds__(256, 1) gemm_sim(
    const __nv_bfloat16* __restrict__ eqn_h, const __nv_bfloat16* __restrict__ eqn_l,
    const __nv_bfloat16* __restrict__ kn_h, const __nv_bfloat16* __restrict__ kn_l,
    const __nv_bfloat16* __restrict__ ev_h, const __nv_bfloat16* __restrict__ ev_l,
    const __nv_bfloat16* __restrict__ vn_h, const __nv_bfloat16* __restrict__ vn_l,
    __nv_bfloat16* ka_h, __nv_bfloat16* ka_l,
    __nv_bfloat16* va_h, __nv_bfloat16* va_l,
    const float* __restrict__ invkn, const float* __restrict__ gpart)
{
    extern __shared__ char smem[];
    const uint32_t sb = smem_u32(smem);
    const int tid = threadIdx.x, lane = tid & 31, wid = tid >> 5;
    const int wr = wid >> 2, wc = wid & 3;
    const int z = blockIdx.z;
    const int blockRow = blockIdx.y * 128;
    float acc[4][4][4];

    __nv_bfloat16 *Ch, *Cl;
    int ldc;
    bool is_val = (z == 0);
    if (is_val) {
        gemm_core(sb, tid, ev_h + (long long)blockRow * DIM, ev_l + (long long)blockRow * DIM, DIM,
                  vn_h, vn_l, DIM, DIM, SLOT, acc);
        Ch = va_h; Cl = va_l; ldc = 128;
    } else {
        int h = z - 1;
        gemm_core(sb, tid, eqn_h + (long long)blockRow * DIM + h * HD,
                  eqn_l + (long long)blockRow * DIM + h * HD, DIM,
                  kn_h + (long long)h * SLOT * HD, kn_l + (long long)h * SLOT * HD, HD,
                  HD, SLOT, acc);
        Ch = ka_h + h * SLOT; Cl = ka_l + h * SLOT; ldc = HEAD * SLOT;
    }

    float* sred = (float*)smem;
    float* ssum = sred + 512;
    const int h = z - 1;

    float scl[4][2];
    #pragma unroll
    for (int mi = 0; mi < 4; mi++)
        #pragma unroll
        for (int half = 0; half < 2; half++) {
            int r = blockRow + wr * 64 + mi * 16 + (lane >> 2) + half * 8;
            float iv;
            if (is_val) {
                float s4 = gpart[r * 4] + gpart[r * 4 + 1] + gpart[r * 4 + 2] + gpart[r * 4 + 3];
                iv = 1.0f / fmaxf(sqrtf(s4), 1e-12f);
            } else {
                iv = invkn[(long long)r * HEAD + h];
            }
            scl[mi][half] = RADIUSF * iv;
        }
    #pragma unroll
    for (int mi = 0; mi < 4; mi++) {
        float m0 = -1e30f, m1 = -1e30f;
        #pragma unroll
        for (int nj = 0; nj < 4; nj++) {
            const int col = wc * 32 + nj * 8 + (lane & 3) * 2;
            bool ok = col < SLOT;
            float l0 = ok ? scl[mi][0] * acc[mi][nj][0] : -1e30f;
            float l1 = ok ? scl[mi][0] * acc[mi][nj][1] : -1e30f;
            float l2 = ok ? scl[mi][1] * acc[mi][nj][2] : -1e30f;
            float l3 = ok ? scl[mi][1] * acc[mi][nj][3] : -1e30f;
            acc[mi][nj][0] = l0; acc[mi][nj][1] = l1;
            acc[mi][nj][2] = l2; acc[mi][nj][3] = l3;
            m0 = fmaxf(m0, fmaxf(l0, l1)); m1 = fmaxf(m1, fmaxf(l2, l3));
        }
        m0 = qred_max(m0); m1 = qred_max(m1);
        if ((lane & 3) == 0) {
            int r0 = wr * 64 + mi * 16 + (lane >> 2);
            sred[r0 * 4 + wc] = m0;
            sred[(r0 + 8) * 4 + wc] = m1;
        }
    }
    __syncthreads();
    #pragma unroll
    for (int mi = 0; mi < 4; mi++) {
        int r0 = wr * 64 + mi * 16 + (lane >> 2), r1 = r0 + 8;
        float M0 = fmaxf(fmaxf(sred[r0 * 4], sred[r0 * 4 + 1]),
                         fmaxf(sred[r0 * 4 + 2], sred[r0 * 4 + 3]));
        float M1 = fmaxf(fmaxf(sred[r1 * 4], sred[r1 * 4 + 1]),
                         fmaxf(sred[r1 * 4 + 2], sred[r1 * 4 + 3]));
        float s0 = 0.f, s1 = 0.f;
        #pragma unroll
        for (int nj = 0; nj < 4; nj++) {
            const int col = wc * 32 + nj * 8 + (lane & 3) * 2;
            bool ok = col < SLOT;
            float e0 = ok ? __expf(acc[mi][nj][0] - M0) : 0.f;
            float e1 = ok ? __expf(acc[mi][nj][1] - M0) : 0.f;
            float e2 = ok ? __expf(acc[mi][nj][2] - M1) : 0.f;
            float e3 = ok ? __expf(acc[mi][nj][3] - M1) : 0.f;
            acc[mi][nj][0] = e0; acc[mi][nj][1] = e1;
            acc[mi][nj][2] = e2; acc[mi][nj][3] = e3;
            s0 += e0 + e1; s1 += e2 + e3;
        }
        s0 = qred_sum(s0); s1 = qred_sum(s1);
        if ((lane & 3) == 0) {
            ssum[r0 * 4 + wc] = s0;
            ssum[r1 * 4 + wc] = s1;
        }
    }
    __syncthreads();
    #pragma unroll
    for (int mi = 0; mi < 4; mi++) {
        int r0l = wr * 64 + mi * 16 + (lane >> 2), r1l = r0l + 8;
        float i0 = 1.0f / (ssum[r0l * 4] + ssum[r0l * 4 + 1] + ssum[r0l * 4 + 2] + ssum[r0l * 4 + 3]);
        float i1 = 1.0f / (ssum[r1l * 4] + ssum[r1l * 4 + 1] + ssum[r1l * 4 + 2] + ssum[r1l * 4 + 3]);
        long long R0 = (long long)(blockRow + r0l) * ldc;
        long long R1 = (long long)(blockRow + r1l) * ldc;
        #pragma unroll
        for (int nj = 0; nj < 4; nj++) {
            const int col = wc * 32 + nj * 8 + (lane & 3) * 2;
            if (!is_val && col >= SLOT) continue;   // vsim writes zero pads
            spair(Ch, Cl, R0 + col, acc[mi][nj][0] * i0, acc[mi][nj][1] * i0);
            spair(Ch, Cl, R1 + col, acc[mi][nj][2] * i1, acc[mi][nj][3] * i1);
        }
    }
}

// ---------------- stage 3: virpre (z=0, K=896) + aud (z=1, K=128) ----------------
__global__ void __launch_bounds__(256, 1) gemm_out(
    const __nv_bfloat16* __restrict__ ka_h, const __nv_bfloat16* __restrict__ ka_l,
    const __nv_bfloat16* __restrict__ m2_h, const __nv_bfloat16* __restrict__ m2_l,
    const __nv_bfloat16* __restrict__ va_h, const __nv_bfloat16* __restrict__ va_l,
    const __nv_bfloat16* __restrict__ vt_h, const __nv_bfloat16* __restrict__ vt_l,
    float* __restrict__ virpre, float* __restrict__ aud,
    const float* __restrict__ bl)
{
    extern __shared__ char smem[];
    const uint32_t sb = smem_u32(smem);
    const int tid = threadIdx.x, lane = tid & 31, wid = tid >> 5;
    const int wr = wid >> 2, wc = wid & 3;
    const int z = blockIdx.z;
    const int blockRow = blockIdx.y * 128, blockCol = blockIdx.x * 128;
    float acc[4][4][4];

    if (z == 0) {
        gemm_core(sb, tid, ka_h + (long long)blockRow * (HEAD * SLOT),
                  ka_l + (long long)blockRow * (HEAD * SLOT), HEAD * SLOT,
                  m2_h + (long long)blockCol * (HEAD * SLOT),
                  m2_l + (long long)blockCol * (HEAD * SLOT), HEAD * SLOT,
                  HEAD * SLOT, 128, acc);
        epi_bias(acc, bl, blockCol, wc, lane);
        epi_f32_store(acc, virpre, DIM, blockRow, blockCol, wr, wc, lane);
    } else {
        gemm_core(sb, tid, va_h + (long long)blockRow * 128, va_l + (long long)blockRow * 128, 128,
                  vt_h + (long long)blockCol * 128, vt_l + (long long)blockCol * 128, 128,
                  128, 128, acc);
        epi_f32_store(acc, aud, DIM, blockRow, blockCol, wr, wc, lane);
    }
}

// ---------------- mega prep ----------------
#define NB_Q  8192
#define NB_V  8192
#define NB_WQ 256
#define NB_WV 256
#define NB_WL 2048
#define NB_VM 56
#define NB_KN 112
#define NB_VN 112
#define NB_VT 256
#define NB_CP 112
#define NB_TOTAL (NB_Q+NB_V+NB_WQ+NB_WV+NB_WL+NB_VM+NB_KN+NB_VN+NB_VT+NB_CP)

__device__ __forceinline__ void do_split4(const float4* src, __nv_bfloat16* h,
                                          __nv_bfloat16* l, long long i) {
    float4 v = src[i];
    __nv_bfloat16 h0 = __float2bfloat16_rn(v.x), h1 = __float2bfloat16_rn(v.y);
    __nv_bfloat16 h2 = __float2bfloat16_rn(v.z), h3 = __float2bfloat16_rn(v.w);
    *(__nv_bfloat162*)(h + i * 4)     = __halves2bfloat162(h0, h1);
    *(__nv_bfloat162*)(h + i * 4 + 2) = __halves2bfloat162(h2, h3);
    *(__nv_bfloat162*)(l + i * 4) = __halves2bfloat162(
        __float2bfloat16_rn(v.x - __bfloat162float(h0)),
        __float2bfloat16_rn(v.y - __bfloat162float(h1)));
    *(__nv_bfloat162*)(l + i * 4 + 2) = __halves2bfloat162(
        __float2bfloat16_rn(v.z - __bfloat162float(h2)),
        __float2bfloat16_rn(v.w - __bfloat162float(h3)));
}

__global__ void mega_prep(
    const float* __restrict__ query, const float* __restrict__ value,
    const float* __restrict__ key_mem, const float* __restrict__ value_mem,
    const float* __restrict__ Wq, const float* __restrict__ Wv, const float* __restrict__ Wl,
    __nv_bfloat16* q_h, __nv_bfloat16* q_l, __nv_bfloat16* v_h, __nv_bfloat16* v_l,
    __nv_bfloat16* wq_h, __nv_bfloat16* wq_l, __nv_bfloat16* wv_h, __nv_bfloat16* wv_l,
    __nv_bfloat16* wl_h, __nv_bfloat16* wl_l, __nv_bfloat16* vm_h, __nv_bfloat16* vm_l,
    __nv_bfloat16* kn_h, __nv_bfloat16* kn_l, __nv_bfloat16* vn_h, __nv_bfloat16* vn_l,
    __nv_bfloat16* vt_h, __nv_bfloat16* vt_l, float* cpart)
{
    __shared__ float sh[544];
    int b = blockIdx.x, tid = threadIdx.x;

    if (b < NB_Q) { do_split4((const float4*)query, q_h, q_l, (long long)b * 256 + tid); return; }
    b -= NB_Q;
    if (b < NB_V) { do_split4((const float4*)value, v_h, v_l, (long long)b * 256 + tid); return; }
    b -= NB_V;
    if (b < NB_WQ) { do_split4((const float4*)Wq, wq_h, wq_l, (long long)b * 256 + tid); return; }
    b -= NB_WQ;
    if (b < NB_WV) { do_split4((const float4*)Wv, wv_h, wv_l, (long long)b * 256 + tid); return; }
    b -= NB_WV;
    if (b < NB_WL) { do_split4((const float4*)Wl, wl_h, wl_l, (long long)b * 256 + tid); return; }
    b -= NB_WL;
    if (b < NB_VM) { do_split4((const float4*)value_mem, vm_h, vm_l, (long long)b * 256 + tid); return; }
    b -= NB_VM;
    if (b < NB_KN) {
        int seg = b * 8 + (tid >> 5), lane = tid & 31;
        long long base = (long long)seg * 64;
        float a = key_mem[base + lane], c = key_mem[base + lane + 32];
        float s = a * a + c * c;
        #pragma unroll
        for (int o = 16; o; o >>= 1) s += __shfl_xor_sync(0xffffffffu, s, o);
        float inv = 1.0f / fmaxf(sqrtf(s), 1e-12f);
        wsplit(kn_h, kn_l, base + lane, a * inv);
        wsplit(kn_h, kn_l, base + lane + 32, c * inv);
        return;
    }
    b -= NB_KN;
    if (b < NB_VN) {
        long long r = b;
        float a = value_mem[r * DIM + tid], c = value_mem[r * DIM + tid + 256];
        float s = blockReduceSum(a * a + c * c, sh);
        float inv = 1.0f / fmaxf(sqrtf(s), 1e-12f);
        wsplit(vn_h, vn_l, r * DIM + tid, a * inv);
        wsplit(vn_h, vn_l, r * DIM + tid + 256, c * inv);
        return;
    }
    b -= NB_VN;
    if (b < NB_VT) {
        int idx = b * 256 + tid;
        int j = idx >> 7, s = idx & 127;
        float v = (s < SLOT) ? value_mem[(long long)s * DIM + j] : 0.0f;
        wsplit(vt_h, vt_l, idx, v);
        return;
    }
    b -= NB_VT;
    {
        int i = b;
        float* vi = sh;
        float* red = sh + 512;
        for (int c = tid; c < DIM; c += 256) vi[c] = value_mem[(long long)i * DIM + c];
        __syncthreads();
        float s = 0.f;
        for (int c = tid; c < DIM; c += 256) s += vi[c] * vi[c];
        s = blockReduceSum(s, red);
        float ni = fmaxf(sqrtf(s), 1e-12f);
        int w = tid >> 5, lane = tid & 31;
        float acc = 0.f;
        for (int j = w; j < SLOT; j += 8) {
            float d = 0.f, jj = 0.f;
            for (int c = lane; c < DIM; c += 32) {
                float vj = value_mem[(long long)j * DIM + c];
                d += vi[c] * vj; jj += vj * vj;
            }
            #pragma unroll
            for (int o = 16; o; o >>= 1) {
                d += __shfl_down_sync(0xffffffffu, d, o);
                jj += __shfl_down_sync(0xffffffffu, jj, o);
            }
            if (lane == 0) {
                float nj = fmaxf(sqrtf(jj), 1e-12f);
                acc += fabsf(((i == j) ? 1.0f : 0.0f) - d / (ni * nj));
            }
        }
        acc = blockReduceSum(acc, red);
        if (tid == 0) cpart[i] = acc;
    }
}

// ---------------- fused te+tr layernorm ----------------
__global__ void fuse_tetr(const float* __restrict__ virpre, const float* __restrict__ aud,
                          const float* __restrict__ query, const float* __restrict__ value,
                          const float* __restrict__ g1, const float* __restrict__ b1,
                          const float* __restrict__ g2, const float* __restrict__ b2,
                          const float* __restrict__ g3, const float* __restrict__ b3,
                          float* __restrict__ out_te, float* __restrict__ out_tr,
                          float* __restrict__ cosbuf)
{
    __shared__ float red[32];
    bool is_tr = blockIdx.x >= NROWS;
    long long r = is_tr ? (blockIdx.x - NROWS) : blockIdx.x;
    const float* src = (is_tr ? aud : virpre) + r * DIM;
    const float* q = query + r * DIM;
    const float* gx = is_tr ? g3 : g2;
    const float* bx = is_tr ? b3 : b2;
    float* o = (is_tr ? out_tr : out_te) + r * DIM;

    float x[4], qv[4];
    float s = 0.f, s2 = 0.f;
    #pragma unroll
    for (int i = 0; i < 4; i++) {
        int c = threadIdx.x + 128 * i;
        x[i] = src[c]; qv[i] = q[c];
        s += x[i]; s2 += x[i] * x[i];
    }
    s  = blockReduceSum(s,  red);
    s2 = blockReduceSum(s2, red);
    if (is_tr) {
        const float* v = value + r * DIM;
        float sav = 0.f, svv = 0.f;
        #pragma unroll
        for (int i = 0; i < 4; i++) {
            int c = threadIdx.x + 128 * i;
            float vv = v[c];
            sav += x[i] * vv; svv += vv * vv;
        }
        sav = blockReduceSum(sav, red);
        svv = blockReduceSum(svv, red);
        if (threadIdx.x == 0) {
            float cosv = sav / fmaxf(sqrtf(s2) * sqrtf(svv), 1e-8f);
            cosbuf[r] = fabsf(1.0f - cosv);
        }
    }
    float mu = s * (1.0f / DIM);
    float var = s2 * (1.0f / DIM) - mu * mu;
    float inv = rsqrtf(var + 1e-5f);
    float t[4]; float ts = 0.f, ts2 = 0.f;
    #pragma unroll
    for (int i = 0; i < 4; i++) {
        int c = threadIdx.x + 128 * i;
        float ln = (x[i] - mu) * inv * gx[c] + bx[c];
        t[i] = qv[i] + ln; ts += t[i]; ts2 += t[i] * t[i];
    }
    ts  = blockReduceSum(ts,  red);
    ts2 = blockReduceSum(ts2, red);
    mu = ts * (1.0f / DIM);
    var = ts2 * (1.0f / DIM) - mu * mu;
    inv = rsqrtf(var + 1e-5f);
    #pragma unroll
    for (int i = 0; i < 4; i++) {
        int c = threadIdx.x + 128 * i;
        o[c] = (t[i] - mu) * inv * g1[c] + b1[c];
    }
}

// ---------------- final reductions ----------------
__global__ void final_reduce(const float* __restrict__ cosbuf, const float* __restrict__ cpart,
                             float* __restrict__ recon, float* __restrict__ contr)
{
    __shared__ float red[32];
    int b = blockIdx.x;
    if (b < 32) {
        float s = 0.0f;
        for (int i = threadIdx.x; i < 512; i += blockDim.x) s += cosbuf[b * 512 + i];
        s = blockReduceSum(s, red);
        if (threadIdx.x == 0) recon[b] = s;
    } else {
        float s = 0.0f;
        for (int i = threadIdx.x; i < SLOT; i += blockDim.x) s += cpart[i];
        s = blockReduceSum(s, red);
        if (threadIdx.x == 0) contr[0] = 0.5f * s;
    }
}

// ---------------- launch ----------------
#define SYM(p, s) cudaGetSymbolAddress((void**)&p, s)

extern "C" void kernel_launch(void* const* d_in, const int* in_sizes, int n_in,
                              void* d_out, int out_size)
{
    const float* query     = (const float*)d_in[0];
    const float* value     = (const float*)d_in[1];
    const float* key_mem   = (const float*)d_in[2];
    const float* value_mem = (const float*)d_in[3];
    const float* Wq = (const float*)d_in[4];
    const float* bq = (const float*)d_in[5];
    const float* Wv = (const float*)d_in[6];
    const float* bv = (const float*)d_in[7];
    const float* Wl = (const float*)d_in[8];
    const float* bl = (const float*)d_in[9];
    const float* g1 = (const float*)d_in[10];
    const float* b1 = (const float*)d_in[11];
    const float* g2 = (const float*)d_in[12];
    const float* b2 = (const float*)d_in[13];
    const float* g3 = (const float*)d_in[14];
    const float* b3 = (const float*)d_in[15];

    float* out        = (float*)d_out;
    float* out_te     = out;
    float* out_tr     = out + (long long)NROWS * DIM;
    float* out_recon  = out + 2ll * NROWS * DIM;
    float* out_contr  = out_recon + 32;

    float *p_virpre, *p_aud, *p_invkn, *p_gpart, *p_cos, *p_cpart;
    SYM(p_virpre, g_virpre); SYM(p_aud, g_aud);
    SYM(p_invkn, g_invkn); SYM(p_gpart, g_gpart);
    SYM(p_cos, g_cosbuf); SYM(p_cpart, g_cpart);

    __nv_bfloat16 *q_h, *q_l, *v_h, *v_l, *wq_h, *wq_l, *wv_h, *wv_l, *wl_h, *wl_l;
    __nv_bfloat16 *vm_h, *vm_l, *eqn_h, *eqn_l, *kn_h, *kn_l, *ka_h, *ka_l, *m2_h, *m2_l;
    __nv_bfloat16 *ev_h, *ev_l, *vn_h, *vn_l, *va_h, *va_l, *vt_h, *vt_l;
    SYM(q_h, g_q_h); SYM(q_l, g_q_l); SYM(v_h, g_v_h); SYM(v_l, g_v_l);
    SYM(wq_h, g_wq_h); SYM(wq_l, g_wq_l); SYM(wv_h, g_wv_h); SYM(wv_l, g_wv_l);
    SYM(wl_h, g_wl_h); SYM(wl_l, g_wl_l); SYM(vm_h, g_vm_h); SYM(vm_l, g_vm_l);
    SYM(eqn_h, g_eqn_h); SYM(eqn_l, g_eqn_l); SYM(kn_h, g_kn_h); SYM(kn_l, g_kn_l);
    SYM(ka_h, g_ka_h); SYM(ka_l, g_ka_l); SYM(m2_h, g_m2_h); SYM(m2_l, g_m2_l);
    SYM(ev_h, g_ev_h); SYM(ev_l, g_ev_l); SYM(vn_h, g_vn_h); SYM(vn_l, g_vn_l);
    SYM(va_h, g_va_h); SYM(va_l, g_va_l); SYM(vt_h, g_vt_h); SYM(vt_l, g_vt_l);

    cudaFuncSetAttribute(gemm_stage1, cudaFuncAttributeMaxDynamicSharedMemorySize, GSMEM);
    cudaFuncSetAttribute(gemm_sim,    cudaFuncAttributeMaxDynamicSharedMemorySize, GSMEM);
    cudaFuncSetAttribute(gemm_out,    cudaFuncAttributeMaxDynamicSharedMemorySize, GSMEM);

    // 0: all prep (splits, norms, contrastive partials)
    mega_prep<<<NB_TOTAL, 256>>>(query, value, key_mem, value_mem, Wq, Wv, Wl,
                                 q_h, q_l, v_h, v_l, wq_h, wq_l, wv_h, wv_l,
                                 wl_h, wl_l, vm_h, vm_l, kn_h, kn_l, vn_h, vn_l,
                                 vt_h, vt_l, p_cpart);

    // 1: eq (z=0) + ev (z=1) + m2t (z=2)
    gemm_stage1<<<dim3(4, 128, 3), 256, GSMEM>>>(
        q_h, q_l, wq_h, wq_l, v_h, v_l, wv_h, wv_l, wl_h, wl_l, vm_h, vm_l,
        eqn_h, eqn_l, ev_h, ev_l, m2_h, m2_l, bq, bv, p_invkn, p_gpart);

    // 2: vsim (z=0) + ksim heads (z=1..8), fused softmaxes
    gemm_sim<<<dim3(1, 128, 9), 256, GSMEM>>>(
        eqn_h, eqn_l, kn_h, kn_l, ev_h, ev_l, vn_h, vn_l,
        ka_h, ka_l, va_h, va_l, p_invkn, p_gpart);

    // 3: virpre (z=0, K=896) + aud (z=1, K=128)
    gemm_out<<<dim3(4, 128, 2), 256, GSMEM>>>(
        ka_h, ka_l, m2_h, m2_l, va_h, va_l, vt_h, vt_l, p_virpre, p_aud, bl);

    // 4: fused te + tr double-layernorm (+cos)
    fuse_tetr<<<2 * NROWS, 128>>>(p_virpre, p_aud, query, value,
                                  g1, b1, g2, b2, g3, b3, out_te, out_tr, p_cos);

    // 5: recon per-batch sums + contrastive final
    final_reduce<<<33, 128>>>(p_cos, p_cpart, out_recon, out_contr);
}

// round 7
// speedup vs baseline: 3.2056x; 1.1307x over previous
#include <cuda_runtime.h>
#include <cuda_bf16.h>
#include <cstdint>

#define NROWS 16384   // B*S
#define DIM 512
#define HEAD 8
#define SLOT 112
#define HD 64
#define RADIUSF 16.0f

// ---------------- scratch (device globals) ----------------
__device__ float g_virpre[NROWS * DIM];
__device__ float g_aud[NROWS * DIM];
__device__ float g_invkn[NROWS * HEAD];
__device__ float g_gpart[NROWS * 4];
__device__ float g_cosbuf[NROWS];
__device__ float g_cpart[SLOT];
// bf16 split pairs
__device__ __nv_bfloat16 g_q_h[NROWS * DIM],  g_q_l[NROWS * DIM];
__device__ __nv_bfloat16 g_v_h[NROWS * DIM],  g_v_l[NROWS * DIM];
__device__ __nv_bfloat16 g_wq_h[DIM * DIM],   g_wq_l[DIM * DIM];
__device__ __nv_bfloat16 g_wv_h[DIM * DIM],   g_wv_l[DIM * DIM];
__device__ __nv_bfloat16 g_wl_h[DIM * DIM * HEAD], g_wl_l[DIM * DIM * HEAD];
__device__ __nv_bfloat16 g_vm_h[SLOT * DIM],  g_vm_l[SLOT * DIM];
__device__ __nv_bfloat16 g_eqn_h[NROWS * DIM], g_eqn_l[NROWS * DIM];
__device__ __nv_bfloat16 g_kn_h[HEAD * SLOT * HD], g_kn_l[HEAD * SLOT * HD];
__device__ __nv_bfloat16 g_ka_h[NROWS * HEAD * SLOT], g_ka_l[NROWS * HEAD * SLOT];
__device__ __nv_bfloat16 g_m2_h[DIM * HEAD * SLOT],   g_m2_l[DIM * HEAD * SLOT];
__device__ __nv_bfloat16 g_ev_h[NROWS * DIM], g_ev_l[NROWS * DIM];
__device__ __nv_bfloat16 g_vn_h[SLOT * DIM],  g_vn_l[SLOT * DIM];
__device__ __nv_bfloat16 g_va_h[NROWS * 128], g_va_l[NROWS * 128];
__device__ __nv_bfloat16 g_vt_h[DIM * 128],   g_vt_l[DIM * 128];

// ---------------- helpers ----------------
__device__ __forceinline__ uint32_t smem_u32(const void* p) {
    uint32_t a;
    asm("{ .reg .u64 t; cvta.to.shared.u64 t, %1; cvt.u32.u64 %0, t; }" : "=r"(a) : "l"(p));
    return a;
}
__device__ __forceinline__ void cp16(uint32_t dst, const void* src, int sz) {
    asm volatile("cp.async.cg.shared.global [%0], [%1], 16, %2;"
                 :: "r"(dst), "l"(src), "r"(sz));
}
__device__ __forceinline__ void cp_commit() { asm volatile("cp.async.commit_group;" ::: "memory"); }
__device__ __forceinline__ void cp_wait0()  { asm volatile("cp.async.wait_group 0;"  ::: "memory"); }

__device__ __forceinline__ void ldm4(uint32_t (&r)[4], uint32_t a) {
    asm volatile("ldmatrix.sync.aligned.m8n8.x4.shared.b16 {%0,%1,%2,%3}, [%4];"
                 : "=r"(r[0]), "=r"(r[1]), "=r"(r[2]), "=r"(r[3]) : "r"(a));
}
__device__ __forceinline__ void mma16816(float (&c)[4], const uint32_t (&a)[4],
                                         uint32_t b0, uint32_t b1) {
    asm volatile(
        "mma.sync.aligned.m16n8k16.row.col.f32.bf16.bf16.f32 "
        "{%0,%1,%2,%3}, {%4,%5,%6,%7}, {%8,%9}, {%0,%1,%2,%3};"
        : "+f"(c[0]), "+f"(c[1]), "+f"(c[2]), "+f"(c[3])
        : "r"(a[0]), "r"(a[1]), "r"(a[2]), "r"(a[3]), "r"(b0), "r"(b1));
}
__device__ __forceinline__ void wsplit(__nv_bfloat16* h, __nv_bfloat16* l, long long i, float v) {
    __nv_bfloat16 hh = __float2bfloat16_rn(v);
    h[i] = hh;
    l[i] = __float2bfloat16_rn(v - __bfloat162float(hh));
}
__device__ __forceinline__ void spair(__nv_bfloat16* H, __nv_bfloat16* L, long long i,
                                      float a, float b) {
    __nv_bfloat16 h0 = __float2bfloat16_rn(a), h1 = __float2bfloat16_rn(b);
    *(__nv_bfloat162*)(H + i) = __halves2bfloat162(h0, h1);
    *(__nv_bfloat162*)(L + i) = __halves2bfloat162(
        __float2bfloat16_rn(a - __bfloat162float(h0)),
        __float2bfloat16_rn(b - __bfloat162float(h1)));
}
__device__ __forceinline__ float qred_sum(float v) {
    v += __shfl_xor_sync(0xffffffffu, v, 1);
    v += __shfl_xor_sync(0xffffffffu, v, 2);
    return v;
}
__device__ __forceinline__ float qred_max(float v) {
    v = fmaxf(v, __shfl_xor_sync(0xffffffffu, v, 1));
    v = fmaxf(v, __shfl_xor_sync(0xffffffffu, v, 2));
    return v;
}
__device__ __forceinline__ float blockReduceSum(float v, float* red) {
    int lane = threadIdx.x & 31, w = threadIdx.x >> 5;
    #pragma unroll
    for (int o = 16; o; o >>= 1) v += __shfl_down_sync(0xffffffffu, v, o);
    if (lane == 0) red[w] = v;
    __syncthreads();
    int nw = blockDim.x >> 5;
    float r = (threadIdx.x < nw) ? red[threadIdx.x] : 0.0f;
    if (w == 0) {
        #pragma unroll
        for (int o = 16; o; o >>= 1) r += __shfl_down_sync(0xffffffffu, r, o);
        if (lane == 0) red[0] = r;
    }
    __syncthreads();
    float out = red[0];
    __syncthreads();
    return out;
}

// ---------------- GEMM core (128x128 tile, bf16 3-split, double-buffered, 2 CTA/SM) ----------------
#define ROWB   80
#define HALFB  10240
#define STAGEB 40960
#define NST    2
#define GSMEM  (NST * STAGEB)

__device__ __forceinline__ void gemm_core(
    uint32_t sb, int tid,
    const __nv_bfloat16* __restrict__ Ah, const __nv_bfloat16* __restrict__ Al, int lda,
    const __nv_bfloat16* __restrict__ Bh, const __nv_bfloat16* __restrict__ Bl, int ldb,
    int K, int nvalid, float (&acc)[4][4][4])
{
    const int lane = tid & 31, wid = tid >> 5;
    const int wr = wid >> 2, wc = wid & 3;
    const int nc = K >> 5;

    auto issue = [&](int st, int c) {
        #pragma unroll
        for (int j = 0; j < 2; j++) {
            int id = tid + j * 256;
            int row = id >> 2, ch = id & 3;
            long long offa = (long long)row * lda + c * 32 + ch * 8;
            uint32_t d = sb + st * STAGEB + row * ROWB + ch * 16;
            cp16(d,         Ah + offa, 16);
            cp16(d + HALFB, Al + offa, 16);
            long long offb = (long long)row * ldb + c * 32 + ch * 8;
            int vb = (row < nvalid) ? 16 : 0;
            if (vb == 0) offb = 0;
            cp16(d + 2 * HALFB, Bh + offb, vb);
            cp16(d + 3 * HALFB, Bl + offb, vb);
        }
    };

    #pragma unroll
    for (int i = 0; i < 4; i++)
        #pragma unroll
        for (int j = 0; j < 4; j++)
            #pragma unroll
            for (int t = 0; t < 4; t++) acc[i][j][t] = 0.0f;

    issue(0, 0);
    cp_commit();

    const int rA = lane & 15, cA = lane >> 4;
    const int rB = (lane & 7) + ((lane >> 4) << 3), cB = (lane >> 3) & 1;

    for (int c = 0; c < nc; c++) {
        cp_wait0();
        __syncthreads();
        int nxt = c + 1;
        if (nxt < nc) issue(nxt & 1, nxt);   // other buffer; prior MMAs on it done (barrier)
        cp_commit();
        const uint32_t base = sb + (c & 1) * STAGEB;
        #pragma unroll
        for (int k16 = 0; k16 < 2; k16++) {
            const int k2 = k16 * 2;
            uint32_t aAddr[4], bAddr[2];
            #pragma unroll
            for (int mi = 0; mi < 4; mi++)
                aAddr[mi] = base + (uint32_t)((wr * 64 + mi * 16 + rA) * ROWB + (k2 + cA) * 16);
            #pragma unroll
            for (int ni = 0; ni < 2; ni++)
                bAddr[ni] = base + 2 * HALFB +
                            (uint32_t)((wc * 32 + ni * 16 + rB) * ROWB + (k2 + cB) * 16);

            uint32_t fAh[4][4], fB[2][4];
            #pragma unroll
            for (int mi = 0; mi < 4; mi++) ldm4(fAh[mi], aAddr[mi]);
            #pragma unroll
            for (int ni = 0; ni < 2; ni++) ldm4(fB[ni], bAddr[ni]);
            // hh
            #pragma unroll
            for (int mi = 0; mi < 4; mi++)
                #pragma unroll
                for (int nj = 0; nj < 4; nj++) {
                    const int bi = nj >> 1, bs = (nj & 1) * 2;
                    mma16816(acc[mi][nj], fAh[mi], fB[bi][bs], fB[bi][bs + 1]);
                }
            // lh (Al x Bh), Al in scoped regs
            {
                uint32_t fAl[4][4];
                #pragma unroll
                for (int mi = 0; mi < 4; mi++) ldm4(fAl[mi], aAddr[mi] + HALFB);
                #pragma unroll
                for (int mi = 0; mi < 4; mi++)
                    #pragma unroll
                    for (int nj = 0; nj < 4; nj++) {
                        const int bi = nj >> 1, bs = (nj & 1) * 2;
                        mma16816(acc[mi][nj], fAl[mi], fB[bi][bs], fB[bi][bs + 1]);
                    }
            }
            // hl (Ah x Bl), Bl overwrites fB
            #pragma unroll
            for (int ni = 0; ni < 2; ni++) ldm4(fB[ni], bAddr[ni] + HALFB);
            #pragma unroll
            for (int mi = 0; mi < 4; mi++)
                #pragma unroll
                for (int nj = 0; nj < 4; nj++) {
                    const int bi = nj >> 1, bs = (nj & 1) * 2;
                    mma16816(acc[mi][nj], fAh[mi], fB[bi][bs], fB[bi][bs + 1]);
                }
        }
    }
    __syncthreads();   // protect smem reuse by epilogue
}

__device__ __forceinline__ void epi_bias(float (&acc)[4][4][4], const float* bias,
                                         int blockCol, int wc, int lane) {
    #pragma unroll
    for (int nj = 0; nj < 4; nj++) {
        const int col = blockCol + wc * 32 + nj * 8 + (lane & 3) * 2;
        float b0 = bias[col], b1 = bias[col + 1];
        #pragma unroll
        for (int mi = 0; mi < 4; mi++) {
            acc[mi][nj][0] += b0; acc[mi][nj][1] += b1;
            acc[mi][nj][2] += b0; acc[mi][nj][3] += b1;
        }
    }
}

__device__ __forceinline__ void epi_split_store(
    float (&acc)[4][4][4], __nv_bfloat16* Ch, __nv_bfloat16* Cl, int ldc,
    int blockRow, int blockCol, int ncols, int wr, int wc, int lane)
{
    #pragma unroll
    for (int mi = 0; mi < 4; mi++) {
        long long R0 = (long long)(blockRow + wr * 64 + mi * 16 + (lane >> 2)) * ldc;
        long long R1 = R0 + 8LL * ldc;
        #pragma unroll
        for (int nj = 0; nj < 4; nj++) {
            int col = blockCol + wc * 32 + nj * 8 + (lane & 3) * 2;
            if (col >= ncols) continue;
            spair(Ch, Cl, R0 + col, acc[mi][nj][0], acc[mi][nj][1]);
            spair(Ch, Cl, R1 + col, acc[mi][nj][2], acc[mi][nj][3]);
        }
    }
}

__device__ __forceinline__ void epi_f32_store(
    float (&acc)[4][4][4], float* Cf, int ldc,
    int blockRow, int blockCol, int wr, int wc, int lane)
{
    #pragma unroll
    for (int mi = 0; mi < 4; mi++) {
        long long R0 = (long long)(blockRow + wr * 64 + mi * 16 + (lane >> 2)) * ldc;
        long long R1 = R0 + 8LL * ldc;
        #pragma unroll
        for (int nj = 0; nj < 4; nj++) {
            int col = blockCol + wc * 32 + nj * 8 + (lane & 3) * 2;
            *(float2*)(Cf + R0 + col) = make_float2(acc[mi][nj][0], acc[mi][nj][1]);
            *(float2*)(Cf + R1 + col) = make_float2(acc[mi][nj][2], acc[mi][nj][3]);
        }
    }
}

// ---------------- stage 1: eq (z=0), ev (z=1), m2t (z=2) ----------------
__global__ void __launch_bounds__(256, 2) gemm_stage1(
    const __nv_bfloat16* __restrict__ q_h, const __nv_bfloat16* __restrict__ q_l,
    const __nv_bfloat16* __restrict__ wq_h, const __nv_bfloat16* __restrict__ wq_l,
    const __nv_bfloat16* __restrict__ v_h, const __nv_bfloat16* __restrict__ v_l,
    const __nv_bfloat16* __restrict__ wv_h, const __nv_bfloat16* __restrict__ wv_l,
    const __nv_bfloat16* __restrict__ wl_h, const __nv_bfloat16* __restrict__ wl_l,
    const __nv_bfloat16* __restrict__ vm_h, const __nv_bfloat16* __restrict__ vm_l,
    __nv_bfloat16* eqn_h, __nv_bfloat16* eqn_l,
    __nv_bfloat16* ev_h, __nv_bfloat16* ev_l,
    __nv_bfloat16* m2_h, __nv_bfloat16* m2_l,
    const float* __restrict__ bq, const float* __restrict__ bv,
    float* __restrict__ invkn, float* __restrict__ gpart)
{
    extern __shared__ char smem[];
    const uint32_t sb = smem_u32(smem);
    const int tid = threadIdx.x, lane = tid & 31, wid = tid >> 5;
    const int wr = wid >> 2, wc = wid & 3;
    const int z = blockIdx.z;
    float acc[4][4][4];

    if (z == 2) {
        if (blockIdx.x != 0 || blockIdx.y >= 32) return;
        int h = blockIdx.y & 7, mb = blockIdx.y >> 3;
        gemm_core(sb, tid, wl_h + h * 512 + (long long)mb * 128 * (HEAD * DIM),
                  wl_l + h * 512 + (long long)mb * 128 * (HEAD * DIM), HEAD * DIM,
                  vm_h, vm_l, DIM, DIM, SLOT, acc);
        epi_split_store(acc, m2_h + h * SLOT, m2_l + h * SLOT, HEAD * SLOT,
                        mb * 128, 0, SLOT, wr, wc, lane);
        return;
    }

    const int blockRow = blockIdx.y * 128, blockCol = blockIdx.x * 128;
    if (z == 0)
        gemm_core(sb, tid, q_h + (long long)blockRow * DIM, q_l + (long long)blockRow * DIM, DIM,
                  wq_h + (long long)blockCol * DIM, wq_l + (long long)blockCol * DIM, DIM,
                  DIM, 128, acc);
    else
        gemm_core(sb, tid, v_h + (long long)blockRow * DIM, v_l + (long long)blockRow * DIM, DIM,
                  wv_h + (long long)blockCol * DIM, wv_l + (long long)blockCol * DIM, DIM,
                  DIM, 128, acc);

    epi_bias(acc, z == 0 ? bq : bv, blockCol, wc, lane);

    float* sred = (float*)smem;
    #pragma unroll
    for (int mi = 0; mi < 4; mi++) {
        float s0 = 0.f, s1 = 0.f;
        #pragma unroll
        for (int nj = 0; nj < 4; nj++) {
            s0 += acc[mi][nj][0] * acc[mi][nj][0] + acc[mi][nj][1] * acc[mi][nj][1];
            s1 += acc[mi][nj][2] * acc[mi][nj][2] + acc[mi][nj][3] * acc[mi][nj][3];
        }
        s0 = qred_sum(s0); s1 = qred_sum(s1);
        if ((lane & 3) == 0) {
            int r0 = wr * 64 + mi * 16 + (lane >> 2);
            sred[r0 * 4 + wc] = s0;
            sred[(r0 + 8) * 4 + wc] = s1;
        }
    }
    __syncthreads();
    if (z == 0) {
        if ((wc == 0 || wc == 2) && (lane & 3) == 0) {
            #pragma unroll
            for (int mi = 0; mi < 4; mi++)
                #pragma unroll
                for (int half = 0; half < 2; half++) {
                    int r = wr * 64 + mi * 16 + (lane >> 2) + half * 8;
                    float s = sred[r * 4 + wc] + sred[r * 4 + wc + 1];
                    invkn[(long long)(blockRow + r) * HEAD + blockIdx.x * 2 + (wc >> 1)]
                        = 1.0f / fmaxf(sqrtf(s), 1e-12f);
                }
        }
    } else {
        if (wc == 0 && (lane & 3) == 0) {
            #pragma unroll
            for (int mi = 0; mi < 4; mi++)
                #pragma unroll
                for (int half = 0; half < 2; half++) {
                    int r = wr * 64 + mi * 16 + (lane >> 2) + half * 8;
                    float s = sred[r * 4] + sred[r * 4 + 1] + sred[r * 4 + 2] + sred[r * 4 + 3];
                    gpart[(long long)(blockRow + r) * 4 + blockIdx.x] = s;
                }
        }
    }
    epi_split_store(acc, z == 0 ? eqn_h : ev_h, z == 0 ? eqn_l : ev_l, DIM,
                    blockRow, blockCol, 1 << 30, wr, wc, lane);
}

// ---------------- stage 2: vsim (z=0) + ksim heads (z=1..8) ----------------
__global__ void __launch_bounds__(256, 2) gemm_sim(
    const __nv_bfloat16* __restrict__ eqn_h, const __nv_bfloat16* __restrict__ eqn_l,
    const __nv_bfloat16* __restrict__ kn_h, const __nv_bfloat16* __restrict__ kn_l,
    const __nv_bfloat16* __restrict__ ev_h, const __nv_bfloat16* __restrict__ ev_l,
    const __nv_bfloat16* __restrict__ vn_h, const __nv_bfloat16* __restrict__ vn_l,
    __nv_bfloat16* ka_h, __nv_bfloat16* ka_l,
    __nv_bfloat16* va_h, __nv_bfloat16* va_l,
    const float* __restrict__ invkn, const float* __restrict__ gpart)
{
    extern __shared__ char smem[];
    const uint32_t sb = smem_u32(smem);
    const int tid = threadIdx.x, lane = tid & 31, wid = tid >> 5;
    const int wr = wid >> 2, wc = wid & 3;
    const int z = blockIdx.z;
    const int blockRow = blockIdx.y * 128;
    float acc[4][4][4];

    __nv_bfloat16 *Ch, *Cl;
    int ldc;
    bool is_val = (z == 0);
    if (is_val) {
        gemm_core(sb, tid, ev_h + (long long)blockRow * DIM, ev_l + (long long)blockRow * DIM, DIM,
                  vn_h, vn_l, DIM, DIM, SLOT, acc);
        Ch = va_h; Cl = va_l; ldc = 128;
    } else {
        int h = z - 1;
        gemm_core(sb, tid, eqn_h + (long long)blockRow * DIM + h * HD,
                  eqn_l + (long long)blockRow * DIM + h * HD, DIM,
                  kn_h + (long long)h * SLOT * HD, kn_l + (long long)h * SLOT * HD, HD,
                  HD, SLOT, acc);
        Ch = ka_h + h * SLOT; Cl = ka_l + h * SLOT; ldc = HEAD * SLOT;
    }

    float* sred = (float*)smem;
    float* ssum = sred + 512;
    const int h = z - 1;

    float scl[4][2];
    #pragma unroll
    for (int mi = 0; mi < 4; mi++)
        #pragma unroll
        for (int half = 0; half < 2; half++) {
            int r = blockRow + wr * 64 + mi * 16 + (lane >> 2) + half * 8;
            float iv;
            if (is_val) {
                float s4 = gpart[r * 4] + gpart[r * 4 + 1] + gpart[r * 4 + 2] + gpart[r * 4 + 3];
                iv = 1.0f / fmaxf(sqrtf(s4), 1e-12f);
            } else {
                iv = invkn[(long long)r * HEAD + h];
            }
            scl[mi][half] = RADIUSF * iv;
        }
    #pragma unroll
    for (int mi = 0; mi < 4; mi++) {
        float m0 = -1e30f, m1 = -1e30f;
        #pragma unroll
        for (int nj = 0; nj < 4; nj++) {
            const int col = wc * 32 + nj * 8 + (lane & 3) * 2;
            bool ok = col < SLOT;
            float l0 = ok ? scl[mi][0] * acc[mi][nj][0] : -1e30f;
            float l1 = ok ? scl[mi][0] * acc[mi][nj][1] : -1e30f;
            float l2 = ok ? scl[mi][1] * acc[mi][nj][2] : -1e30f;
            float l3 = ok ? scl[mi][1] * acc[mi][nj][3] : -1e30f;
            acc[mi][nj][0] = l0; acc[mi][nj][1] = l1;
            acc[mi][nj][2] = l2; acc[mi][nj][3] = l3;
            m0 = fmaxf(m0, fmaxf(l0, l1)); m1 = fmaxf(m1, fmaxf(l2, l3));
        }
        m0 = qred_max(m0); m1 = qred_max(m1);
        if ((lane & 3) == 0) {
            int r0 = wr * 64 + mi * 16 + (lane >> 2);
            sred[r0 * 4 + wc] = m0;
            sred[(r0 + 8) * 4 + wc] = m1;
        }
    }
    __syncthreads();
    #pragma unroll
    for (int mi = 0; mi < 4; mi++) {
        int r0 = wr * 64 + mi * 16 + (lane >> 2), r1 = r0 + 8;
        float M0 = fmaxf(fmaxf(sred[r0 * 4], sred[r0 * 4 + 1]),
                         fmaxf(sred[r0 * 4 + 2], sred[r0 * 4 + 3]));
        float M1 = fmaxf(fmaxf(sred[r1 * 4], sred[r1 * 4 + 1]),
                         fmaxf(sred[r1 * 4 + 2], sred[r1 * 4 + 3]));
        float s0 = 0.f, s1 = 0.f;
        #pragma unroll
        for (int nj = 0; nj < 4; nj++) {
            const int col = wc * 32 + nj * 8 + (lane & 3) * 2;
            bool ok = col < SLOT;
            float e0 = ok ? __expf(acc[mi][nj][0] - M0) : 0.f;
            float e1 = ok ? __expf(acc[mi][nj][1] - M0) : 0.f;
            float e2 = ok ? __expf(acc[mi][nj][2] - M1) : 0.f;
            float e3 = ok ? __expf(acc[mi][nj][3] - M1) : 0.f;
            acc[mi][nj][0] = e0; acc[mi][nj][1] = e1;
            acc[mi][nj][2] = e2; acc[mi][nj][3] = e3;
            s0 += e0 + e1; s1 += e2 + e3;
        }
        s0 = qred_sum(s0); s1 = qred_sum(s1);
        if ((lane & 3) == 0) {
            ssum[r0 * 4 + wc] = s0;
            ssum[r1 * 4 + wc] = s1;
        }
    }
    __syncthreads();
    #pragma unroll
    for (int mi = 0; mi < 4; mi++) {
        int r0l = wr * 64 + mi * 16 + (lane >> 2), r1l = r0l + 8;
        float i0 = 1.0f / (ssum[r0l * 4] + ssum[r0l * 4 + 1] + ssum[r0l * 4 + 2] + ssum[r0l * 4 + 3]);
        float i1 = 1.0f / (ssum[r1l * 4] + ssum[r1l * 4 + 1] + ssum[r1l * 4 + 2] + ssum[r1l * 4 + 3]);
        long long R0 = (long long)(blockRow + r0l) * ldc;
        long long R1 = (long long)(blockRow + r1l) * ldc;
        #pragma unroll
        for (int nj = 0; nj < 4; nj++) {
            const int col = wc * 32 + nj * 8 + (lane & 3) * 2;
            if (!is_val && col >= SLOT) continue;   // vsim writes zero pads
            spair(Ch, Cl, R0 + col, acc[mi][nj][0] * i0, acc[mi][nj][1] * i0);
            spair(Ch, Cl, R1 + col, acc[mi][nj][2] * i1, acc[mi][nj][3] * i1);
        }
    }
}

// ---------------- stage 3: virpre (z=0, K=896) + aud (z=1, K=128) ----------------
__global__ void __launch_bounds__(256, 2) gemm_out(
    const __nv_bfloat16* __restrict__ ka_h, const __nv_bfloat16* __restrict__ ka_l,
    const __nv_bfloat16* __restrict__ m2_h, const __nv_bfloat16* __restrict__ m2_l,
    const __nv_bfloat16* __restrict__ va_h, const __nv_bfloat16* __restrict__ va_l,
    const __nv_bfloat16* __restrict__ vt_h, const __nv_bfloat16* __restrict__ vt_l,
    float* __restrict__ virpre, float* __restrict__ aud,
    const float* __restrict__ bl)
{
    extern __shared__ char smem[];
    const uint32_t sb = smem_u32(smem);
    const int tid = threadIdx.x, lane = tid & 31, wid = tid >> 5;
    const int wr = wid >> 2, wc = wid & 3;
    const int z = blockIdx.z;
    const int blockRow = blockIdx.y * 128, blockCol = blockIdx.x * 128;
    float acc[4][4][4];

    if (z == 0) {
        gemm_core(sb, tid, ka_h + (long long)blockRow * (HEAD * SLOT),
                  ka_l + (long long)blockRow * (HEAD * SLOT), HEAD * SLOT,
                  m2_h + (long long)blockCol * (HEAD * SLOT),
                  m2_l + (long long)blockCol * (HEAD * SLOT), HEAD * SLOT,
                  HEAD * SLOT, 128, acc);
        epi_bias(acc, bl, blockCol, wc, lane);
        epi_f32_store(acc, virpre, DIM, blockRow, blockCol, wr, wc, lane);
    } else {
        gemm_core(sb, tid, va_h + (long long)blockRow * 128, va_l + (long long)blockRow * 128, 128,
                  vt_h + (long long)blockCol * 128, vt_l + (long long)blockCol * 128, 128,
                  128, 128, acc);
        epi_f32_store(acc, aud, DIM, blockRow, blockCol, wr, wc, lane);
    }
}

// ---------------- mega prep ----------------
#define NB_Q  8192
#define NB_V  8192
#define NB_WQ 256
#define NB_WV 256
#define NB_WL 2048
#define NB_VM 56
#define NB_KN 112
#define NB_VN 112
#define NB_VT 256
#define NB_CP 112
#define NB_TOTAL (NB_Q+NB_V+NB_WQ+NB_WV+NB_WL+NB_VM+NB_KN+NB_VN+NB_VT+NB_CP)

__device__ __forceinline__ void do_split4(const float4* src, __nv_bfloat16* h,
                                          __nv_bfloat16* l, long long i) {
    float4 v = src[i];
    __nv_bfloat16 h0 = __float2bfloat16_rn(v.x), h1 = __float2bfloat16_rn(v.y);
    __nv_bfloat16 h2 = __float2bfloat16_rn(v.z), h3 = __float2bfloat16_rn(v.w);
    *(__nv_bfloat162*)(h + i * 4)     = __halves2bfloat162(h0, h1);
    *(__nv_bfloat162*)(h + i * 4 + 2) = __halves2bfloat162(h2, h3);
    *(__nv_bfloat162*)(l + i * 4) = __halves2bfloat162(
        __float2bfloat16_rn(v.x - __bfloat162float(h0)),
        __float2bfloat16_rn(v.y - __bfloat162float(h1)));
    *(__nv_bfloat162*)(l + i * 4 + 2) = __halves2bfloat162(
        __float2bfloat16_rn(v.z - __bfloat162float(h2)),
        __float2bfloat16_rn(v.w - __bfloat162float(h3)));
}

__global__ void mega_prep(
    const float* __restrict__ query, const float* __restrict__ value,
    const float* __restrict__ key_mem, const float* __restrict__ value_mem,
    const float* __restrict__ Wq, const float* __restrict__ Wv, const float* __restrict__ Wl,
    __nv_bfloat16* q_h, __nv_bfloat16* q_l, __nv_bfloat16* v_h, __nv_bfloat16* v_l,
    __nv_bfloat16* wq_h, __nv_bfloat16* wq_l, __nv_bfloat16* wv_h, __nv_bfloat16* wv_l,
    __nv_bfloat16* wl_h, __nv_bfloat16* wl_l, __nv_bfloat16* vm_h, __nv_bfloat16* vm_l,
    __nv_bfloat16* kn_h, __nv_bfloat16* kn_l, __nv_bfloat16* vn_h, __nv_bfloat16* vn_l,
    __nv_bfloat16* vt_h, __nv_bfloat16* vt_l, float* cpart)
{
    __shared__ float sh[544];
    int b = blockIdx.x, tid = threadIdx.x;

    if (b < NB_Q) { do_split4((const float4*)query, q_h, q_l, (long long)b * 256 + tid); return; }
    b -= NB_Q;
    if (b < NB_V) { do_split4((const float4*)value, v_h, v_l, (long long)b * 256 + tid); return; }
    b -= NB_V;
    if (b < NB_WQ) { do_split4((const float4*)Wq, wq_h, wq_l, (long long)b * 256 + tid); return; }
    b -= NB_WQ;
    if (b < NB_WV) { do_split4((const float4*)Wv, wv_h, wv_l, (long long)b * 256 + tid); return; }
    b -= NB_WV;
    if (b < NB_WL) { do_split4((const float4*)Wl, wl_h, wl_l, (long long)b * 256 + tid); return; }
    b -= NB_WL;
    if (b < NB_VM) { do_split4((const float4*)value_mem, vm_h, vm_l, (long long)b * 256 + tid); return; }
    b -= NB_VM;
    if (b < NB_KN) {
        int seg = b * 8 + (tid >> 5), lane = tid & 31;
        long long base = (long long)seg * 64;
        float a = key_mem[base + lane], c = key_mem[base + lane + 32];
        float s = a * a + c * c;
        #pragma unroll
        for (int o = 16; o; o >>= 1) s += __shfl_xor_sync(0xffffffffu, s, o);
        float inv = 1.0f / fmaxf(sqrtf(s), 1e-12f);
        wsplit(kn_h, kn_l, base + lane, a * inv);
        wsplit(kn_h, kn_l, base + lane + 32, c * inv);
        return;
    }
    b -= NB_KN;
    if (b < NB_VN) {
        long long r = b;
        float a = value_mem[r * DIM + tid], c = value_mem[r * DIM + tid + 256];
        float s = blockReduceSum(a * a + c * c, sh);
        float inv = 1.0f / fmaxf(sqrtf(s), 1e-12f);
        wsplit(vn_h, vn_l, r * DIM + tid, a * inv);
        wsplit(vn_h, vn_l, r * DIM + tid + 256, c * inv);
        return;
    }
    b -= NB_VN;
    if (b < NB_VT) {
        int idx = b * 256 + tid;
        int j = idx >> 7, s = idx & 127;
        float v = (s < SLOT) ? value_mem[(long long)s * DIM + j] : 0.0f;
        wsplit(vt_h, vt_l, idx, v);
        return;
    }
    b -= NB_VT;
    {
        int i = b;
        float* vi = sh;
        float* red = sh + 512;
        for (int c = tid; c < DIM; c += 256) vi[c] = value_mem[(long long)i * DIM + c];
        __syncthreads();
        float s = 0.f;
        for (int c = tid; c < DIM; c += 256) s += vi[c] * vi[c];
        s = blockReduceSum(s, red);
        float ni = fmaxf(sqrtf(s), 1e-12f);
        int w = tid >> 5, lane = tid & 31;
        float acc = 0.f;
        for (int j = w; j < SLOT; j += 8) {
            float d = 0.f, jj = 0.f;
            for (int c = lane; c < DIM; c += 32) {
                float vj = value_mem[(long long)j * DIM + c];
                d += vi[c] * vj; jj += vj * vj;
            }
            #pragma unroll
            for (int o = 16; o; o >>= 1) {
                d += __shfl_down_sync(0xffffffffu, d, o);
                jj += __shfl_down_sync(0xffffffffu, jj, o);
            }
            if (lane == 0) {
                float nj = fmaxf(sqrtf(jj), 1e-12f);
                acc += fabsf(((i == j) ? 1.0f : 0.0f) - d / (ni * nj));
            }
        }
        acc = blockReduceSum(acc, red);
        if (tid == 0) cpart[i] = acc;
    }
}

// ---------------- fused te+tr layernorm ----------------
__global__ void fuse_tetr(const float* __restrict__ virpre, const float* __restrict__ aud,
                          const float* __restrict__ query, const float* __restrict__ value,
                          const float* __restrict__ g1, const float* __restrict__ b1,
                          const float* __restrict__ g2, const float* __restrict__ b2,
                          const float* __restrict__ g3, const float* __restrict__ b3,
                          float* __restrict__ out_te, float* __restrict__ out_tr,
                          float* __restrict__ cosbuf)
{
    __shared__ float red[32];
    bool is_tr = blockIdx.x >= NROWS;
    long long r = is_tr ? (blockIdx.x - NROWS) : blockIdx.x;
    const float* src = (is_tr ? aud : virpre) + r * DIM;
    const float* q = query + r * DIM;
    const float* gx = is_tr ? g3 : g2;
    const float* bx = is_tr ? b3 : b2;
    float* o = (is_tr ? out_tr : out_te) + r * DIM;

    float x[4], qv[4];
    float s = 0.f, s2 = 0.f;
    #pragma unroll
    for (int i = 0; i < 4; i++) {
        int c = threadIdx.x + 128 * i;
        x[i] = src[c]; qv[i] = q[c];
        s += x[i]; s2 += x[i] * x[i];
    }
    s  = blockReduceSum(s,  red);
    s2 = blockReduceSum(s2, red);
    if (is_tr) {
        const float* v = value + r * DIM;
        float sav = 0.f, svv = 0.f;
        #pragma unroll
        for (int i = 0; i < 4; i++) {
            int c = threadIdx.x + 128 * i;
            float vv = v[c];
            sav += x[i] * vv; svv += vv * vv;
        }
        sav = blockReduceSum(sav, red);
        svv = blockReduceSum(svv, red);
        if (threadIdx.x == 0) {
            float cosv = sav / fmaxf(sqrtf(s2) * sqrtf(svv), 1e-8f);
            cosbuf[r] = fabsf(1.0f - cosv);
        }
    }
    float mu = s * (1.0f / DIM);
    float var = s2 * (1.0f / DIM) - mu * mu;
    float inv = rsqrtf(var + 1e-5f);
    float t[4]; float ts = 0.f, ts2 = 0.f;
    #pragma unroll
    for (int i = 0; i < 4; i++) {
        int c = threadIdx.x + 128 * i;
        float ln = (x[i] - mu) * inv * gx[c] + bx[c];
        t[i] = qv[i] + ln; ts += t[i]; ts2 += t[i] * t[i];
    }
    ts  = blockReduceSum(ts,  red);
    ts2 = blockReduceSum(ts2, red);
    mu = ts * (1.0f / DIM);
    var = ts2 * (1.0f / DIM) - mu * mu;
    inv = rsqrtf(var + 1e-5f);
    #pragma unroll
    for (int i = 0; i < 4; i++) {
        int c = threadIdx.x + 128 * i;
        o[c] = (t[i] - mu) * inv * g1[c] + b1[c];
    }
}

// ---------------- final reductions ----------------
__global__ void final_reduce(const float* __restrict__ cosbuf, const float* __restrict__ cpart,
                             float* __restrict__ recon, float* __restrict__ contr)
{
    __shared__ float red[32];
    int b = blockIdx.x;
    if (b < 32) {
        float s = 0.0f;
        for (int i = threadIdx.x; i < 512; i += blockDim.x) s += cosbuf[b * 512 + i];
        s = blockReduceSum(s, red);
        if (threadIdx.x == 0) recon[b] = s;
    } else {
        float s = 0.0f;
        for (int i = threadIdx.x; i < SLOT; i += blockDim.x) s += cpart[i];
        s = blockReduceSum(s, red);
        if (threadIdx.x == 0) contr[0] = 0.5f * s;
    }
}

// ---------------- launch ----------------
#define SYM(p, s) cudaGetSymbolAddress((void**)&p, s)

extern "C" void kernel_launch(void* const* d_in, const int* in_sizes, int n_in,
                              void* d_out, int out_size)
{
    const float* query     = (const float*)d_in[0];
    const float* value     = (const float*)d_in[1];
    const float* key_mem   = (const float*)d_in[2];
    const float* value_mem = (const float*)d_in[3];
    const float* Wq = (const float*)d_in[4];
    const float* bq = (const float*)d_in[5];
    const float* Wv = (const float*)d_in[6];
    const float* bv = (const float*)d_in[7];
    const float* Wl = (const float*)d_in[8];
    const float* bl = (const float*)d_in[9];
    const float* g1 = (const float*)d_in[10];
    const float* b1 = (const float*)d_in[11];
    const float* g2 = (const float*)d_in[12];
    const float* b2 = (const float*)d_in[13];
    const float* g3 = (const float*)d_in[14];
    const float* b3 = (const float*)d_in[15];

    float* out        = (float*)d_out;
    float* out_te     = out;
    float* out_tr     = out + (long long)NROWS * DIM;
    float* out_recon  = out + 2ll * NROWS * DIM;
    float* out_contr  = out_recon + 32;

    float *p_virpre, *p_aud, *p_invkn, *p_gpart, *p_cos, *p_cpart;
    SYM(p_virpre, g_virpre); SYM(p_aud, g_aud);
    SYM(p_invkn, g_invkn); SYM(p_gpart, g_gpart);
    SYM(p_cos, g_cosbuf); SYM(p_cpart, g_cpart);

    __nv_bfloat16 *q_h, *q_l, *v_h, *v_l, *wq_h, *wq_l, *wv_h, *wv_l, *wl_h, *wl_l;
    __nv_bfloat16 *vm_h, *vm_l, *eqn_h, *eqn_l, *kn_h, *kn_l, *ka_h, *ka_l, *m2_h, *m2_l;
    __nv_bfloat16 *ev_h, *ev_l, *vn_h, *vn_l, *va_h, *va_l, *vt_h, *vt_l;
    SYM(q_h, g_q_h); SYM(q_l, g_q_l); SYM(v_h, g_v_h); SYM(v_l, g_v_l);
    SYM(wq_h, g_wq_h); SYM(wq_l, g_wq_l); SYM(wv_h, g_wv_h); SYM(wv_l, g_wv_l);
    SYM(wl_h, g_wl_h); SYM(wl_l, g_wl_l); SYM(vm_h, g_vm_h); SYM(vm_l, g_vm_l);
    SYM(eqn_h, g_eqn_h); SYM(eqn_l, g_eqn_l); SYM(kn_h, g_kn_h); SYM(kn_l, g_kn_l);
    SYM(ka_h, g_ka_h); SYM(ka_l, g_ka_l); SYM(m2_h, g_m2_h); SYM(m2_l, g_m2_l);
    SYM(ev_h, g_ev_h); SYM(ev_l, g_ev_l); SYM(vn_h, g_vn_h); SYM(vn_l, g_vn_l);
    SYM(va_h, g_va_h); SYM(va_l, g_va_l); SYM(vt_h, g_vt_h); SYM(vt_l, g_vt_l);

    cudaFuncSetAttribute(gemm_stage1, cudaFuncAttributeMaxDynamicSharedMemorySize, GSMEM);
    cudaFuncSetAttribute(gemm_sim,    cudaFuncAttributeMaxDynamicSharedMemorySize, GSMEM);
    cudaFuncSetAttribute(gemm_out,    cudaFuncAttributeMaxDynamicSharedMemorySize, GSMEM);

    // 0: all prep (splits, norms, contrastive partials)
    mega_prep<<<NB_TOTAL, 256>>>(query, value, key_mem, value_mem, Wq, Wv, Wl,
                                 q_h, q_l, v_h, v_l, wq_h, wq_l, wv_h, wv_l,
                                 wl_h, wl_l, vm_h, vm_l, kn_h, kn_l, vn_h, vn_l,
                                 vt_h, vt_l, p_cpart);

    // 1: eq (z=0) + ev (z=1) + m2t (z=2)
    gemm_stage1<<<dim3(4, 128, 3), 256, GSMEM>>>(
        q_h, q_l, wq_h, wq_l, v_h, v_l, wv_h, wv_l, wl_h, wl_l, vm_h, vm_l,
        eqn_h, eqn_l, ev_h, ev_l, m2_h, m2_l, bq, bv, p_invkn, p_gpart);

    // 2: vsim (z=0) + ksim heads (z=1..8), fused softmaxes
    gemm_sim<<<dim3(1, 128, 9), 256, GSMEM>>>(
        eqn_h, eqn_l, kn_h, kn_l, ev_h, ev_l, vn_h, vn_l,
        ka_h, ka_l, va_h, va_l, p_invkn, p_gpart);

    // 3: virpre (z=0, K=896) + aud (z=1, K=128)
    gemm_out<<<dim3(4, 128, 2), 256, GSMEM>>>(
        ka_h, ka_l, m2_h, m2_l, va_h, va_l, vt_h, vt_l, p_virpre, p_aud, bl);

    // 4: fused te + tr double-layernorm (+cos)
    fuse_tetr<<<2 * NROWS, 128>>>(p_virpre, p_aud, query, value,
                                  g1, b1, g2, b2, g3, b3, out_te, out_tr, p_cos);

    // 5: recon per-batch sums + contrastive final
    final_reduce<<<33, 128>>>(p_cos, p_cpart, out_recon, out_contr);
}

// round 8
// speedup vs baseline: 3.6451x; 1.1371x over previous
#include <cuda_runtime.h>
#include <cuda_bf16.h>
#include <cuda_fp16.h>
#include <cstdint>

#define NROWS 16384   // B*S
#define DIM 512
#define HEAD 8
#define SLOT 112
#define HD 64
#define RADIUSF 16.0f

// ---------------- scratch (device globals) ----------------
__device__ float g_virpre[NROWS * DIM];
__device__ float g_aud[NROWS * DIM];
__device__ float g_invkn[NROWS * HEAD];
__device__ float g_gpart[NROWS * 4];
__device__ float g_cosbuf[NROWS];
__device__ float g_cpart[SLOT];
// bf16 split pairs (softmax-feeding path: full 3-term accuracy)
__device__ __nv_bfloat16 g_q_h[NROWS * DIM],  g_q_l[NROWS * DIM];
__device__ __nv_bfloat16 g_v_h[NROWS * DIM],  g_v_l[NROWS * DIM];
__device__ __nv_bfloat16 g_wq_h[DIM * DIM],   g_wq_l[DIM * DIM];
__device__ __nv_bfloat16 g_wv_h[DIM * DIM],   g_wv_l[DIM * DIM];
__device__ __nv_bfloat16 g_wl_h[DIM * DIM * HEAD], g_wl_l[DIM * DIM * HEAD];
__device__ __nv_bfloat16 g_vm_h[SLOT * DIM],  g_vm_l[SLOT * DIM];
__device__ __nv_bfloat16 g_eqn_h[NROWS * DIM], g_eqn_l[NROWS * DIM];
__device__ __nv_bfloat16 g_kn_h[HEAD * SLOT * HD], g_kn_l[HEAD * SLOT * HD];
__device__ __nv_bfloat16 g_ev_h[NROWS * DIM], g_ev_l[NROWS * DIM];
__device__ __nv_bfloat16 g_vn_h[SLOT * DIM],  g_vn_l[SLOT * DIM];
// fp16 (output path: 2-term scheme; A side hi-only, B side hi+lo)
__device__ __half g_ka[NROWS * HEAD * SLOT];
__device__ __half g_va[NROWS * 128];
__device__ __half g_m2h[DIM * HEAD * SLOT], g_m2l[DIM * HEAD * SLOT];
__device__ __half g_vth[DIM * 128],         g_vtl[DIM * 128];

// ---------------- helpers ----------------
__device__ __forceinline__ uint32_t smem_u32(const void* p) {
    uint32_t a;
    asm("{ .reg .u64 t; cvta.to.shared.u64 t, %1; cvt.u32.u64 %0, t; }" : "=r"(a) : "l"(p));
    return a;
}
__device__ __forceinline__ void cp16(uint32_t dst, const void* src, int sz) {
    asm volatile("cp.async.cg.shared.global [%0], [%1], 16, %2;"
                 :: "r"(dst), "l"(src), "r"(sz));
}
__device__ __forceinline__ void cp_commit() { asm volatile("cp.async.commit_group;" ::: "memory"); }
__device__ __forceinline__ void cp_wait0()  { asm volatile("cp.async.wait_group 0;"  ::: "memory"); }

__device__ __forceinline__ void ldm4(uint32_t (&r)[4], uint32_t a) {
    asm volatile("ldmatrix.sync.aligned.m8n8.x4.shared.b16 {%0,%1,%2,%3}, [%4];"
                 : "=r"(r[0]), "=r"(r[1]), "=r"(r[2]), "=r"(r[3]) : "r"(a));
}
__device__ __forceinline__ void mma16816(float (&c)[4], const uint32_t (&a)[4],
                                         uint32_t b0, uint32_t b1) {
    asm volatile(
        "mma.sync.aligned.m16n8k16.row.col.f32.bf16.bf16.f32 "
        "{%0,%1,%2,%3}, {%4,%5,%6,%7}, {%8,%9}, {%0,%1,%2,%3};"
        : "+f"(c[0]), "+f"(c[1]), "+f"(c[2]), "+f"(c[3])
        : "r"(a[0]), "r"(a[1]), "r"(a[2]), "r"(a[3]), "r"(b0), "r"(b1));
}
__device__ __forceinline__ void mma16816h(float (&c)[4], const uint32_t (&a)[4],
                                          uint32_t b0, uint32_t b1) {
    asm volatile(
        "mma.sync.aligned.m16n8k16.row.col.f32.f16.f16.f32 "
        "{%0,%1,%2,%3}, {%4,%5,%6,%7}, {%8,%9}, {%0,%1,%2,%3};"
        : "+f"(c[0]), "+f"(c[1]), "+f"(c[2]), "+f"(c[3])
        : "r"(a[0]), "r"(a[1]), "r"(a[2]), "r"(a[3]), "r"(b0), "r"(b1));
}
__device__ __forceinline__ void wsplit(__nv_bfloat16* h, __nv_bfloat16* l, long long i, float v) {
    __nv_bfloat16 hh = __float2bfloat16_rn(v);
    h[i] = hh;
    l[i] = __float2bfloat16_rn(v - __bfloat162float(hh));
}
__device__ __forceinline__ void wsplit_f16(__half* h, __half* l, long long i, float v) {
    __half hh = __float2half_rn(v);
    h[i] = hh;
    l[i] = __float2half_rn(v - __half2float(hh));
}
__device__ __forceinline__ void spair(__nv_bfloat16* H, __nv_bfloat16* L, long long i,
                                      float a, float b) {
    __nv_bfloat16 h0 = __float2bfloat16_rn(a), h1 = __float2bfloat16_rn(b);
    *(__nv_bfloat162*)(H + i) = __halves2bfloat162(h0, h1);
    *(__nv_bfloat162*)(L + i) = __halves2bfloat162(
        __float2bfloat16_rn(a - __bfloat162float(h0)),
        __float2bfloat16_rn(b - __bfloat162float(h1)));
}
__device__ __forceinline__ void spair_f16(__half* H, __half* L, long long i,
                                          float a, float b) {
    __half h0 = __float2half_rn(a), h1 = __float2half_rn(b);
    *(__half2*)(H + i) = __halves2half2(h0, h1);
    *(__half2*)(L + i) = __halves2half2(
        __float2half_rn(a - __half2float(h0)),
        __float2half_rn(b - __half2float(h1)));
}
__device__ __forceinline__ void hpair(__half* H, long long i, float a, float b) {
    *(__half2*)(H + i) = __floats2half2_rn(a, b);
}
__device__ __forceinline__ float qred_sum(float v) {
    v += __shfl_xor_sync(0xffffffffu, v, 1);
    v += __shfl_xor_sync(0xffffffffu, v, 2);
    return v;
}
__device__ __forceinline__ float qred_max(float v) {
    v = fmaxf(v, __shfl_xor_sync(0xffffffffu, v, 1));
    v = fmaxf(v, __shfl_xor_sync(0xffffffffu, v, 2));
    return v;
}
__device__ __forceinline__ float blockReduceSum(float v, float* red) {
    int lane = threadIdx.x & 31, w = threadIdx.x >> 5;
    #pragma unroll
    for (int o = 16; o; o >>= 1) v += __shfl_down_sync(0xffffffffu, v, o);
    if (lane == 0) red[w] = v;
    __syncthreads();
    int nw = blockDim.x >> 5;
    float r = (threadIdx.x < nw) ? red[threadIdx.x] : 0.0f;
    if (w == 0) {
        #pragma unroll
        for (int o = 16; o; o >>= 1) r += __shfl_down_sync(0xffffffffu, r, o);
        if (lane == 0) red[0] = r;
    }
    __syncthreads();
    float out = red[0];
    __syncthreads();
    return out;
}

// ---------------- bf16 3-term GEMM core (128x128 tile, double-buffered) ----------------
#define ROWB   80
#define HALFB  10240
#define STAGEB 40960
#define GSMEM  (2 * STAGEB)

__device__ __forceinline__ void gemm_core(
    uint32_t sb, int tid,
    const __nv_bfloat16* __restrict__ Ah, const __nv_bfloat16* __restrict__ Al, int lda,
    const __nv_bfloat16* __restrict__ Bh, const __nv_bfloat16* __restrict__ Bl, int ldb,
    int K, int nvalid, float (&acc)[4][4][4])
{
    const int lane = tid & 31, wid = tid >> 5;
    const int wr = wid >> 2, wc = wid & 3;
    const int nc = K >> 5;

    auto issue = [&](int st, int c) {
        #pragma unroll
        for (int j = 0; j < 2; j++) {
            int id = tid + j * 256;
            int row = id >> 2, ch = id & 3;
            long long offa = (long long)row * lda + c * 32 + ch * 8;
            uint32_t d = sb + st * STAGEB + row * ROWB + ch * 16;
            cp16(d,         Ah + offa, 16);
            cp16(d + HALFB, Al + offa, 16);
            long long offb = (long long)row * ldb + c * 32 + ch * 8;
            int vb = (row < nvalid) ? 16 : 0;
            if (vb == 0) offb = 0;
            cp16(d + 2 * HALFB, Bh + offb, vb);
            cp16(d + 3 * HALFB, Bl + offb, vb);
        }
    };

    #pragma unroll
    for (int i = 0; i < 4; i++)
        #pragma unroll
        for (int j = 0; j < 4; j++)
            #pragma unroll
            for (int t = 0; t < 4; t++) acc[i][j][t] = 0.0f;

    issue(0, 0);
    cp_commit();

    const int rA = lane & 15, cA = lane >> 4;
    const int rB = (lane & 7) + ((lane >> 4) << 3), cB = (lane >> 3) & 1;

    for (int c = 0; c < nc; c++) {
        cp_wait0();
        __syncthreads();
        int nxt = c + 1;
        if (nxt < nc) issue(nxt & 1, nxt);
        cp_commit();
        const uint32_t base = sb + (c & 1) * STAGEB;
        #pragma unroll
        for (int k16 = 0; k16 < 2; k16++) {
            const int k2 = k16 * 2;
            uint32_t aAddr[4], bAddr[2];
            #pragma unroll
            for (int mi = 0; mi < 4; mi++)
                aAddr[mi] = base + (uint32_t)((wr * 64 + mi * 16 + rA) * ROWB + (k2 + cA) * 16);
            #pragma unroll
            for (int ni = 0; ni < 2; ni++)
                bAddr[ni] = base + 2 * HALFB +
                            (uint32_t)((wc * 32 + ni * 16 + rB) * ROWB + (k2 + cB) * 16);

            uint32_t fAh[4][4], fB[2][4];
            #pragma unroll
            for (int mi = 0; mi < 4; mi++) ldm4(fAh[mi], aAddr[mi]);
            #pragma unroll
            for (int ni = 0; ni < 2; ni++) ldm4(fB[ni], bAddr[ni]);
            #pragma unroll
            for (int mi = 0; mi < 4; mi++)
                #pragma unroll
                for (int nj = 0; nj < 4; nj++) {
                    const int bi = nj >> 1, bs = (nj & 1) * 2;
                    mma16816(acc[mi][nj], fAh[mi], fB[bi][bs], fB[bi][bs + 1]);
                }
            {
                uint32_t fAl[4][4];
                #pragma unroll
                for (int mi = 0; mi < 4; mi++) ldm4(fAl[mi], aAddr[mi] + HALFB);
                #pragma unroll
                for (int mi = 0; mi < 4; mi++)
                    #pragma unroll
                    for (int nj = 0; nj < 4; nj++) {
                        const int bi = nj >> 1, bs = (nj & 1) * 2;
                        mma16816(acc[mi][nj], fAl[mi], fB[bi][bs], fB[bi][bs + 1]);
                    }
            }
            #pragma unroll
            for (int ni = 0; ni < 2; ni++) ldm4(fB[ni], bAddr[ni] + HALFB);
            #pragma unroll
            for (int mi = 0; mi < 4; mi++)
                #pragma unroll
                for (int nj = 0; nj < 4; nj++) {
                    const int bi = nj >> 1, bs = (nj & 1) * 2;
                    mma16816(acc[mi][nj], fAh[mi], fB[bi][bs], fB[bi][bs + 1]);
                }
        }
    }
    __syncthreads();
}

// ---------------- fp16 2-term GEMM core (A hi-only, B hi+lo) ----------------
#define STAGEB2 30720
#define GSMEM2  (2 * STAGEB2)

__device__ __forceinline__ void gemm_core_f16(
    uint32_t sb, int tid,
    const __half* __restrict__ Ah, int lda,
    const __half* __restrict__ Bh, const __half* __restrict__ Bl, int ldb,
    int K, float (&acc)[4][4][4])
{
    const int lane = tid & 31, wid = tid >> 5;
    const int wr = wid >> 2, wc = wid & 3;
    const int nc = K >> 5;

    auto issue = [&](int st, int c) {
        #pragma unroll
        for (int j = 0; j < 2; j++) {
            int id = tid + j * 256;
            int row = id >> 2, ch = id & 3;
            long long offa = (long long)row * lda + c * 32 + ch * 8;
            uint32_t d = sb + st * STAGEB2 + row * ROWB + ch * 16;
            cp16(d, Ah + offa, 16);
            long long offb = (long long)row * ldb + c * 32 + ch * 8;
            cp16(d + HALFB,     Bh + offb, 16);
            cp16(d + 2 * HALFB, Bl + offb, 16);
        }
    };

    #pragma unroll
    for (int i = 0; i < 4; i++)
        #pragma unroll
        for (int j = 0; j < 4; j++)
            #pragma unroll
            for (int t = 0; t < 4; t++) acc[i][j][t] = 0.0f;

    issue(0, 0);
    cp_commit();

    const int rA = lane & 15, cA = lane >> 4;
    const int rB = (lane & 7) + ((lane >> 4) << 3), cB = (lane >> 3) & 1;

    for (int c = 0; c < nc; c++) {
        cp_wait0();
        __syncthreads();
        int nxt = c + 1;
        if (nxt < nc) issue(nxt & 1, nxt);
        cp_commit();
        const uint32_t base = sb + (c & 1) * STAGEB2;
        #pragma unroll
        for (int k16 = 0; k16 < 2; k16++) {
            const int k2 = k16 * 2;
            uint32_t aAddr[4], bAddr[2];
            #pragma unroll
            for (int mi = 0; mi < 4; mi++)
                aAddr[mi] = base + (uint32_t)((wr * 64 + mi * 16 + rA) * ROWB + (k2 + cA) * 16);
            #pragma unroll
            for (int ni = 0; ni < 2; ni++)
                bAddr[ni] = base + HALFB +
                            (uint32_t)((wc * 32 + ni * 16 + rB) * ROWB + (k2 + cB) * 16);

            uint32_t fAh[4][4], fB[2][4];
            #pragma unroll
            for (int mi = 0; mi < 4; mi++) ldm4(fAh[mi], aAddr[mi]);
            #pragma unroll
            for (int ni = 0; ni < 2; ni++) ldm4(fB[ni], bAddr[ni]);
            #pragma unroll
            for (int mi = 0; mi < 4; mi++)
                #pragma unroll
                for (int nj = 0; nj < 4; nj++) {
                    const int bi = nj >> 1, bs = (nj & 1) * 2;
                    mma16816h(acc[mi][nj], fAh[mi], fB[bi][bs], fB[bi][bs + 1]);
                }
            #pragma unroll
            for (int ni = 0; ni < 2; ni++) ldm4(fB[ni], bAddr[ni] + HALFB);
            #pragma unroll
            for (int mi = 0; mi < 4; mi++)
                #pragma unroll
                for (int nj = 0; nj < 4; nj++) {
                    const int bi = nj >> 1, bs = (nj & 1) * 2;
                    mma16816h(acc[mi][nj], fAh[mi], fB[bi][bs], fB[bi][bs + 1]);
                }
        }
    }
    __syncthreads();
}

__device__ __forceinline__ void epi_bias(float (&acc)[4][4][4], const float* bias,
                                         int blockCol, int wc, int lane) {
    #pragma unroll
    for (int nj = 0; nj < 4; nj++) {
        const int col = blockCol + wc * 32 + nj * 8 + (lane & 3) * 2;
        float b0 = bias[col], b1 = bias[col + 1];
        #pragma unroll
        for (int mi = 0; mi < 4; mi++) {
            acc[mi][nj][0] += b0; acc[mi][nj][1] += b1;
            acc[mi][nj][2] += b0; acc[mi][nj][3] += b1;
        }
    }
}

__device__ __forceinline__ void epi_split_store(
    float (&acc)[4][4][4], __nv_bfloat16* Ch, __nv_bfloat16* Cl, int ldc,
    int blockRow, int blockCol, int ncols, int wr, int wc, int lane)
{
    #pragma unroll
    for (int mi = 0; mi < 4; mi++) {
        long long R0 = (long long)(blockRow + wr * 64 + mi * 16 + (lane >> 2)) * ldc;
        long long R1 = R0 + 8LL * ldc;
        #pragma unroll
        for (int nj = 0; nj < 4; nj++) {
            int col = blockCol + wc * 32 + nj * 8 + (lane & 3) * 2;
            if (col >= ncols) continue;
            spair(Ch, Cl, R0 + col, acc[mi][nj][0], acc[mi][nj][1]);
            spair(Ch, Cl, R1 + col, acc[mi][nj][2], acc[mi][nj][3]);
        }
    }
}

__device__ __forceinline__ void epi_split_store_f16(
    float (&acc)[4][4][4], __half* Ch, __half* Cl, int ldc,
    int blockRow, int blockCol, int ncols, int wr, int wc, int lane)
{
    #pragma unroll
    for (int mi = 0; mi < 4; mi++) {
        long long R0 = (long long)(blockRow + wr * 64 + mi * 16 + (lane >> 2)) * ldc;
        long long R1 = R0 + 8LL * ldc;
        #pragma unroll
        for (int nj = 0; nj < 4; nj++) {
            int col = blockCol + wc * 32 + nj * 8 + (lane & 3) * 2;
            if (col >= ncols) continue;
            spair_f16(Ch, Cl, R0 + col, acc[mi][nj][0], acc[mi][nj][1]);
            spair_f16(Ch, Cl, R1 + col, acc[mi][nj][2], acc[mi][nj][3]);
        }
    }
}

__device__ __forceinline__ void epi_f32_store(
    float (&acc)[4][4][4], float* Cf, int ldc,
    int blockRow, int blockCol, int wr, int wc, int lane)
{
    #pragma unroll
    for (int mi = 0; mi < 4; mi++) {
        long long R0 = (long long)(blockRow + wr * 64 + mi * 16 + (lane >> 2)) * ldc;
        long long R1 = R0 + 8LL * ldc;
        #pragma unroll
        for (int nj = 0; nj < 4; nj++) {
            int col = blockCol + wc * 32 + nj * 8 + (lane & 3) * 2;
            *(float2*)(Cf + R0 + col) = make_float2(acc[mi][nj][0], acc[mi][nj][1]);
            *(float2*)(Cf + R1 + col) = make_float2(acc[mi][nj][2], acc[mi][nj][3]);
        }
    }
}

// ---------------- stage 1: eq (z=0), ev (z=1), m2t (z=2) ----------------
__global__ void __launch_bounds__(256, 2) gemm_stage1(
    const __nv_bfloat16* __restrict__ q_h, const __nv_bfloat16* __restrict__ q_l,
    const __nv_bfloat16* __restrict__ wq_h, const __nv_bfloat16* __restrict__ wq_l,
    const __nv_bfloat16* __restrict__ v_h, const __nv_bfloat16* __restrict__ v_l,
    const __nv_bfloat16* __restrict__ wv_h, const __nv_bfloat16* __restrict__ wv_l,
    const __nv_bfloat16* __restrict__ wl_h, const __nv_bfloat16* __restrict__ wl_l,
    const __nv_bfloat16* __restrict__ vm_h, const __nv_bfloat16* __restrict__ vm_l,
    __nv_bfloat16* eqn_h, __nv_bfloat16* eqn_l,
    __nv_bfloat16* ev_h, __nv_bfloat16* ev_l,
    __half* m2h, __half* m2l,
    const float* __restrict__ bq, const float* __restrict__ bv,
    float* __restrict__ invkn, float* __restrict__ gpart)
{
    extern __shared__ char smem[];
    const uint32_t sb = smem_u32(smem);
    const int tid = threadIdx.x, lane = tid & 31, wid = tid >> 5;
    const int wr = wid >> 2, wc = wid & 3;
    const int z = blockIdx.z;
    float acc[4][4][4];

    if (z == 2) {
        if (blockIdx.x != 0 || blockIdx.y >= 32) return;
        int h = blockIdx.y & 7, mb = blockIdx.y >> 3;
        gemm_core(sb, tid, wl_h + h * 512 + (long long)mb * 128 * (HEAD * DIM),
                  wl_l + h * 512 + (long long)mb * 128 * (HEAD * DIM), HEAD * DIM,
                  vm_h, vm_l, DIM, DIM, SLOT, acc);
        epi_split_store_f16(acc, m2h + h * SLOT, m2l + h * SLOT, HEAD * SLOT,
                            mb * 128, 0, SLOT, wr, wc, lane);
        return;
    }

    const int blockRow = blockIdx.y * 128, blockCol = blockIdx.x * 128;
    if (z == 0)
        gemm_core(sb, tid, q_h + (long long)blockRow * DIM, q_l + (long long)blockRow * DIM, DIM,
                  wq_h + (long long)blockCol * DIM, wq_l + (long long)blockCol * DIM, DIM,
                  DIM, 128, acc);
    else
        gemm_core(sb, tid, v_h + (long long)blockRow * DIM, v_l + (long long)blockRow * DIM, DIM,
                  wv_h + (long long)blockCol * DIM, wv_l + (long long)blockCol * DIM, DIM,
                  DIM, 128, acc);

    epi_bias(acc, z == 0 ? bq : bv, blockCol, wc, lane);

    float* sred = (float*)smem;
    #pragma unroll
    for (int mi = 0; mi < 4; mi++) {
        float s0 = 0.f, s1 = 0.f;
        #pragma unroll
        for (int nj = 0; nj < 4; nj++) {
            s0 += acc[mi][nj][0] * acc[mi][nj][0] + acc[mi][nj][1] * acc[mi][nj][1];
            s1 += acc[mi][nj][2] * acc[mi][nj][2] + acc[mi][nj][3] * acc[mi][nj][3];
        }
        s0 = qred_sum(s0); s1 = qred_sum(s1);
        if ((lane & 3) == 0) {
            int r0 = wr * 64 + mi * 16 + (lane >> 2);
            sred[r0 * 4 + wc] = s0;
            sred[(r0 + 8) * 4 + wc] = s1;
        }
    }
    __syncthreads();
    if (z == 0) {
        if ((wc == 0 || wc == 2) && (lane & 3) == 0) {
            #pragma unroll
            for (int mi = 0; mi < 4; mi++)
                #pragma unroll
                for (int half = 0; half < 2; half++) {
                    int r = wr * 64 + mi * 16 + (lane >> 2) + half * 8;
                    float s = sred[r * 4 + wc] + sred[r * 4 + wc + 1];
                    invkn[(long long)(blockRow + r) * HEAD + blockIdx.x * 2 + (wc >> 1)]
                        = 1.0f / fmaxf(sqrtf(s), 1e-12f);
                }
        }
    } else {
        if (wc == 0 && (lane & 3) == 0) {
            #pragma unroll
            for (int mi = 0; mi < 4; mi++)
                #pragma unroll
                for (int half = 0; half < 2; half++) {
                    int r = wr * 64 + mi * 16 + (lane >> 2) + half * 8;
                    float s = sred[r * 4] + sred[r * 4 + 1] + sred[r * 4 + 2] + sred[r * 4 + 3];
                    gpart[(long long)(blockRow + r) * 4 + blockIdx.x] = s;
                }
        }
    }
    epi_split_store(acc, z == 0 ? eqn_h : ev_h, z == 0 ? eqn_l : ev_l, DIM,
                    blockRow, blockCol, 1 << 30, wr, wc, lane);
}

// ---------------- stage 2: vsim (z=0) + ksim heads (z=1..8), fp16 softmax outputs ----------------
__global__ void __launch_bounds__(256, 2) gemm_sim(
    const __nv_bfloat16* __restrict__ eqn_h, const __nv_bfloat16* __restrict__ eqn_l,
    const __nv_bfloat16* __restrict__ kn_h, const __nv_bfloat16* __restrict__ kn_l,
    const __nv_bfloat16* __restrict__ ev_h, const __nv_bfloat16* __restrict__ ev_l,
    const __nv_bfloat16* __restrict__ vn_h, const __nv_bfloat16* __restrict__ vn_l,
    __half* ka, __half* va,
    const float* __restrict__ invkn, const float* __restrict__ gpart)
{
    extern __shared__ char smem[];
    const uint32_t sb = smem_u32(smem);
    const int tid = threadIdx.x, lane = tid & 31, wid = tid >> 5;
    const int wr = wid >> 2, wc = wid & 3;
    const int z = blockIdx.z;
    const int blockRow = blockIdx.y * 128;
    float acc[4][4][4];

    __half* Ch;
    int ldc;
    bool is_val = (z == 0);
    if (is_val) {
        gemm_core(sb, tid, ev_h + (long long)blockRow * DIM, ev_l + (long long)blockRow * DIM, DIM,
                  vn_h, vn_l, DIM, DIM, SLOT, acc);
        Ch = va; ldc = 128;
    } else {
        int h = z - 1;
        gemm_core(sb, tid, eqn_h + (long long)blockRow * DIM + h * HD,
                  eqn_l + (long long)blockRow * DIM + h * HD, DIM,
                  kn_h + (long long)h * SLOT * HD, kn_l + (long long)h * SLOT * HD, HD,
                  HD, SLOT, acc);
        Ch = ka + h * SLOT; ldc = HEAD * SLOT;
    }

    float* sred = (float*)smem;
    float* ssum = sred + 512;
    const int h = z - 1;

    float scl[4][2];
    #pragma unroll
    for (int mi = 0; mi < 4; mi++)
        #pragma unroll
        for (int half = 0; half < 2; half++) {
            int r = blockRow + wr * 64 + mi * 16 + (lane >> 2) + half * 8;
            float iv;
            if (is_val) {
                float s4 = gpart[r * 4] + gpart[r * 4 + 1] + gpart[r * 4 + 2] + gpart[r * 4 + 3];
                iv = 1.0f / fmaxf(sqrtf(s4), 1e-12f);
            } else {
                iv = invkn[(long long)r * HEAD + h];
            }
            scl[mi][half] = RADIUSF * iv;
        }
    #pragma unroll
    for (int mi = 0; mi < 4; mi++) {
        float m0 = -1e30f, m1 = -1e30f;
        #pragma unroll
        for (int nj = 0; nj < 4; nj++) {
            const int col = wc * 32 + nj * 8 + (lane & 3) * 2;
            bool ok = col < SLOT;
            float l0 = ok ? scl[mi][0] * acc[mi][nj][0] : -1e30f;
            float l1 = ok ? scl[mi][0] * acc[mi][nj][1] : -1e30f;
            float l2 = ok ? scl[mi][1] * acc[mi][nj][2] : -1e30f;
            float l3 = ok ? scl[mi][1] * acc[mi][nj][3] : -1e30f;
            acc[mi][nj][0] = l0; acc[mi][nj][1] = l1;
            acc[mi][nj][2] = l2; acc[mi][nj][3] = l3;
            m0 = fmaxf(m0, fmaxf(l0, l1)); m1 = fmaxf(m1, fmaxf(l2, l3));
        }
        m0 = qred_max(m0); m1 = qred_max(m1);
        if ((lane & 3) == 0) {
            int r0 = wr * 64 + mi * 16 + (lane >> 2);
            sred[r0 * 4 + wc] = m0;
            sred[(r0 + 8) * 4 + wc] = m1;
        }
    }
    __syncthreads();
    #pragma unroll
    for (int mi = 0; mi < 4; mi++) {
        int r0 = wr * 64 + mi * 16 + (lane >> 2), r1 = r0 + 8;
        float M0 = fmaxf(fmaxf(sred[r0 * 4], sred[r0 * 4 + 1]),
                         fmaxf(sred[r0 * 4 + 2], sred[r0 * 4 + 3]));
        float M1 = fmaxf(fmaxf(sred[r1 * 4], sred[r1 * 4 + 1]),
                         fmaxf(sred[r1 * 4 + 2], sred[r1 * 4 + 3]));
        float s0 = 0.f, s1 = 0.f;
        #pragma unroll
        for (int nj = 0; nj < 4; nj++) {
            const int col = wc * 32 + nj * 8 + (lane & 3) * 2;
            bool ok = col < SLOT;
            float e0 = ok ? __expf(acc[mi][nj][0] - M0) : 0.f;
            float e1 = ok ? __expf(acc[mi][nj][1] - M0) : 0.f;
            float e2 = ok ? __expf(acc[mi][nj][2] - M1) : 0.f;
            float e3 = ok ? __expf(acc[mi][nj][3] - M1) : 0.f;
            acc[mi][nj][0] = e0; acc[mi][nj][1] = e1;
            acc[mi][nj][2] = e2; acc[mi][nj][3] = e3;
            s0 += e0 + e1; s1 += e2 + e3;
        }
        s0 = qred_sum(s0); s1 = qred_sum(s1);
        if ((lane & 3) == 0) {
            ssum[r0 * 4 + wc] = s0;
            ssum[r1 * 4 + wc] = s1;
        }
    }
    __syncthreads();
    #pragma unroll
    for (int mi = 0; mi < 4; mi++) {
        int r0l = wr * 64 + mi * 16 + (lane >> 2), r1l = r0l + 8;
        float i0 = 1.0f / (ssum[r0l * 4] + ssum[r0l * 4 + 1] + ssum[r0l * 4 + 2] + ssum[r0l * 4 + 3]);
        float i1 = 1.0f / (ssum[r1l * 4] + ssum[r1l * 4 + 1] + ssum[r1l * 4 + 2] + ssum[r1l * 4 + 3]);
        long long R0 = (long long)(blockRow + r0l) * ldc;
        long long R1 = (long long)(blockRow + r1l) * ldc;
        #pragma unroll
        for (int nj = 0; nj < 4; nj++) {
            const int col = wc * 32 + nj * 8 + (lane & 3) * 2;
            if (!is_val && col >= SLOT) continue;   // vsim writes zero pads (e==0)
            hpair(Ch, R0 + col, acc[mi][nj][0] * i0, acc[mi][nj][1] * i0);
            hpair(Ch, R1 + col, acc[mi][nj][2] * i1, acc[mi][nj][3] * i1);
        }
    }
}

// ---------------- stage 3 (fp16 2-term): virpre (z=0, K=896) + aud (z=1, K=128) ----------------
__global__ void __launch_bounds__(256, 2) gemm_out(
    const __half* __restrict__ ka, const __half* __restrict__ m2h, const __half* __restrict__ m2l,
    const __half* __restrict__ va, const __half* __restrict__ vth, const __half* __restrict__ vtl,
    float* __restrict__ virpre, float* __restrict__ aud,
    const float* __restrict__ bl)
{
    extern __shared__ char smem[];
    const uint32_t sb = smem_u32(smem);
    const int tid = threadIdx.x, lane = tid & 31, wid = tid >> 5;
    const int wr = wid >> 2, wc = wid & 3;
    const int z = blockIdx.z;
    const int blockRow = blockIdx.y * 128, blockCol = blockIdx.x * 128;
    float acc[4][4][4];

    if (z == 0) {
        gemm_core_f16(sb, tid, ka + (long long)blockRow * (HEAD * SLOT), HEAD * SLOT,
                      m2h + (long long)blockCol * (HEAD * SLOT),
                      m2l + (long long)blockCol * (HEAD * SLOT), HEAD * SLOT,
                      HEAD * SLOT, acc);
        epi_bias(acc, bl, blockCol, wc, lane);
        epi_f32_store(acc, virpre, DIM, blockRow, blockCol, wr, wc, lane);
    } else {
        gemm_core_f16(sb, tid, va + (long long)blockRow * 128, 128,
                      vth + (long long)blockCol * 128,
                      vtl + (long long)blockCol * 128, 128,
                      128, acc);
        epi_f32_store(acc, aud, DIM, blockRow, blockCol, wr, wc, lane);
    }
}

// ---------------- mega prep ----------------
#define NB_Q  8192
#define NB_V  8192
#define NB_WQ 256
#define NB_WV 256
#define NB_WL 2048
#define NB_VM 56
#define NB_KN 112
#define NB_VN 112
#define NB_VT 256
#define NB_CP 112
#define NB_TOTAL (NB_Q+NB_V+NB_WQ+NB_WV+NB_WL+NB_VM+NB_KN+NB_VN+NB_VT+NB_CP)

__device__ __forceinline__ void do_split4(const float4* src, __nv_bfloat16* h,
                                          __nv_bfloat16* l, long long i) {
    float4 v = src[i];
    __nv_bfloat16 h0 = __float2bfloat16_rn(v.x), h1 = __float2bfloat16_rn(v.y);
    __nv_bfloat16 h2 = __float2bfloat16_rn(v.z), h3 = __float2bfloat16_rn(v.w);
    *(__nv_bfloat162*)(h + i * 4)     = __halves2bfloat162(h0, h1);
    *(__nv_bfloat162*)(h + i * 4 + 2) = __halves2bfloat162(h2, h3);
    *(__nv_bfloat162*)(l + i * 4) = __halves2bfloat162(
        __float2bfloat16_rn(v.x - __bfloat162float(h0)),
        __float2bfloat16_rn(v.y - __bfloat162float(h1)));
    *(__nv_bfloat162*)(l + i * 4 + 2) = __halves2bfloat162(
        __float2bfloat16_rn(v.z - __bfloat162float(h2)),
        __float2bfloat16_rn(v.w - __bfloat162float(h3)));
}

__global__ void mega_prep(
    const float* __restrict__ query, const float* __restrict__ value,
    const float* __restrict__ key_mem, const float* __restrict__ value_mem,
    const float* __restrict__ Wq, const float* __restrict__ Wv, const float* __restrict__ Wl,
    __nv_bfloat16* q_h, __nv_bfloat16* q_l, __nv_bfloat16* v_h, __nv_bfloat16* v_l,
    __nv_bfloat16* wq_h, __nv_bfloat16* wq_l, __nv_bfloat16* wv_h, __nv_bfloat16* wv_l,
    __nv_bfloat16* wl_h, __nv_bfloat16* wl_l, __nv_bfloat16* vm_h, __nv_bfloat16* vm_l,
    __nv_bfloat16* kn_h, __nv_bfloat16* kn_l, __nv_bfloat16* vn_h, __nv_bfloat16* vn_l,
    __half* vth, __half* vtl, float* cpart)
{
    __shared__ float sh[544];
    int b = blockIdx.x, tid = threadIdx.x;

    if (b < NB_Q) { do_split4((const float4*)query, q_h, q_l, (long long)b * 256 + tid); return; }
    b -= NB_Q;
    if (b < NB_V) { do_split4((const float4*)value, v_h, v_l, (long long)b * 256 + tid); return; }
    b -= NB_V;
    if (b < NB_WQ) { do_split4((const float4*)Wq, wq_h, wq_l, (long long)b * 256 + tid); return; }
    b -= NB_WQ;
    if (b < NB_WV) { do_split4((const float4*)Wv, wv_h, wv_l, (long long)b * 256 + tid); return; }
    b -= NB_WV;
    if (b < NB_WL) { do_split4((const float4*)Wl, wl_h, wl_l, (long long)b * 256 + tid); return; }
    b -= NB_WL;
    if (b < NB_VM) { do_split4((const float4*)value_mem, vm_h, vm_l, (long long)b * 256 + tid); return; }
    b -= NB_VM;
    if (b < NB_KN) {
        int seg = b * 8 + (tid >> 5), lane = tid & 31;
        long long base = (long long)seg * 64;
        float a = key_mem[base + lane], c = key_mem[base + lane + 32];
        float s = a * a + c * c;
        #pragma unroll
        for (int o = 16; o; o >>= 1) s += __shfl_xor_sync(0xffffffffu, s, o);
        float inv = 1.0f / fmaxf(sqrtf(s), 1e-12f);
        wsplit(kn_h, kn_l, base + lane, a * inv);
        wsplit(kn_h, kn_l, base + lane + 32, c * inv);
        return;
    }
    b -= NB_KN;
    if (b < NB_VN) {
        long long r = b;
        float a = value_mem[r * DIM + tid], c = value_mem[r * DIM + tid + 256];
        float s = blockReduceSum(a * a + c * c, sh);
        float inv = 1.0f / fmaxf(sqrtf(s), 1e-12f);
        wsplit(vn_h, vn_l, r * DIM + tid, a * inv);
        wsplit(vn_h, vn_l, r * DIM + tid + 256, c * inv);
        return;
    }
    b -= NB_VN;
    if (b < NB_VT) {
        int idx = b * 256 + tid;
        int j = idx >> 7, s = idx & 127;
        float v = (s < SLOT) ? value_mem[(long long)s * DIM + j] : 0.0f;
        wsplit_f16(vth, vtl, idx, v);
        return;
    }
    b -= NB_VT;
    {
        int i = b;
        float* vi = sh;
        float* red = sh + 512;
        for (int c = tid; c < DIM; c += 256) vi[c] = value_mem[(long long)i * DIM + c];
        __syncthreads();
        float s = 0.f;
        for (int c = tid; c < DIM; c += 256) s += vi[c] * vi[c];
        s = blockReduceSum(s, red);
        float ni = fmaxf(sqrtf(s), 1e-12f);
        int w = tid >> 5, lane = tid & 31;
        float acc = 0.f;
        for (int j = w; j < SLOT; j += 8) {
            float d = 0.f, jj = 0.f;
            for (int c = lane; c < DIM; c += 32) {
                float vj = value_mem[(long long)j * DIM + c];
                d += vi[c] * vj; jj += vj * vj;
            }
            #pragma unroll
            for (int o = 16; o; o >>= 1) {
                d += __shfl_down_sync(0xffffffffu, d, o);
                jj += __shfl_down_sync(0xffffffffu, jj, o);
            }
            if (lane == 0) {
                float nj = fmaxf(sqrtf(jj), 1e-12f);
                acc += fabsf(((i == j) ? 1.0f : 0.0f) - d / (ni * nj));
            }
        }
        acc = blockReduceSum(acc, red);
        if (tid == 0) cpart[i] = acc;
    }
}

// ---------------- fused te+tr layernorm ----------------
__global__ void fuse_tetr(const float* __restrict__ virpre, const float* __restrict__ aud,
                          const float* __restrict__ query, const float* __restrict__ value,
                          const float* __restrict__ g1, const float* __restrict__ b1,
                          const float* __restrict__ g2, const float* __restrict__ b2,
                          const float* __restrict__ g3, const float* __restrict__ b3,
                          float* __restrict__ out_te, float* __restrict__ out_tr,
                          float* __restrict__ cosbuf)
{
    __shared__ float red[32];
    bool is_tr = blockIdx.x >= NROWS;
    long long r = is_tr ? (blockIdx.x - NROWS) : blockIdx.x;
    const float* src = (is_tr ? aud : virpre) + r * DIM;
    const float* q = query + r * DIM;
    const float* gx = is_tr ? g3 : g2;
    const float* bx = is_tr ? b3 : b2;
    float* o = (is_tr ? out_tr : out_te) + r * DIM;

    float x[4], qv[4];
    float s = 0.f, s2 = 0.f;
    #pragma unroll
    for (int i = 0; i < 4; i++) {
        int c = threadIdx.x + 128 * i;
        x[i] = src[c]; qv[i] = q[c];
        s += x[i]; s2 += x[i] * x[i];
    }
    s  = blockReduceSum(s,  red);
    s2 = blockReduceSum(s2, red);
    if (is_tr) {
        const float* v = value + r * DIM;
        float sav = 0.f, svv = 0.f;
        #pragma unroll
        for (int i = 0; i < 4; i++) {
            int c = threadIdx.x + 128 * i;
            float vv = v[c];
            sav += x[i] * vv; svv += vv * vv;
        }
        sav = blockReduceSum(sav, red);
        svv = blockReduceSum(svv, red);
        if (threadIdx.x == 0) {
            float cosv = sav / fmaxf(sqrtf(s2) * sqrtf(svv), 1e-8f);
            cosbuf[r] = fabsf(1.0f - cosv);
        }
    }
    float mu = s * (1.0f / DIM);
    float var = s2 * (1.0f / DIM) - mu * mu;
    float inv = rsqrtf(var + 1e-5f);
    float t[4]; float ts = 0.f, ts2 = 0.f;
    #pragma unroll
    for (int i = 0; i < 4; i++) {
        int c = threadIdx.x + 128 * i;
        float ln = (x[i] - mu) * inv * gx[c] + bx[c];
        t[i] = qv[i] + ln; ts += t[i]; ts2 += t[i] * t[i];
    }
    ts  = blockReduceSum(ts,  red);
    ts2 = blockReduceSum(ts2, red);
    mu = ts * (1.0f / DIM);
    var = ts2 * (1.0f / DIM) - mu * mu;
    inv = rsqrtf(var + 1e-5f);
    #pragma unroll
    for (int i = 0; i < 4; i++) {
        int c = threadIdx.x + 128 * i;
        o[c] = (t[i] - mu) * inv * g1[c] + b1[c];
    }
}

// ---------------- final reductions ----------------
__global__ void final_reduce(const float* __restrict__ cosbuf, const float* __restrict__ cpart,
                             float* __restrict__ recon, float* __restrict__ contr)
{
    __shared__ float red[32];
    int b = blockIdx.x;
    if (b < 32) {
        float s = 0.0f;
        for (int i = threadIdx.x; i < 512; i += blockDim.x) s += cosbuf[b * 512 + i];
        s = blockReduceSum(s, red);
        if (threadIdx.x == 0) recon[b] = s;
    } else {
        float s = 0.0f;
        for (int i = threadIdx.x; i < SLOT; i += blockDim.x) s += cpart[i];
        s = blockReduceSum(s, red);
        if (threadIdx.x == 0) contr[0] = 0.5f * s;
    }
}

// ---------------- launch ----------------
#define SYM(p, s) cudaGetSymbolAddress((void**)&p, s)

extern "C" void kernel_launch(void* const* d_in, const int* in_sizes, int n_in,
                              void* d_out, int out_size)
{
    const float* query     = (const float*)d_in[0];
    const float* value     = (const float*)d_in[1];
    const float* key_mem   = (const float*)d_in[2];
    const float* value_mem = (const float*)d_in[3];
    const float* Wq = (const float*)d_in[4];
    const float* bq = (const float*)d_in[5];
    const float* Wv = (const float*)d_in[6];
    const float* bv = (const float*)d_in[7];
    const float* Wl = (const float*)d_in[8];
    const float* bl = (const float*)d_in[9];
    const float* g1 = (const float*)d_in[10];
    const float* b1 = (const float*)d_in[11];
    const float* g2 = (const float*)d_in[12];
    const float* b2 = (const float*)d_in[13];
    const float* g3 = (const float*)d_in[14];
    const float* b3 = (const float*)d_in[15];

    float* out        = (float*)d_out;
    float* out_te     = out;
    float* out_tr     = out + (long long)NROWS * DIM;
    float* out_recon  = out + 2ll * NROWS * DIM;
    float* out_contr  = out_recon + 32;

    float *p_virpre, *p_aud, *p_invkn, *p_gpart, *p_cos, *p_cpart;
    SYM(p_virpre, g_virpre); SYM(p_aud, g_aud);
    SYM(p_invkn, g_invkn); SYM(p_gpart, g_gpart);
    SYM(p_cos, g_cosbuf); SYM(p_cpart, g_cpart);

    __nv_bfloat16 *q_h, *q_l, *v_h, *v_l, *wq_h, *wq_l, *wv_h, *wv_l, *wl_h, *wl_l;
    __nv_bfloat16 *vm_h, *vm_l, *eqn_h, *eqn_l, *kn_h, *kn_l;
    __nv_bfloat16 *ev_h, *ev_l, *vn_h, *vn_l;
    __half *ka, *va, *m2h, *m2l, *vth, *vtl;
    SYM(q_h, g_q_h); SYM(q_l, g_q_l); SYM(v_h, g_v_h); SYM(v_l, g_v_l);
    SYM(wq_h, g_wq_h); SYM(wq_l, g_wq_l); SYM(wv_h, g_wv_h); SYM(wv_l, g_wv_l);
    SYM(wl_h, g_wl_h); SYM(wl_l, g_wl_l); SYM(vm_h, g_vm_h); SYM(vm_l, g_vm_l);
    SYM(eqn_h, g_eqn_h); SYM(eqn_l, g_eqn_l); SYM(kn_h, g_kn_h); SYM(kn_l, g_kn_l);
    SYM(ev_h, g_ev_h); SYM(ev_l, g_ev_l); SYM(vn_h, g_vn_h); SYM(vn_l, g_vn_l);
    SYM(ka, g_ka); SYM(va, g_va); SYM(m2h, g_m2h); SYM(m2l, g_m2l);
    SYM(vth, g_vth); SYM(vtl, g_vtl);

    cudaFuncSetAttribute(gemm_stage1, cudaFuncAttributeMaxDynamicSharedMemorySize, GSMEM);
    cudaFuncSetAttribute(gemm_sim,    cudaFuncAttributeMaxDynamicSharedMemorySize, GSMEM);
    cudaFuncSetAttribute(gemm_out,    cudaFuncAttributeMaxDynamicSharedMemorySize, GSMEM2);

    // 0: all prep (splits, norms, contrastive partials)
    mega_prep<<<NB_TOTAL, 256>>>(query, value, key_mem, value_mem, Wq, Wv, Wl,
                                 q_h, q_l, v_h, v_l, wq_h, wq_l, wv_h, wv_l,
                                 wl_h, wl_l, vm_h, vm_l, kn_h, kn_l, vn_h, vn_l,
                                 vth, vtl, p_cpart);

    // 1: eq (z=0) + ev (z=1) + m2t (z=2, fp16 split out)
    gemm_stage1<<<dim3(4, 128, 3), 256, GSMEM>>>(
        q_h, q_l, wq_h, wq_l, v_h, v_l, wv_h, wv_l, wl_h, wl_l, vm_h, vm_l,
        eqn_h, eqn_l, ev_h, ev_l, m2h, m2l, bq, bv, p_invkn, p_gpart);

    // 2: vsim (z=0) + ksim heads (z=1..8), fused softmaxes -> fp16 hi
    gemm_sim<<<dim3(1, 128, 9), 256, GSMEM>>>(
        eqn_h, eqn_l, kn_h, kn_l, ev_h, ev_l, vn_h, vn_l,
        ka, va, p_invkn, p_gpart);

    // 3: virpre (z=0, K=896) + aud (z=1, K=128) — fp16 2-term
    gemm_out<<<dim3(4, 128, 2), 256, GSMEM2>>>(
        ka, m2h, m2l, va, vth, vtl, p_virpre, p_aud, bl);

    // 4: fused te + tr double-layernorm (+cos)
    fuse_tetr<<<2 * NROWS, 128>>>(p_virpre, p_aud, query, value,
                                  g1, b1, g2, b2, g3, b3, out_te, out_tr, p_cos);

    // 5: recon per-batch sums + contrastive final
    final_reduce<<<33, 128>>>(p_cos, p_cpart, out_recon, out_contr);
}